// round 1
// baseline (speedup 1.0000x reference)
#include <cuda_runtime.h>
#include <cuda_bf16.h>
#include <cstdint>

// Problem constants
#define BATCH 2
#define SEQ   2048
#define DMODEL 1024
#define NHEADS 16
#define DK    64
#define NTOK  (BATCH*SEQ)          // 4096
#define NEGV  (-1e12f)

// ---------------------------------------------------------------------------
// Scratch (device globals; no runtime allocation allowed)
// ---------------------------------------------------------------------------
__device__ float g_Q[BATCH*NHEADS*SEQ*DK];   // [b,h,s,dk]
__device__ float g_K[BATCH*NHEADS*SEQ*DK];
__device__ float g_V[BATCH*NHEADS*SEQ*DK];
__device__ float g_ctx[NTOK*DMODEL];         // [token, h*64+dk]
__device__ float g_tmp[NTOK*DMODEL];         // pre-LN

// ---------------------------------------------------------------------------
// GEMM: C[m,n] = sum_k A[m,k] * W[n,k]   (A [4096,1024], W [1024,1024] row-major)
// mode 0: scatter to QKV layout out[((b*16+h)*2048+s)*64 + d]
// mode 1: out[m,n] = C + resid[m,n]   (plain [4096,1024])
// 128x128 tile, k-tile 8, 256 threads, 8x8 microtile.
// ---------------------------------------------------------------------------
__global__ void __launch_bounds__(256) gemm_kernel(
    const float* __restrict__ A, const float* __restrict__ W,
    const float* __restrict__ resid, float* __restrict__ outp, int mode)
{
    __shared__ float As[8][132];
    __shared__ float Bs[8][132];

    const int tid = threadIdx.x;
    const int bm = blockIdx.y * 128;
    const int bn = blockIdx.x * 128;
    const int lr = tid >> 1;            // 0..127
    const int lc = (tid & 1) * 4;       // 0 or 4
    const int tx = tid & 15;            // n-groups
    const int ty = tid >> 4;            // m-groups

    const float* Aptr = A + (size_t)(bm + lr) * DMODEL + lc;
    const float* Wptr = W + (size_t)(bn + lr) * DMODEL + lc;

    float acc[8][8];
#pragma unroll
    for (int i = 0; i < 8; i++)
#pragma unroll
        for (int j = 0; j < 8; j++) acc[i][j] = 0.f;

    for (int k0 = 0; k0 < DMODEL; k0 += 8) {
        float4 av = *(const float4*)(Aptr + k0);
        float4 bv = *(const float4*)(Wptr + k0);
        As[lc+0][lr] = av.x; As[lc+1][lr] = av.y;
        As[lc+2][lr] = av.z; As[lc+3][lr] = av.w;
        Bs[lc+0][lr] = bv.x; Bs[lc+1][lr] = bv.y;
        Bs[lc+2][lr] = bv.z; Bs[lc+3][lr] = bv.w;
        __syncthreads();
#pragma unroll
        for (int kk = 0; kk < 8; kk++) {
            float4 a0 = *(const float4*)&As[kk][ty*8];
            float4 a1 = *(const float4*)&As[kk][ty*8+4];
            float4 b0 = *(const float4*)&Bs[kk][tx*8];
            float4 b1 = *(const float4*)&Bs[kk][tx*8+4];
            float af[8] = {a0.x,a0.y,a0.z,a0.w,a1.x,a1.y,a1.z,a1.w};
            float bf[8] = {b0.x,b0.y,b0.z,b0.w,b1.x,b1.y,b1.z,b1.w};
#pragma unroll
            for (int i = 0; i < 8; i++)
#pragma unroll
                for (int j = 0; j < 8; j++)
                    acc[i][j] = fmaf(af[i], bf[j], acc[i][j]);
        }
        __syncthreads();
    }

    if (mode == 0) {
#pragma unroll
        for (int i = 0; i < 8; i++) {
            int m = bm + ty*8 + i;
            int b = m >> 11, s = m & 2047;
            int n0 = bn + tx*8;
            int h = n0 >> 6, d0 = n0 & 63;
            float* dst = outp + (((size_t)(b*NHEADS + h)*SEQ + s)*DK + d0);
            *(float4*)dst     = make_float4(acc[i][0],acc[i][1],acc[i][2],acc[i][3]);
            *(float4*)(dst+4) = make_float4(acc[i][4],acc[i][5],acc[i][6],acc[i][7]);
        }
    } else {
#pragma unroll
        for (int i = 0; i < 8; i++) {
            size_t off = (size_t)(bm + ty*8 + i) * DMODEL + bn + tx*8;
            float4 r0 = *(const float4*)&resid[off];
            float4 r1 = *(const float4*)&resid[off+4];
            *(float4*)&outp[off]   = make_float4(acc[i][0]+r0.x, acc[i][1]+r0.y,
                                                 acc[i][2]+r0.z, acc[i][3]+r0.w);
            *(float4*)&outp[off+4] = make_float4(acc[i][4]+r1.x, acc[i][5]+r1.y,
                                                 acc[i][6]+r1.z, acc[i][7]+r1.w);
        }
    }
}

// ---------------------------------------------------------------------------
// Attention: per (q-tile 64, head, batch) CTA, 128 threads, flash-style online
// softmax over 32 key tiles of 64. fp32 throughout.
// Mask semantics (faithful to reference): score unmasked iff am[key]!=0 AND key>query;
// otherwise score += -1e12f (fp32 add identical to the reference's).
// ---------------------------------------------------------------------------
#define APAD 68
#define ATT_SMEM ((4*64*APAD)*4 + 64*4)

__global__ void __launch_bounds__(128) attn_kernel(
    const float* __restrict__ Q, const float* __restrict__ K,
    const float* __restrict__ V, const int* __restrict__ amask,
    float* __restrict__ ctx)
{
    extern __shared__ float sm[];
    float* QsT = sm;                  // [d][q]  64 x APAD
    float* KsT = sm + 64*APAD;        // [d][k]
    float* Vs  = sm + 2*64*APAD;      // [k][v]
    float* PsT = sm + 3*64*APAD;      // [k][q]
    int*   msk = (int*)(sm + 4*64*APAD);

    const int qt = blockIdx.x, h = blockIdx.y, b = blockIdx.z;
    const int q0 = qt * 64;
    const int tid = threadIdx.x;
    const int tx = tid & 7;           // key/value column group (8 of 8)
    const int ty = tid >> 3;          // query row group (16 of 4)

    const size_t bh = (size_t)(b*NHEADS + h) * SEQ * DK;
    const float* Qb = Q + bh;
    const float* Kb = K + bh;
    const float* Vb = V + bh;

    // Load Q tile transposed: QsT[d][q]
    for (int i = tid; i < 64*16; i += 128) {
        int r = i >> 4, c = (i & 15) << 2;
        float4 v = *(const float4*)&Qb[(size_t)(q0 + r)*DK + c];
        QsT[(c+0)*APAD + r] = v.x;
        QsT[(c+1)*APAD + r] = v.y;
        QsT[(c+2)*APAD + r] = v.z;
        QsT[(c+3)*APAD + r] = v.w;
    }

    float m_i[4], l_i[4], acc[4][8];
#pragma unroll
    for (int i = 0; i < 4; i++) {
        m_i[i] = -3.0e38f; l_i[i] = 0.f;
#pragma unroll
        for (int j = 0; j < 8; j++) acc[i][j] = 0.f;
    }

    for (int kt = 0; kt < SEQ/64; kt++) {
        const int k0 = kt * 64;
        __syncthreads();   // protect previous tile's PsT/Vs reads
        for (int i = tid; i < 64*16; i += 128) {
            int r = i >> 4, c = (i & 15) << 2;
            float4 kv = *(const float4*)&Kb[(size_t)(k0 + r)*DK + c];
            KsT[(c+0)*APAD + r] = kv.x;
            KsT[(c+1)*APAD + r] = kv.y;
            KsT[(c+2)*APAD + r] = kv.z;
            KsT[(c+3)*APAD + r] = kv.w;
            float4 vv = *(const float4*)&Vb[(size_t)(k0 + r)*DK + c];
            *(float4*)&Vs[r*APAD + c] = vv;
        }
        if (tid < 64) msk[tid] = amask[b*SEQ + k0 + tid];
        __syncthreads();

        // scores S[4q][8k] = Q . K
        float s[4][8];
#pragma unroll
        for (int i = 0; i < 4; i++)
#pragma unroll
            for (int j = 0; j < 8; j++) s[i][j] = 0.f;
#pragma unroll 8
        for (int d = 0; d < 64; d++) {
            float4 aq = *(const float4*)&QsT[d*APAD + ty*4];
            float4 k0v = *(const float4*)&KsT[d*APAD + tx*8];
            float4 k1v = *(const float4*)&KsT[d*APAD + tx*8 + 4];
            float af[4] = {aq.x, aq.y, aq.z, aq.w};
            float bf[8] = {k0v.x,k0v.y,k0v.z,k0v.w,k1v.x,k1v.y,k1v.z,k1v.w};
#pragma unroll
            for (int i = 0; i < 4; i++)
#pragma unroll
                for (int j = 0; j < 8; j++)
                    s[i][j] = fmaf(af[i], bf[j], s[i][j]);
        }

        int mk[8];
#pragma unroll
        for (int j = 0; j < 8; j++) mk[j] = msk[tx*8 + j];

        // scale + mask + tile row max
        float tmax[4];
#pragma unroll
        for (int i = 0; i < 4; i++) {
            const int qg = q0 + ty*4 + i;
            tmax[i] = -3.0e38f;
#pragma unroll
            for (int j = 0; j < 8; j++) {
                const int kg = k0 + tx*8 + j;
                float sc = s[i][j] * 0.125f;
                if (!((mk[j] != 0) && (kg > qg))) sc += NEGV;
                s[i][j] = sc;
                tmax[i] = fmaxf(tmax[i], sc);
            }
        }
#pragma unroll
        for (int i = 0; i < 4; i++) {
            tmax[i] = fmaxf(tmax[i], __shfl_xor_sync(0xffffffffu, tmax[i], 1));
            tmax[i] = fmaxf(tmax[i], __shfl_xor_sync(0xffffffffu, tmax[i], 2));
            tmax[i] = fmaxf(tmax[i], __shfl_xor_sync(0xffffffffu, tmax[i], 4));
        }

        // online softmax update
#pragma unroll
        for (int i = 0; i < 4; i++) {
            float mnew = fmaxf(m_i[i], tmax[i]);
            float corr = __expf(m_i[i] - mnew);
            float psum = 0.f;
#pragma unroll
            for (int j = 0; j < 8; j++) {
                float p = __expf(s[i][j] - mnew);
                s[i][j] = p;
                psum += p;
            }
            psum += __shfl_xor_sync(0xffffffffu, psum, 1);
            psum += __shfl_xor_sync(0xffffffffu, psum, 2);
            psum += __shfl_xor_sync(0xffffffffu, psum, 4);
            l_i[i] = l_i[i] * corr + psum;
            m_i[i] = mnew;
#pragma unroll
            for (int j = 0; j < 8; j++) acc[i][j] *= corr;
        }

        // write P transposed: PsT[k][q]
#pragma unroll
        for (int i = 0; i < 4; i++)
#pragma unroll
            for (int j = 0; j < 8; j++)
                PsT[(tx*8 + j)*APAD + (ty*4 + i)] = s[i][j];
        __syncthreads();

        // O += P @ V
#pragma unroll 8
        for (int kk = 0; kk < 64; kk++) {
            float4 pv = *(const float4*)&PsT[kk*APAD + ty*4];
            float4 v0 = *(const float4*)&Vs[kk*APAD + tx*8];
            float4 v1 = *(const float4*)&Vs[kk*APAD + tx*8 + 4];
            float pf[4] = {pv.x, pv.y, pv.z, pv.w};
            float vf[8] = {v0.x,v0.y,v0.z,v0.w,v1.x,v1.y,v1.z,v1.w};
#pragma unroll
            for (int i = 0; i < 4; i++)
#pragma unroll
                for (int j = 0; j < 8; j++)
                    acc[i][j] = fmaf(pf[i], vf[j], acc[i][j]);
        }
    }

    // epilogue: divide by l, write ctx [token, h*64+v]
#pragma unroll
    for (int i = 0; i < 4; i++) {
        float inv = 1.0f / l_i[i];
        size_t row = (size_t)b*SEQ + q0 + ty*4 + i;
        float* dst = ctx + row*DMODEL + h*DK + tx*8;
        *(float4*)dst     = make_float4(acc[i][0]*inv, acc[i][1]*inv,
                                        acc[i][2]*inv, acc[i][3]*inv);
        *(float4*)(dst+4) = make_float4(acc[i][4]*inv, acc[i][5]*inv,
                                        acc[i][6]*inv, acc[i][7]*inv);
    }
}

// ---------------------------------------------------------------------------
// LayerNorm: one CTA per token row (1024 elems, 256 threads)
// ---------------------------------------------------------------------------
__global__ void __launch_bounds__(256) ln_kernel(
    const float* __restrict__ x, const float* __restrict__ gamma,
    const float* __restrict__ beta, float* __restrict__ out)
{
    const int row = blockIdx.x;
    const int tid = threadIdx.x;
    const float* xr = x + (size_t)row * DMODEL;

    float4 v = *(const float4*)&xr[tid*4];
    float s  = v.x + v.y + v.z + v.w;
    float sq = v.x*v.x + v.y*v.y + v.z*v.z + v.w*v.w;
#pragma unroll
    for (int o = 16; o > 0; o >>= 1) {
        s  += __shfl_xor_sync(0xffffffffu, s,  o);
        sq += __shfl_xor_sync(0xffffffffu, sq, o);
    }
    __shared__ float ss[8], ssq[8], smu, sinv;
    const int wid = tid >> 5, lane = tid & 31;
    if (lane == 0) { ss[wid] = s; ssq[wid] = sq; }
    __syncthreads();
    if (tid == 0) {
        float S = 0.f, SQ = 0.f;
#pragma unroll
        for (int i = 0; i < 8; i++) { S += ss[i]; SQ += ssq[i]; }
        float mu = S * (1.0f/DMODEL);
        float var = SQ * (1.0f/DMODEL) - mu*mu;
        smu = mu;
        sinv = rsqrtf(var + 1e-5f);
    }
    __syncthreads();
    float mu = smu, inv = sinv;
    float4 g = *(const float4*)&gamma[tid*4];
    float4 be = *(const float4*)&beta[tid*4];
    float4 o;
    o.x = (v.x - mu) * inv * g.x + be.x;
    o.y = (v.y - mu) * inv * g.y + be.y;
    o.z = (v.z - mu) * inv * g.z + be.z;
    o.w = (v.w - mu) * inv * g.w + be.w;
    *(float4*)&out[(size_t)row*DMODEL + tid*4] = o;
}

// ---------------------------------------------------------------------------
extern "C" void kernel_launch(void* const* d_in, const int* in_sizes, int n_in,
                              void* d_out, int out_size)
{
    const float* inQ   = (const float*)d_in[0];
    const float* inK   = (const float*)d_in[1];
    const float* inV   = (const float*)d_in[2];
    const int*   amask = (const int*)  d_in[3];
    const float* WQ    = (const float*)d_in[4];
    const float* WK    = (const float*)d_in[5];
    const float* WV    = (const float*)d_in[6];
    const float* WO    = (const float*)d_in[7];
    const float* gamma = (const float*)d_in[8];
    const float* beta  = (const float*)d_in[9];
    float* out = (float*)d_out;

    float *Qb, *Kb, *Vb, *ctx, *tmp;
    cudaGetSymbolAddress((void**)&Qb,  g_Q);
    cudaGetSymbolAddress((void**)&Kb,  g_K);
    cudaGetSymbolAddress((void**)&Vb,  g_V);
    cudaGetSymbolAddress((void**)&ctx, g_ctx);
    cudaGetSymbolAddress((void**)&tmp, g_tmp);

    dim3 ggrid(DMODEL/128, NTOK/128);   // (8, 32)
    gemm_kernel<<<ggrid, 256>>>(inQ, WQ, nullptr, Qb, 0);
    gemm_kernel<<<ggrid, 256>>>(inK, WK, nullptr, Kb, 0);
    gemm_kernel<<<ggrid, 256>>>(inV, WV, nullptr, Vb, 0);

    cudaFuncSetAttribute(attn_kernel,
                         cudaFuncAttributeMaxDynamicSharedMemorySize, ATT_SMEM);
    attn_kernel<<<dim3(SEQ/64, NHEADS, BATCH), 128, ATT_SMEM>>>(Qb, Kb, Vb, amask, ctx);

    gemm_kernel<<<ggrid, 256>>>(ctx, WO, inQ, tmp, 1);
    ln_kernel<<<NTOK, 256>>>(tmp, gamma, beta, out);
}

// round 4
// speedup vs baseline: 2.6370x; 2.6370x over previous
#include <cuda_runtime.h>
#include <cuda_bf16.h>
#include <cstdint>

// Problem constants
#define BATCH 2
#define SEQ   2048
#define DMODEL 1024
#define NHEADS 16
#define DK    64
#define NTOK  (BATCH*SEQ)          // 4096
#define NEGV  (-1e12f)

// ---------------------------------------------------------------------------
// Scratch (device globals; no runtime allocation allowed)
// ---------------------------------------------------------------------------
__device__ float g_Q[BATCH*NHEADS*SEQ*DK];   // [b,h,s,dk]
__device__ float g_K[BATCH*NHEADS*SEQ*DK];
__device__ float g_V[BATCH*NHEADS*SEQ*DK];
__device__ float g_ctx[NTOK*DMODEL];         // [token, h*64+dk]
__device__ float g_tmp[NTOK*DMODEL];         // pre-LN
__device__ float g_meanV[BATCH*NHEADS*DK];   // mean of V over seq, per (b,h)
__device__ int   g_fm[NTOK];                 // 1 if row has NO unmasked future key

// ---------------------------------------------------------------------------
// mma.sync m16n8k16 bf16 (target-agnostic tensor-core path; tcgen05 is
// rejected by this toolchain's ptxas target sm_103)
// ---------------------------------------------------------------------------
__device__ __forceinline__ void mma16816(float* c, const uint32_t* a,
                                         const uint32_t* b) {
    asm volatile(
        "mma.sync.aligned.m16n8k16.row.col.f32.bf16.bf16.f32 "
        "{%0,%1,%2,%3}, {%4,%5,%6,%7}, {%8,%9}, {%0,%1,%2,%3};"
        : "+f"(c[0]), "+f"(c[1]), "+f"(c[2]), "+f"(c[3])
        : "r"(a[0]), "r"(a[1]), "r"(a[2]), "r"(a[3]), "r"(b[0]), "r"(b[1]));
}

__device__ __forceinline__ uint32_t pack_bf2(float a, float b) {
    __nv_bfloat162 t = __floats2bfloat162_rn(a, b);
    return *(uint32_t*)&t;
}

// ---------------------------------------------------------------------------
// Tensor-core GEMM: C[m,n] = sum_k A[m,k] * W[n,k]
// A [4096,1024] row-major, W [1024,1024] row-major ([n][k] = K-major = "col").
// fp32 via bf16 split: hi*hi + hi*lo + lo*hi, fp32 accumulate.
// 128x128 CTA tile, 256 threads (8 warps, 2x4 -> 64x32 per warp), k-chunk 32.
// smem word stride per row = 20 (16 data + 4 pad) -> conflict-free frag loads.
// mode 0: scatter to [b,h,s,dk]; mode 1: out = C + resid  ([4096,1024]).
// ---------------------------------------------------------------------------
#define KC 32
#define SROW 20   // uint32 words per row (16 data words + 4 pad)

__global__ void __launch_bounds__(256) gemm_mma_kernel(
    const float* __restrict__ A, const float* __restrict__ W,
    const float* __restrict__ resid, float* __restrict__ outp, int mode)
{
    __shared__ uint32_t sAH[128*SROW];
    __shared__ uint32_t sAL[128*SROW];
    __shared__ uint32_t sWH[128*SROW];
    __shared__ uint32_t sWL[128*SROW];

    const int tid  = threadIdx.x;
    const int wid  = tid >> 5;
    const int lane = tid & 31;
    const int bm = blockIdx.y * 128;
    const int bn = blockIdx.x * 128;

    const int mw = wid & 1;            // 0..1 -> 64-row half
    const int nw = wid >> 1;           // 0..3 -> 32-col quarter
    const int g  = lane >> 2;          // 0..7
    const int kq = lane & 3;           // k-word within step

    float acc[4][4][4];
#pragma unroll
    for (int mt = 0; mt < 4; mt++)
#pragma unroll
        for (int nt = 0; nt < 4; nt++)
#pragma unroll
            for (int i = 0; i < 4; i++) acc[mt][nt][i] = 0.f;

    for (int kt = 0; kt < DMODEL / KC; kt++) {
        const int kk = kt * KC;
        __syncthreads();
        // load + split-convert: 128 rows x 32 cols of A and W
#pragma unroll
        for (int it = 0; it < 4; it++) {
            const int idx = tid + it * 256;
            const int r = idx >> 3;
            const int c4 = (idx & 7) << 2;       // 0,4,...,28
            const int sw = r * SROW + (c4 >> 1); // word index

            float4 v = *(const float4*)&A[(size_t)(bm + r) * DMODEL + kk + c4];
            __nv_bfloat16 h0 = __float2bfloat16(v.x), h1 = __float2bfloat16(v.y);
            __nv_bfloat16 h2 = __float2bfloat16(v.z), h3 = __float2bfloat16(v.w);
            *(uint2*)&sAH[sw] = make_uint2(
                pack_bf2(__bfloat162float(h0), __bfloat162float(h1)),
                pack_bf2(__bfloat162float(h2), __bfloat162float(h3)));
            *(uint2*)&sAL[sw] = make_uint2(
                pack_bf2(v.x - __bfloat162float(h0), v.y - __bfloat162float(h1)),
                pack_bf2(v.z - __bfloat162float(h2), v.w - __bfloat162float(h3)));

            float4 w = *(const float4*)&W[(size_t)(bn + r) * DMODEL + kk + c4];
            __nv_bfloat16 g0 = __float2bfloat16(w.x), g1 = __float2bfloat16(w.y);
            __nv_bfloat16 g2 = __float2bfloat16(w.z), g3 = __float2bfloat16(w.w);
            *(uint2*)&sWH[sw] = make_uint2(
                pack_bf2(__bfloat162float(g0), __bfloat162float(g1)),
                pack_bf2(__bfloat162float(g2), __bfloat162float(g3)));
            *(uint2*)&sWL[sw] = make_uint2(
                pack_bf2(w.x - __bfloat162float(g0), w.y - __bfloat162float(g1)),
                pack_bf2(w.z - __bfloat162float(g2), w.w - __bfloat162float(g3)));
        }
        __syncthreads();

#pragma unroll
        for (int ks = 0; ks < 2; ks++) {
            const int kw = ks * 8 + kq;
            // B fragments for this warp's 32 columns (4 tiles of n8)
            uint32_t bH[4][2], bL[4][2];
#pragma unroll
            for (int nt = 0; nt < 4; nt++) {
                const int nrow = nw * 32 + nt * 8 + g;
                bH[nt][0] = sWH[nrow * SROW + kw];
                bH[nt][1] = sWH[nrow * SROW + kw + 4];
                bL[nt][0] = sWL[nrow * SROW + kw];
                bL[nt][1] = sWL[nrow * SROW + kw + 4];
            }
#pragma unroll
            for (int mt = 0; mt < 4; mt++) {
                const int r0 = mw * 64 + mt * 16 + g;
                uint32_t aH[4], aL[4];
                aH[0] = sAH[r0 * SROW + kw];
                aH[1] = sAH[(r0 + 8) * SROW + kw];
                aH[2] = sAH[r0 * SROW + kw + 4];
                aH[3] = sAH[(r0 + 8) * SROW + kw + 4];
                aL[0] = sAL[r0 * SROW + kw];
                aL[1] = sAL[(r0 + 8) * SROW + kw];
                aL[2] = sAL[r0 * SROW + kw + 4];
                aL[3] = sAL[(r0 + 8) * SROW + kw + 4];
#pragma unroll
                for (int nt = 0; nt < 4; nt++) {
                    mma16816(acc[mt][nt], aH, bH[nt]);
                    mma16816(acc[mt][nt], aH, bL[nt]);
                    mma16816(acc[mt][nt], aL, bH[nt]);
                }
            }
        }
    }

    // epilogue: c0,c1 -> row g, cols n0,n0+1 ; c2,c3 -> row g+8
#pragma unroll
    for (int mt = 0; mt < 4; mt++) {
#pragma unroll
        for (int nt = 0; nt < 4; nt++) {
            const int m0 = bm + mw * 64 + mt * 16 + g;
            const int n  = bn + nw * 32 + nt * 8 + ((lane & 3) << 1);
#pragma unroll
            for (int half = 0; half < 2; half++) {
                const int m = m0 + half * 8;
                const float c0 = acc[mt][nt][half * 2 + 0];
                const float c1 = acc[mt][nt][half * 2 + 1];
                if (mode == 0) {
                    const int b = m >> 11, s = m & 2047;
                    const int h = n >> 6, d0 = n & 63;
                    float* dst = outp +
                        (((size_t)(b * NHEADS + h) * SEQ + s) * DK + d0);
                    *(float2*)dst = make_float2(c0, c1);
                } else {
                    const size_t off = (size_t)m * DMODEL + n;
                    float2 rs = *(const float2*)&resid[off];
                    *(float2*)&outp[off] = make_float2(c0 + rs.x, c1 + rs.y);
                }
            }
        }
    }
}

// ---------------------------------------------------------------------------
// Helper: fully-masked-row flags.  fm[b,q] = 1 iff no key k>q has mask[k]==1.
// ---------------------------------------------------------------------------
__global__ void fullmask_kernel(const int* __restrict__ amask, int* __restrict__ fm)
{
    const int b = blockIdx.y;
    const int q = blockIdx.x * blockDim.x + threadIdx.x;
    if (q >= SEQ) return;
    const int* m = amask + b * SEQ;
    int any = 0;
    for (int k = q + 1; k < SEQ; k++) { if (m[k]) { any = 1; break; } }
    fm[b * SEQ + q] = !any;
}

// Helper: meanV[b,h,d] = (1/SEQ) sum_s V[b,h,s,d]
__global__ void meanv_kernel(const float* __restrict__ V, float* __restrict__ mv)
{
    const int bh = blockIdx.x;
    const int d = threadIdx.x;
    const float* vb = V + (size_t)bh * SEQ * DK + d;
    float s = 0.f;
    for (int k = 0; k < SEQ; k++) s += vb[(size_t)k * DK];
    mv[bh * DK + d] = s * (1.0f / SEQ);
}

// ---------------------------------------------------------------------------
// Attention: per (q-tile 64, head, batch) CTA, 128 threads, flash-style online
// softmax.  Key tiles start at the diagonal (below-diagonal keys are always
// masked; in fp32, -1e12 + s rounds to -1e12 exactly and exp underflows to 0,
// so skipping them reproduces the reference bit-behavior for any row with an
// unmasked future key).  Fully-masked rows -> uniform attn = meanV.
// ---------------------------------------------------------------------------
#define APAD 68
#define ATT_SMEM ((4*64*APAD)*4 + 64*4)

__global__ void __launch_bounds__(128) attn_kernel(
    const float* __restrict__ Q, const float* __restrict__ K,
    const float* __restrict__ V, const int* __restrict__ amask,
    const int* __restrict__ fm, const float* __restrict__ meanV,
    float* __restrict__ ctx)
{
    extern __shared__ float sm[];
    float* QsT = sm;                  // [d][q]  64 x APAD
    float* KsT = sm + 64*APAD;        // [d][k]
    float* Vs  = sm + 2*64*APAD;      // [k][v]
    float* PsT = sm + 3*64*APAD;      // [k][q]
    int*   msk = (int*)(sm + 4*64*APAD);

    const int qt = blockIdx.x, h = blockIdx.y, b = blockIdx.z;
    const int q0 = qt * 64;
    const int tid = threadIdx.x;
    const int tx = tid & 7;           // key/value column group
    const int ty = tid >> 3;          // query row group

    const size_t bh = (size_t)(b*NHEADS + h) * SEQ * DK;
    const float* Qb = Q + bh;
    const float* Kb = K + bh;
    const float* Vb = V + bh;

    for (int i = tid; i < 64*16; i += 128) {
        int r = i >> 4, c = (i & 15) << 2;
        float4 v = *(const float4*)&Qb[(size_t)(q0 + r)*DK + c];
        QsT[(c+0)*APAD + r] = v.x;
        QsT[(c+1)*APAD + r] = v.y;
        QsT[(c+2)*APAD + r] = v.z;
        QsT[(c+3)*APAD + r] = v.w;
    }

    float m_i[4], l_i[4], acc[4][8];
#pragma unroll
    for (int i = 0; i < 4; i++) {
        m_i[i] = -3.0e38f; l_i[i] = 0.f;
#pragma unroll
        for (int j = 0; j < 8; j++) acc[i][j] = 0.f;
    }

    for (int kt = qt; kt < SEQ/64; kt++) {
        const int k0 = kt * 64;
        __syncthreads();
        for (int i = tid; i < 64*16; i += 128) {
            int r = i >> 4, c = (i & 15) << 2;
            float4 kv = *(const float4*)&Kb[(size_t)(k0 + r)*DK + c];
            KsT[(c+0)*APAD + r] = kv.x;
            KsT[(c+1)*APAD + r] = kv.y;
            KsT[(c+2)*APAD + r] = kv.z;
            KsT[(c+3)*APAD + r] = kv.w;
            float4 vv = *(const float4*)&Vb[(size_t)(k0 + r)*DK + c];
            *(float4*)&Vs[r*APAD + c] = vv;
        }
        if (tid < 64) msk[tid] = amask[b*SEQ + k0 + tid];
        __syncthreads();

        float s[4][8];
#pragma unroll
        for (int i = 0; i < 4; i++)
#pragma unroll
            for (int j = 0; j < 8; j++) s[i][j] = 0.f;
#pragma unroll 8
        for (int d = 0; d < 64; d++) {
            float4 aq = *(const float4*)&QsT[d*APAD + ty*4];
            float4 k0v = *(const float4*)&KsT[d*APAD + tx*8];
            float4 k1v = *(const float4*)&KsT[d*APAD + tx*8 + 4];
            float af[4] = {aq.x, aq.y, aq.z, aq.w};
            float bf[8] = {k0v.x,k0v.y,k0v.z,k0v.w,k1v.x,k1v.y,k1v.z,k1v.w};
#pragma unroll
            for (int i = 0; i < 4; i++)
#pragma unroll
                for (int j = 0; j < 8; j++)
                    s[i][j] = fmaf(af[i], bf[j], s[i][j]);
        }

        int mk[8];
#pragma unroll
        for (int j = 0; j < 8; j++) mk[j] = msk[tx*8 + j];

        float tmax[4];
#pragma unroll
        for (int i = 0; i < 4; i++) {
            const int qg = q0 + ty*4 + i;
            tmax[i] = -3.0e38f;
#pragma unroll
            for (int j = 0; j < 8; j++) {
                const int kg = k0 + tx*8 + j;
                float sc = s[i][j] * 0.125f;
                if (!((mk[j] != 0) && (kg > qg))) sc += NEGV;
                s[i][j] = sc;
                tmax[i] = fmaxf(tmax[i], sc);
            }
        }
#pragma unroll
        for (int i = 0; i < 4; i++) {
            tmax[i] = fmaxf(tmax[i], __shfl_xor_sync(0xffffffffu, tmax[i], 1));
            tmax[i] = fmaxf(tmax[i], __shfl_xor_sync(0xffffffffu, tmax[i], 2));
            tmax[i] = fmaxf(tmax[i], __shfl_xor_sync(0xffffffffu, tmax[i], 4));
        }

#pragma unroll
        for (int i = 0; i < 4; i++) {
            float mnew = fmaxf(m_i[i], tmax[i]);
            float corr = __expf(m_i[i] - mnew);
            float psum = 0.f;
#pragma unroll
            for (int j = 0; j < 8; j++) {
                float p = __expf(s[i][j] - mnew);
                s[i][j] = p;
                psum += p;
            }
            psum += __shfl_xor_sync(0xffffffffu, psum, 1);
            psum += __shfl_xor_sync(0xffffffffu, psum, 2);
            psum += __shfl_xor_sync(0xffffffffu, psum, 4);
            l_i[i] = l_i[i] * corr + psum;
            m_i[i] = mnew;
#pragma unroll
            for (int j = 0; j < 8; j++) acc[i][j] *= corr;
        }

#pragma unroll
        for (int i = 0; i < 4; i++)
#pragma unroll
            for (int j = 0; j < 8; j++)
                PsT[(tx*8 + j)*APAD + (ty*4 + i)] = s[i][j];
        __syncthreads();

#pragma unroll 8
        for (int kk = 0; kk < 64; kk++) {
            float4 pv = *(const float4*)&PsT[kk*APAD + ty*4];
            float4 v0 = *(const float4*)&Vs[kk*APAD + tx*8];
            float4 v1 = *(const float4*)&Vs[kk*APAD + tx*8 + 4];
            float pf[4] = {pv.x, pv.y, pv.z, pv.w};
            float vf[8] = {v0.x,v0.y,v0.z,v0.w,v1.x,v1.y,v1.z,v1.w};
#pragma unroll
            for (int i = 0; i < 4; i++)
#pragma unroll
                for (int j = 0; j < 8; j++)
                    acc[i][j] = fmaf(pf[i], vf[j], acc[i][j]);
        }
    }

    // epilogue
#pragma unroll
    for (int i = 0; i < 4; i++) {
        const int q = q0 + ty*4 + i;
        size_t row = (size_t)b*SEQ + q;
        float* dst = ctx + row*DMODEL + h*DK + tx*8;
        if (fm[b*SEQ + q]) {
            const float* mvp = meanV + (size_t)(b*NHEADS + h)*DK + tx*8;
            *(float4*)dst     = *(const float4*)mvp;
            *(float4*)(dst+4) = *(const float4*)(mvp+4);
        } else {
            float inv = 1.0f / l_i[i];
            *(float4*)dst     = make_float4(acc[i][0]*inv, acc[i][1]*inv,
                                            acc[i][2]*inv, acc[i][3]*inv);
            *(float4*)(dst+4) = make_float4(acc[i][4]*inv, acc[i][5]*inv,
                                            acc[i][6]*inv, acc[i][7]*inv);
        }
    }
}

// ---------------------------------------------------------------------------
// LayerNorm: one CTA per token row (1024 elems, 256 threads)
// ---------------------------------------------------------------------------
__global__ void __launch_bounds__(256) ln_kernel(
    const float* __restrict__ x, const float* __restrict__ gamma,
    const float* __restrict__ beta, float* __restrict__ out)
{
    const int row = blockIdx.x;
    const int tid = threadIdx.x;
    const float* xr = x + (size_t)row * DMODEL;

    float4 v = *(const float4*)&xr[tid*4];
    float s  = v.x + v.y + v.z + v.w;
    float sq = v.x*v.x + v.y*v.y + v.z*v.z + v.w*v.w;
#pragma unroll
    for (int o = 16; o > 0; o >>= 1) {
        s  += __shfl_xor_sync(0xffffffffu, s,  o);
        sq += __shfl_xor_sync(0xffffffffu, sq, o);
    }
    __shared__ float ss[8], ssq[8], smu, sinv;
    const int wid = tid >> 5, lane = tid & 31;
    if (lane == 0) { ss[wid] = s; ssq[wid] = sq; }
    __syncthreads();
    if (tid == 0) {
        float S = 0.f, SQ = 0.f;
#pragma unroll
        for (int i = 0; i < 8; i++) { S += ss[i]; SQ += ssq[i]; }
        float mu = S * (1.0f/DMODEL);
        float var = SQ * (1.0f/DMODEL) - mu*mu;
        smu = mu;
        sinv = rsqrtf(var + 1e-5f);
    }
    __syncthreads();
    float mu = smu, inv = sinv;
    float4 g = *(const float4*)&gamma[tid*4];
    float4 be = *(const float4*)&beta[tid*4];
    float4 o;
    o.x = (v.x - mu) * inv * g.x + be.x;
    o.y = (v.y - mu) * inv * g.y + be.y;
    o.z = (v.z - mu) * inv * g.z + be.z;
    o.w = (v.w - mu) * inv * g.w + be.w;
    *(float4*)&out[(size_t)row*DMODEL + tid*4] = o;
}

// ---------------------------------------------------------------------------
extern "C" void kernel_launch(void* const* d_in, const int* in_sizes, int n_in,
                              void* d_out, int out_size)
{
    const float* inQ   = (const float*)d_in[0];
    const float* inK   = (const float*)d_in[1];
    const float* inV   = (const float*)d_in[2];
    const int*   amask = (const int*)  d_in[3];
    const float* WQ    = (const float*)d_in[4];
    const float* WK    = (const float*)d_in[5];
    const float* WV    = (const float*)d_in[6];
    const float* WO    = (const float*)d_in[7];
    const float* gamma = (const float*)d_in[8];
    const float* beta  = (const float*)d_in[9];
    float* out = (float*)d_out;

    float *Qb, *Kb, *Vb, *ctx, *tmp, *mv;
    int *fmp;
    cudaGetSymbolAddress((void**)&Qb,  g_Q);
    cudaGetSymbolAddress((void**)&Kb,  g_K);
    cudaGetSymbolAddress((void**)&Vb,  g_V);
    cudaGetSymbolAddress((void**)&ctx, g_ctx);
    cudaGetSymbolAddress((void**)&tmp, g_tmp);
    cudaGetSymbolAddress((void**)&mv,  g_meanV);
    cudaGetSymbolAddress((void**)&fmp, g_fm);

    cudaFuncSetAttribute(attn_kernel,
                         cudaFuncAttributeMaxDynamicSharedMemorySize, ATT_SMEM);

    dim3 ggrid(DMODEL/128, NTOK/128);   // (8, 32)
    gemm_mma_kernel<<<ggrid, 256>>>(inQ, WQ, nullptr, Qb, 0);
    gemm_mma_kernel<<<ggrid, 256>>>(inK, WK, nullptr, Kb, 0);
    gemm_mma_kernel<<<ggrid, 256>>>(inV, WV, nullptr, Vb, 0);

    fullmask_kernel<<<dim3(SEQ/1024, BATCH), 1024>>>(amask, fmp);
    meanv_kernel<<<BATCH*NHEADS, DK>>>(Vb, mv);

    attn_kernel<<<dim3(SEQ/64, NHEADS, BATCH), 128, ATT_SMEM>>>(
        Qb, Kb, Vb, amask, fmp, mv, ctx);

    gemm_mma_kernel<<<ggrid, 256>>>(ctx, WO, inQ, tmp, 1);
    ln_kernel<<<NTOK, 256>>>(tmp, gamma, beta, out);
}

// round 5
// speedup vs baseline: 3.9287x; 1.4898x over previous
#include <cuda_runtime.h>
#include <cuda_bf16.h>
#include <cstdint>

// Problem constants
#define BATCH 2
#define SEQ   2048
#define DMODEL 1024
#define NHEADS 16
#define DK    64
#define NTOK  (BATCH*SEQ)          // 4096

// ---------------------------------------------------------------------------
// Scratch (device globals; no runtime allocation allowed)
// ---------------------------------------------------------------------------
__device__ float g_Q[BATCH*NHEADS*SEQ*DK];   // [b,h,s,dk]
__device__ float g_K[BATCH*NHEADS*SEQ*DK];
__device__ float g_V[BATCH*NHEADS*SEQ*DK];
__device__ float g_ctx[NTOK*DMODEL];         // [token, h*64+dk]
__device__ float g_tmp[NTOK*DMODEL];         // pre-LN
__device__ float g_meanV[BATCH*NHEADS*DK];   // mean of V over seq, per (b,h)
__device__ int   g_fm[NTOK];                 // 1 if row has NO unmasked future key

// ---------------------------------------------------------------------------
// mma.sync m16n8k16 bf16 (tcgen05 rejected by this toolchain's ptxas sm_103)
// ---------------------------------------------------------------------------
__device__ __forceinline__ void mma16816(float* c, const uint32_t* a,
                                         const uint32_t* b) {
    asm volatile(
        "mma.sync.aligned.m16n8k16.row.col.f32.bf16.bf16.f32 "
        "{%0,%1,%2,%3}, {%4,%5,%6,%7}, {%8,%9}, {%0,%1,%2,%3};"
        : "+f"(c[0]), "+f"(c[1]), "+f"(c[2]), "+f"(c[3])
        : "r"(a[0]), "r"(a[1]), "r"(a[2]), "r"(a[3]), "r"(b[0]), "r"(b[1]));
}

__device__ __forceinline__ uint32_t pack_bf2(float a, float b) {
    __nv_bfloat162 t = __floats2bfloat162_rn(a, b);
    return *(uint32_t*)&t;
}
__device__ __forceinline__ uint32_t pbits(__nv_bfloat16 a, __nv_bfloat16 b) {
    uint16_t ab = *(uint16_t*)&a, bb = *(uint16_t*)&b;
    return (uint32_t)ab | ((uint32_t)bb << 16);
}

// ---------------------------------------------------------------------------
// Tensor-core GEMM: C[m,n] = sum_k A[m,k] * W[n,k]   (unchanged from round 4)
// fp32 via bf16 split: hi*hi + hi*lo + lo*hi, fp32 accumulate.
// 128x128 CTA tile, 256 threads (8 warps, 2x4 -> 64x32 per warp), k-chunk 32.
// mode 0: scatter to [b,h,s,dk]; mode 1: out = C + resid  ([4096,1024]).
// ---------------------------------------------------------------------------
#define KC 32
#define SROW 20   // uint32 words per row (16 data words + 4 pad)

__global__ void __launch_bounds__(256) gemm_mma_kernel(
    const float* __restrict__ A, const float* __restrict__ W,
    const float* __restrict__ resid, float* __restrict__ outp, int mode)
{
    __shared__ uint32_t sAH[128*SROW];
    __shared__ uint32_t sAL[128*SROW];
    __shared__ uint32_t sWH[128*SROW];
    __shared__ uint32_t sWL[128*SROW];

    const int tid  = threadIdx.x;
    const int wid  = tid >> 5;
    const int lane = tid & 31;
    const int bm = blockIdx.y * 128;
    const int bn = blockIdx.x * 128;

    const int mw = wid & 1;
    const int nw = wid >> 1;
    const int g  = lane >> 2;
    const int kq = lane & 3;

    float acc[4][4][4];
#pragma unroll
    for (int mt = 0; mt < 4; mt++)
#pragma unroll
        for (int nt = 0; nt < 4; nt++)
#pragma unroll
            for (int i = 0; i < 4; i++) acc[mt][nt][i] = 0.f;

    for (int kt = 0; kt < DMODEL / KC; kt++) {
        const int kk = kt * KC;
        __syncthreads();
#pragma unroll
        for (int it = 0; it < 4; it++) {
            const int idx = tid + it * 256;
            const int r = idx >> 3;
            const int c4 = (idx & 7) << 2;
            const int sw = r * SROW + (c4 >> 1);

            float4 v = *(const float4*)&A[(size_t)(bm + r) * DMODEL + kk + c4];
            __nv_bfloat16 h0 = __float2bfloat16(v.x), h1 = __float2bfloat16(v.y);
            __nv_bfloat16 h2 = __float2bfloat16(v.z), h3 = __float2bfloat16(v.w);
            *(uint2*)&sAH[sw] = make_uint2(pbits(h0, h1), pbits(h2, h3));
            *(uint2*)&sAL[sw] = make_uint2(
                pack_bf2(v.x - __bfloat162float(h0), v.y - __bfloat162float(h1)),
                pack_bf2(v.z - __bfloat162float(h2), v.w - __bfloat162float(h3)));

            float4 w = *(const float4*)&W[(size_t)(bn + r) * DMODEL + kk + c4];
            __nv_bfloat16 g0 = __float2bfloat16(w.x), g1 = __float2bfloat16(w.y);
            __nv_bfloat16 g2 = __float2bfloat16(w.z), g3 = __float2bfloat16(w.w);
            *(uint2*)&sWH[sw] = make_uint2(pbits(g0, g1), pbits(g2, g3));
            *(uint2*)&sWL[sw] = make_uint2(
                pack_bf2(w.x - __bfloat162float(g0), w.y - __bfloat162float(g1)),
                pack_bf2(w.z - __bfloat162float(g2), w.w - __bfloat162float(g3)));
        }
        __syncthreads();

#pragma unroll
        for (int ks = 0; ks < 2; ks++) {
            const int kw = ks * 8 + kq;
            uint32_t bH[4][2], bL[4][2];
#pragma unroll
            for (int nt = 0; nt < 4; nt++) {
                const int nrow = nw * 32 + nt * 8 + g;
                bH[nt][0] = sWH[nrow * SROW + kw];
                bH[nt][1] = sWH[nrow * SROW + kw + 4];
                bL[nt][0] = sWL[nrow * SROW + kw];
                bL[nt][1] = sWL[nrow * SROW + kw + 4];
            }
#pragma unroll
            for (int mt = 0; mt < 4; mt++) {
                const int r0 = mw * 64 + mt * 16 + g;
                uint32_t aH[4], aL[4];
                aH[0] = sAH[r0 * SROW + kw];
                aH[1] = sAH[(r0 + 8) * SROW + kw];
                aH[2] = sAH[r0 * SROW + kw + 4];
                aH[3] = sAH[(r0 + 8) * SROW + kw + 4];
                aL[0] = sAL[r0 * SROW + kw];
                aL[1] = sAL[(r0 + 8) * SROW + kw];
                aL[2] = sAL[r0 * SROW + kw + 4];
                aL[3] = sAL[(r0 + 8) * SROW + kw + 4];
#pragma unroll
                for (int nt = 0; nt < 4; nt++) {
                    mma16816(acc[mt][nt], aH, bH[nt]);
                    mma16816(acc[mt][nt], aH, bL[nt]);
                    mma16816(acc[mt][nt], aL, bH[nt]);
                }
            }
        }
    }

#pragma unroll
    for (int mt = 0; mt < 4; mt++) {
#pragma unroll
        for (int nt = 0; nt < 4; nt++) {
            const int m0 = bm + mw * 64 + mt * 16 + g;
            const int n  = bn + nw * 32 + nt * 8 + ((lane & 3) << 1);
#pragma unroll
            for (int half = 0; half < 2; half++) {
                const int m = m0 + half * 8;
                const float c0 = acc[mt][nt][half * 2 + 0];
                const float c1 = acc[mt][nt][half * 2 + 1];
                if (mode == 0) {
                    const int b = m >> 11, s = m & 2047;
                    const int h = n >> 6, d0 = n & 63;
                    float* dst = outp +
                        (((size_t)(b * NHEADS + h) * SEQ + s) * DK + d0);
                    *(float2*)dst = make_float2(c0, c1);
                } else {
                    const size_t off = (size_t)m * DMODEL + n;
                    float2 rs = *(const float2*)&resid[off];
                    *(float2*)&outp[off] = make_float2(c0 + rs.x, c1 + rs.y);
                }
            }
        }
    }
}

// ---------------------------------------------------------------------------
// Helper kernels (unchanged)
// ---------------------------------------------------------------------------
__global__ void fullmask_kernel(const int* __restrict__ amask, int* __restrict__ fm)
{
    const int b = blockIdx.y;
    const int q = blockIdx.x * blockDim.x + threadIdx.x;
    if (q >= SEQ) return;
    const int* m = amask + b * SEQ;
    int any = 0;
    for (int k = q + 1; k < SEQ; k++) { if (m[k]) { any = 1; break; } }
    fm[b * SEQ + q] = !any;
}

__global__ void meanv_kernel(const float* __restrict__ V, float* __restrict__ mv)
{
    const int bh = blockIdx.x;
    const int d = threadIdx.x;
    const float* vb = V + (size_t)bh * SEQ * DK + d;
    float s = 0.f;
    for (int k = 0; k < SEQ; k++) s += vb[(size_t)k * DK];
    mv[bh * DK + d] = s * (1.0f / SEQ);
}

// ---------------------------------------------------------------------------
// Flash attention via mma.sync: 64q x 64k tile per CTA, 128 threads (4 warps,
// each m16).  QK^T and PV on tensor cores with bf16 hi/lo 3-term splits.
// Mask: p = active ? exp(s - m) : 0 (bit-equivalent to reference's +(-1e12)
// for rows with an active key; fully-masked rows overridden with meanV).
// Score accumulators double as PV A-fragments (register pass-through).
// ---------------------------------------------------------------------------
#define WS 36                       // uint32 words per 64-elem bf16 row (+pad)
#define TW (64*WS)                  // words per tile array
#define OQH 0
#define OQL (OQH+TW)
#define OKH (OQL+TW)
#define OKL (OKH+TW)
#define OVH (OKL+TW)
#define OVL (OVH+TW)
#define OMSK (OVL+TW)
#define ATT_SMEM ((OMSK+64)*4)      // 55552 bytes

__global__ void __launch_bounds__(128) attn_mma_kernel(
    const float* __restrict__ Q, const float* __restrict__ K,
    const float* __restrict__ V, const int* __restrict__ amask,
    const int* __restrict__ fm, const float* __restrict__ meanV,
    float* __restrict__ ctx)
{
    extern __shared__ uint32_t sw[];
    const int tid = threadIdx.x;
    const int wid = tid >> 5, lane = tid & 31;
    const int g = lane >> 2, kq = lane & 3;
    const int qt = blockIdx.x, h = blockIdx.y, b = blockIdx.z;
    const int q0 = qt * 64;

    const size_t bhoff = (size_t)(b * NHEADS + h) * SEQ * DK;
    const float* Qb = Q + bhoff;
    const float* Kb = K + bhoff;
    const float* Vb = V + bhoff;

    // ---- load Q tile, hi/lo split, row-major [q][d] ----
    for (int idx = tid; idx < 1024; idx += 128) {
        const int r = idx >> 4, c4 = (idx & 15) << 2;
        float4 v = *(const float4*)&Qb[(size_t)(q0 + r) * DK + c4];
        __nv_bfloat16 h0 = __float2bfloat16(v.x), h1 = __float2bfloat16(v.y);
        __nv_bfloat16 h2 = __float2bfloat16(v.z), h3 = __float2bfloat16(v.w);
        *(uint2*)&sw[OQH + r*WS + (c4 >> 1)] = make_uint2(pbits(h0, h1), pbits(h2, h3));
        *(uint2*)&sw[OQL + r*WS + (c4 >> 1)] = make_uint2(
            pack_bf2(v.x - __bfloat162float(h0), v.y - __bfloat162float(h1)),
            pack_bf2(v.z - __bfloat162float(h2), v.w - __bfloat162float(h3)));
    }
    __syncthreads();

    // ---- Q fragments into registers (reused across all key tiles) ----
    const int qr0 = q0 + wid * 16 + g;
    const int qr1 = qr0 + 8;
    uint32_t aQh[4][4], aQl[4][4];
    {
        const int r0 = wid * 16 + g;
#pragma unroll
        for (int kc = 0; kc < 4; kc++) {
            const int kw = kc * 8 + kq;
            aQh[kc][0] = sw[OQH + r0*WS + kw];
            aQh[kc][1] = sw[OQH + (r0+8)*WS + kw];
            aQh[kc][2] = sw[OQH + r0*WS + kw + 4];
            aQh[kc][3] = sw[OQH + (r0+8)*WS + kw + 4];
            aQl[kc][0] = sw[OQL + r0*WS + kw];
            aQl[kc][1] = sw[OQL + (r0+8)*WS + kw];
            aQl[kc][2] = sw[OQL + r0*WS + kw + 4];
            aQl[kc][3] = sw[OQL + (r0+8)*WS + kw + 4];
        }
    }

    float m0 = -3.0e38f, m1 = -3.0e38f, l0 = 0.f, l1 = 0.f;
    float o[8][4];
#pragma unroll
    for (int dt = 0; dt < 8; dt++)
#pragma unroll
        for (int i = 0; i < 4; i++) o[dt][i] = 0.f;

    __nv_bfloat16* vhp = (__nv_bfloat16*)(sw + OVH);
    __nv_bfloat16* vlp = (__nv_bfloat16*)(sw + OVL);

    for (int kt = qt; kt < SEQ / 64; kt++) {
        const int k0 = kt * 64;
        __syncthreads();   // previous iteration's mma reads done

        // ---- load K (split, [key][d]) and V (split, transposed [d][key]) ----
        for (int idx = tid; idx < 1024; idx += 128) {
            const int r = idx >> 4, c4 = (idx & 15) << 2;
            float4 kv = *(const float4*)&Kb[(size_t)(k0 + r) * DK + c4];
            __nv_bfloat16 h0 = __float2bfloat16(kv.x), h1 = __float2bfloat16(kv.y);
            __nv_bfloat16 h2 = __float2bfloat16(kv.z), h3 = __float2bfloat16(kv.w);
            *(uint2*)&sw[OKH + r*WS + (c4 >> 1)] = make_uint2(pbits(h0, h1), pbits(h2, h3));
            *(uint2*)&sw[OKL + r*WS + (c4 >> 1)] = make_uint2(
                pack_bf2(kv.x - __bfloat162float(h0), kv.y - __bfloat162float(h1)),
                pack_bf2(kv.z - __bfloat162float(h2), kv.w - __bfloat162float(h3)));

            float4 vv = *(const float4*)&Vb[(size_t)(k0 + r) * DK + c4];
            float vf[4] = {vv.x, vv.y, vv.z, vv.w};
#pragma unroll
            for (int j = 0; j < 4; j++) {
                __nv_bfloat16 vh = __float2bfloat16(vf[j]);
                vhp[(c4 + j) * (2*WS) + r] = vh;
                vlp[(c4 + j) * (2*WS) + r] =
                    __float2bfloat16(vf[j] - __bfloat162float(vh));
            }
        }
        if (tid < 64) ((int*)(sw + OMSK))[tid] = amask[b * SEQ + k0 + tid];
        __syncthreads();

        // ---- scores: c[nt][4] = Q . K^T ----
        float c[8][4];
#pragma unroll
        for (int nt = 0; nt < 8; nt++)
#pragma unroll
            for (int i = 0; i < 4; i++) c[nt][i] = 0.f;
#pragma unroll
        for (int kc = 0; kc < 4; kc++) {
            const int kw = kc * 8 + kq;
#pragma unroll
            for (int nt = 0; nt < 8; nt++) {
                const int krow = nt * 8 + g;
                uint32_t bh[2] = { sw[OKH + krow*WS + kw], sw[OKH + krow*WS + kw + 4] };
                uint32_t bl[2] = { sw[OKL + krow*WS + kw], sw[OKL + krow*WS + kw + 4] };
                mma16816(c[nt], aQh[kc], bh);
                mma16816(c[nt], aQh[kc], bl);
                mma16816(c[nt], aQl[kc], bh);
            }
        }

        // ---- activity bits ----
        const int* mk = (const int*)(sw + OMSK);
        uint32_t act0 = 0, act1 = 0;
#pragma unroll
        for (int nt = 0; nt < 8; nt++) {
#pragma unroll
            for (int e = 0; e < 2; e++) {
                const int cl = nt * 8 + 2 * kq + e;
                const int mv_ = mk[cl];
                const int colg = k0 + cl;
                if (mv_ && colg > qr0) act0 |= 1u << (nt * 2 + e);
                if (mv_ && colg > qr1) act1 |= 1u << (nt * 2 + e);
            }
        }

        // ---- scale + masked tile max ----
        float t0 = -3.0e38f, t1 = -3.0e38f;
#pragma unroll
        for (int nt = 0; nt < 8; nt++) {
#pragma unroll
            for (int e = 0; e < 2; e++) {
                float s0 = c[nt][e] * 0.125f;     c[nt][e] = s0;
                float s1 = c[nt][2 + e] * 0.125f; c[nt][2 + e] = s1;
                if ((act0 >> (nt * 2 + e)) & 1) t0 = fmaxf(t0, s0);
                if ((act1 >> (nt * 2 + e)) & 1) t1 = fmaxf(t1, s1);
            }
        }
        t0 = fmaxf(t0, __shfl_xor_sync(0xffffffffu, t0, 1));
        t0 = fmaxf(t0, __shfl_xor_sync(0xffffffffu, t0, 2));
        t1 = fmaxf(t1, __shfl_xor_sync(0xffffffffu, t1, 1));
        t1 = fmaxf(t1, __shfl_xor_sync(0xffffffffu, t1, 2));

        const float mn0 = fmaxf(m0, t0), mn1 = fmaxf(m1, t1);
        const float cr0 = __expf(m0 - mn0), cr1 = __expf(m1 - mn1);
        m0 = mn0; m1 = mn1;

        // ---- p = exp or 0; row sums ----
        float rs0 = 0.f, rs1 = 0.f;
#pragma unroll
        for (int nt = 0; nt < 8; nt++) {
#pragma unroll
            for (int e = 0; e < 2; e++) {
                float p0 = ((act0 >> (nt * 2 + e)) & 1) ? __expf(c[nt][e] - mn0) : 0.f;
                float p1 = ((act1 >> (nt * 2 + e)) & 1) ? __expf(c[nt][2 + e] - mn1) : 0.f;
                c[nt][e] = p0;     rs0 += p0;
                c[nt][2 + e] = p1; rs1 += p1;
            }
        }
        rs0 += __shfl_xor_sync(0xffffffffu, rs0, 1);
        rs0 += __shfl_xor_sync(0xffffffffu, rs0, 2);
        rs1 += __shfl_xor_sync(0xffffffffu, rs1, 1);
        rs1 += __shfl_xor_sync(0xffffffffu, rs1, 2);
        l0 = l0 * cr0 + rs0;
        l1 = l1 * cr1 + rs1;

        // ---- rescale O, then O += P @ V ----
#pragma unroll
        for (int dt = 0; dt < 8; dt++) {
            o[dt][0] *= cr0; o[dt][1] *= cr0;
            o[dt][2] *= cr1; o[dt][3] *= cr1;
        }
#pragma unroll
        for (int kc = 0; kc < 4; kc++) {
            const int tA = 2 * kc, tB = 2 * kc + 1;
            uint32_t aPh[4], aPl[4];
            {
                __nv_bfloat16 h0 = __float2bfloat16(c[tA][0]), h1 = __float2bfloat16(c[tA][1]);
                __nv_bfloat16 h2 = __float2bfloat16(c[tA][2]), h3 = __float2bfloat16(c[tA][3]);
                __nv_bfloat16 h4 = __float2bfloat16(c[tB][0]), h5 = __float2bfloat16(c[tB][1]);
                __nv_bfloat16 h6 = __float2bfloat16(c[tB][2]), h7 = __float2bfloat16(c[tB][3]);
                aPh[0] = pbits(h0, h1); aPh[1] = pbits(h2, h3);
                aPh[2] = pbits(h4, h5); aPh[3] = pbits(h6, h7);
                aPl[0] = pack_bf2(c[tA][0] - __bfloat162float(h0),
                                  c[tA][1] - __bfloat162float(h1));
                aPl[1] = pack_bf2(c[tA][2] - __bfloat162float(h2),
                                  c[tA][3] - __bfloat162float(h3));
                aPl[2] = pack_bf2(c[tB][0] - __bfloat162float(h4),
                                  c[tB][1] - __bfloat162float(h5));
                aPl[3] = pack_bf2(c[tB][2] - __bfloat162float(h6),
                                  c[tB][3] - __bfloat162float(h7));
            }
            const int kw = kc * 8 + kq;
#pragma unroll
            for (int dt = 0; dt < 8; dt++) {
                const int dr = dt * 8 + g;
                uint32_t bh[2] = { sw[OVH + dr*WS + kw], sw[OVH + dr*WS + kw + 4] };
                uint32_t bl[2] = { sw[OVL + dr*WS + kw], sw[OVL + dr*WS + kw + 4] };
                mma16816(o[dt], aPh, bh);
                mma16816(o[dt], aPh, bl);
                mma16816(o[dt], aPl, bh);
            }
        }
    }

    // ---- epilogue ----
    const float inv0 = 1.0f / l0, inv1 = 1.0f / l1;
    const int fm0 = fm[b * SEQ + qr0];
    const int fm1 = fm[b * SEQ + qr1];
    const float* mvb = meanV + (size_t)(b * NHEADS + h) * DK;
#pragma unroll
    for (int dt = 0; dt < 8; dt++) {
        const int d = dt * 8 + 2 * kq;
        float2 mvv = *(const float2*)&mvb[d];
        float2 v0 = fm0 ? mvv : make_float2(o[dt][0] * inv0, o[dt][1] * inv0);
        float2 v1 = fm1 ? mvv : make_float2(o[dt][2] * inv1, o[dt][3] * inv1);
        *(float2*)&ctx[(size_t)(b * SEQ + qr0) * DMODEL + h * DK + d] = v0;
        *(float2*)&ctx[(size_t)(b * SEQ + qr1) * DMODEL + h * DK + d] = v1;
    }
}

// ---------------------------------------------------------------------------
// LayerNorm: one CTA per token row (1024 elems, 256 threads)
// ---------------------------------------------------------------------------
__global__ void __launch_bounds__(256) ln_kernel(
    const float* __restrict__ x, const float* __restrict__ gamma,
    const float* __restrict__ beta, float* __restrict__ out)
{
    const int row = blockIdx.x;
    const int tid = threadIdx.x;
    const float* xr = x + (size_t)row * DMODEL;

    float4 v = *(const float4*)&xr[tid*4];
    float s  = v.x + v.y + v.z + v.w;
    float sq = v.x*v.x + v.y*v.y + v.z*v.z + v.w*v.w;
#pragma unroll
    for (int o = 16; o > 0; o >>= 1) {
        s  += __shfl_xor_sync(0xffffffffu, s,  o);
        sq += __shfl_xor_sync(0xffffffffu, sq, o);
    }
    __shared__ float ss[8], ssq[8], smu, sinv;
    const int wid = tid >> 5, lane = tid & 31;
    if (lane == 0) { ss[wid] = s; ssq[wid] = sq; }
    __syncthreads();
    if (tid == 0) {
        float S = 0.f, SQ = 0.f;
#pragma unroll
        for (int i = 0; i < 8; i++) { S += ss[i]; SQ += ssq[i]; }
        float mu = S * (1.0f/DMODEL);
        float var = SQ * (1.0f/DMODEL) - mu*mu;
        smu = mu;
        sinv = rsqrtf(var + 1e-5f);
    }
    __syncthreads();
    float mu = smu, inv = sinv;
    float4 g = *(const float4*)&gamma[tid*4];
    float4 be = *(const float4*)&beta[tid*4];
    float4 o;
    o.x = (v.x - mu) * inv * g.x + be.x;
    o.y = (v.y - mu) * inv * g.y + be.y;
    o.z = (v.z - mu) * inv * g.z + be.z;
    o.w = (v.w - mu) * inv * g.w + be.w;
    *(float4*)&out[(size_t)row*DMODEL + tid*4] = o;
}

// ---------------------------------------------------------------------------
extern "C" void kernel_launch(void* const* d_in, const int* in_sizes, int n_in,
                              void* d_out, int out_size)
{
    const float* inQ   = (const float*)d_in[0];
    const float* inK   = (const float*)d_in[1];
    const float* inV   = (const float*)d_in[2];
    const int*   amask = (const int*)  d_in[3];
    const float* WQ    = (const float*)d_in[4];
    const float* WK    = (const float*)d_in[5];
    const float* WV    = (const float*)d_in[6];
    const float* WO    = (const float*)d_in[7];
    const float* gamma = (const float*)d_in[8];
    const float* beta  = (const float*)d_in[9];
    float* out = (float*)d_out;

    float *Qb, *Kb, *Vb, *ctx, *tmp, *mv;
    int *fmp;
    cudaGetSymbolAddress((void**)&Qb,  g_Q);
    cudaGetSymbolAddress((void**)&Kb,  g_K);
    cudaGetSymbolAddress((void**)&Vb,  g_V);
    cudaGetSymbolAddress((void**)&ctx, g_ctx);
    cudaGetSymbolAddress((void**)&tmp, g_tmp);
    cudaGetSymbolAddress((void**)&mv,  g_meanV);
    cudaGetSymbolAddress((void**)&fmp, g_fm);

    cudaFuncSetAttribute(attn_mma_kernel,
                         cudaFuncAttributeMaxDynamicSharedMemorySize, ATT_SMEM);

    dim3 ggrid(DMODEL/128, NTOK/128);   // (8, 32)
    gemm_mma_kernel<<<ggrid, 256>>>(inQ, WQ, nullptr, Qb, 0);
    gemm_mma_kernel<<<ggrid, 256>>>(inK, WK, nullptr, Kb, 0);
    gemm_mma_kernel<<<ggrid, 256>>>(inV, WV, nullptr, Vb, 0);

    fullmask_kernel<<<dim3(SEQ/1024, BATCH), 1024>>>(amask, fmp);
    meanv_kernel<<<BATCH*NHEADS, DK>>>(Vb, mv);

    attn_mma_kernel<<<dim3(SEQ/64, NHEADS, BATCH), 128, ATT_SMEM>>>(
        Qb, Kb, Vb, amask, fmp, mv, ctx);

    gemm_mma_kernel<<<ggrid, 256>>>(ctx, WO, inQ, tmp, 1);
    ln_kernel<<<NTOK, 256>>>(tmp, gamma, beta, out);
}

// round 7
// speedup vs baseline: 4.9530x; 1.2607x over previous
#include <cuda_runtime.h>
#include <cuda_bf16.h>
#include <cstdint>

// Problem constants
#define BATCH 2
#define SEQ   2048
#define DMODEL 1024
#define NHEADS 16
#define DK    64
#define NTOK  (BATCH*SEQ)          // 4096
#define BH    (BATCH*NHEADS)       // 32

// ---------------------------------------------------------------------------
// Scratch (device globals; no runtime allocation allowed)
// ---------------------------------------------------------------------------
__device__ __nv_bfloat16 g_inH[3][NTOK*DMODEL];    // split inputs (Q,K,V)
__device__ __nv_bfloat16 g_inL[3][NTOK*DMODEL];
__device__ __nv_bfloat16 g_WH[4][DMODEL*DMODEL];   // split weights (WQ,WK,WV,WO)
__device__ __nv_bfloat16 g_WL[4][DMODEL*DMODEL];
__device__ __nv_bfloat16 g_QH[BH*SEQ*DK], g_QL[BH*SEQ*DK];   // [b,h,s,d]
__device__ __nv_bfloat16 g_KH[BH*SEQ*DK], g_KL[BH*SEQ*DK];
__device__ float         g_V [BH*SEQ*DK];                    // fp32 [b,h,s,d]
__device__ __nv_bfloat16 g_VTH[BH*DK*SEQ], g_VTL[BH*DK*SEQ]; // [b,h,d,s]
__device__ __nv_bfloat16 g_ctxH[NTOK*DMODEL], g_ctxL[NTOK*DMODEL];
__device__ float g_tmp[NTOK*DMODEL];         // pre-LN
__device__ float g_meanV[BH*DK];
__device__ int   g_fm[NTOK];                 // 1 if row has NO unmasked future key

// ---------------------------------------------------------------------------
// mma.sync m16n8k16 bf16 (tcgen05 rejected by this toolchain's ptxas sm_103)
// ---------------------------------------------------------------------------
__device__ __forceinline__ void mma16816(float* c, const uint32_t* a,
                                         const uint32_t* b) {
    asm volatile(
        "mma.sync.aligned.m16n8k16.row.col.f32.bf16.bf16.f32 "
        "{%0,%1,%2,%3}, {%4,%5,%6,%7}, {%8,%9}, {%0,%1,%2,%3};"
        : "+f"(c[0]), "+f"(c[1]), "+f"(c[2]), "+f"(c[3])
        : "r"(a[0]), "r"(a[1]), "r"(a[2]), "r"(a[3]), "r"(b[0]), "r"(b[1]));
}

__device__ __forceinline__ uint32_t pack_bf2(float a, float b) {
    __nv_bfloat162 t = __floats2bfloat162_rn(a, b);
    return *(uint32_t*)&t;
}
__device__ __forceinline__ uint32_t pbits(__nv_bfloat16 a, __nv_bfloat16 b) {
    uint16_t ab = *(uint16_t*)&a, bb = *(uint16_t*)&b;
    return (uint32_t)ab | ((uint32_t)bb << 16);
}

// ---------------------------------------------------------------------------
// Split kernel: fp32 -> (hi, lo) bf16, elementwise (vectorized x4)
// ---------------------------------------------------------------------------
__global__ void __launch_bounds__(256) split_kernel(
    const float4* __restrict__ x, uint2* __restrict__ hi, uint2* __restrict__ lo)
{
    const int i = blockIdx.x * 256 + threadIdx.x;
    float4 v = x[i];
    __nv_bfloat16 h0 = __float2bfloat16(v.x), h1 = __float2bfloat16(v.y);
    __nv_bfloat16 h2 = __float2bfloat16(v.z), h3 = __float2bfloat16(v.w);
    hi[i] = make_uint2(pbits(h0, h1), pbits(h2, h3));
    lo[i] = make_uint2(
        pack_bf2(v.x - __bfloat162float(h0), v.y - __bfloat162float(h1)),
        pack_bf2(v.z - __bfloat162float(h2), v.w - __bfloat162float(h3)));
}

// ---------------------------------------------------------------------------
// GEMM body (shared by QKV-fused and out-proj kernels):
// C[m,n] = sum_k A[m,k]*W[n,k], operands pre-split bf16 hi/lo in gmem.
// fp32 via 3 terms: hi*hi + hi*lo + lo*hi, fp32 accumulate.
// 128x128 CTA tile, 256 threads (8 warps, 2x4 -> 64x32 per warp), k-chunk 32.
// mode 0: write bf16 hi/lo split, scattered to [b,h,s,d]
// mode 1: outF = C + resid ([4096,1024] fp32)
// mode 2: outF fp32 scattered to [b,h,s,d]
// ---------------------------------------------------------------------------
#define KC 32
#define SROW 20   // uint32 words per row (16 data words + 4 pad)

__device__ __forceinline__ void gemm_body(
    const __nv_bfloat16* __restrict__ Ah, const __nv_bfloat16* __restrict__ Al,
    const __nv_bfloat16* __restrict__ Wh, const __nv_bfloat16* __restrict__ Wl,
    const float* __restrict__ resid, float* __restrict__ outF,
    __nv_bfloat16* __restrict__ outH, __nv_bfloat16* __restrict__ outL,
    int mode, uint32_t* sAH, uint32_t* sAL, uint32_t* sWH, uint32_t* sWL)
{
    const int tid  = threadIdx.x;
    const int wid  = tid >> 5;
    const int lane = tid & 31;
    const int bm = blockIdx.y * 128;
    const int bn = blockIdx.x * 128;

    const int mw = wid & 1;
    const int nw = wid >> 1;
    const int g  = lane >> 2;
    const int kq = lane & 3;

    float acc[4][4][4];
#pragma unroll
    for (int mt = 0; mt < 4; mt++)
#pragma unroll
        for (int nt = 0; nt < 4; nt++)
#pragma unroll
            for (int i = 0; i < 4; i++) acc[mt][nt][i] = 0.f;

    for (int kt = 0; kt < DMODEL / KC; kt++) {
        const int kk = kt * KC;
        __syncthreads();
#pragma unroll
        for (int it = 0; it < 2; it++) {
            const int idx = tid + it * 256;       // 0..511
            const int r  = idx >> 2;              // 0..127
            const int ch = idx & 3;               // 16B chunk
            const size_t ga = (size_t)(bm + r) * DMODEL + kk + ch * 8;
            const size_t gw = (size_t)(bn + r) * DMODEL + kk + ch * 8;
            const int so = r * SROW + ch * 4;
            *(uint4*)&sAH[so] = *(const uint4*)&Ah[ga];
            *(uint4*)&sAL[so] = *(const uint4*)&Al[ga];
            *(uint4*)&sWH[so] = *(const uint4*)&Wh[gw];
            *(uint4*)&sWL[so] = *(const uint4*)&Wl[gw];
        }
        __syncthreads();

#pragma unroll
        for (int ks = 0; ks < 2; ks++) {
            const int kw = ks * 8 + kq;
            uint32_t bHf[4][2], bLf[4][2];
#pragma unroll
            for (int nt = 0; nt < 4; nt++) {
                const int nrow = nw * 32 + nt * 8 + g;
                bHf[nt][0] = sWH[nrow * SROW + kw];
                bHf[nt][1] = sWH[nrow * SROW + kw + 4];
                bLf[nt][0] = sWL[nrow * SROW + kw];
                bLf[nt][1] = sWL[nrow * SROW + kw + 4];
            }
#pragma unroll
            for (int mt = 0; mt < 4; mt++) {
                const int r0 = mw * 64 + mt * 16 + g;
                uint32_t aH[4], aL[4];
                aH[0] = sAH[r0 * SROW + kw];
                aH[1] = sAH[(r0 + 8) * SROW + kw];
                aH[2] = sAH[r0 * SROW + kw + 4];
                aH[3] = sAH[(r0 + 8) * SROW + kw + 4];
                aL[0] = sAL[r0 * SROW + kw];
                aL[1] = sAL[(r0 + 8) * SROW + kw];
                aL[2] = sAL[r0 * SROW + kw + 4];
                aL[3] = sAL[(r0 + 8) * SROW + kw + 4];
#pragma unroll
                for (int nt = 0; nt < 4; nt++) {
                    mma16816(acc[mt][nt], aH, bHf[nt]);
                    mma16816(acc[mt][nt], aH, bLf[nt]);
                    mma16816(acc[mt][nt], aL, bHf[nt]);
                }
            }
        }
    }

#pragma unroll
    for (int mt = 0; mt < 4; mt++) {
#pragma unroll
        for (int nt = 0; nt < 4; nt++) {
            const int m0 = bm + mw * 64 + mt * 16 + g;
            const int n  = bn + nw * 32 + nt * 8 + ((lane & 3) << 1);
#pragma unroll
            for (int half = 0; half < 2; half++) {
                const int m = m0 + half * 8;
                const float c0 = acc[mt][nt][half * 2 + 0];
                const float c1 = acc[mt][nt][half * 2 + 1];
                if (mode == 1) {
                    const size_t off = (size_t)m * DMODEL + n;
                    float2 rs = *(const float2*)&resid[off];
                    *(float2*)&outF[off] = make_float2(c0 + rs.x, c1 + rs.y);
                } else {
                    const int b = m >> 11, s = m & 2047;
                    const int h = n >> 6, d0 = n & 63;
                    const size_t p =
                        ((size_t)(b * NHEADS + h) * SEQ + s) * DK + d0;
                    if (mode == 2) {
                        *(float2*)&outF[p] = make_float2(c0, c1);
                    } else {
                        __nv_bfloat16 h0 = __float2bfloat16(c0);
                        __nv_bfloat16 h1 = __float2bfloat16(c1);
                        *(uint32_t*)(outH + p) = pbits(h0, h1);
                        *(uint32_t*)(outL + p) =
                            pack_bf2(c0 - __bfloat162float(h0),
                                     c1 - __bfloat162float(h1));
                    }
                }
            }
        }
    }
}

struct QKVPtrs {
    const __nv_bfloat16 *ah[3], *al[3], *wh[3], *wl[3];
};

__global__ void __launch_bounds__(256) qkv_gemm_kernel(
    QKVPtrs p, __nv_bfloat16* qh, __nv_bfloat16* ql,
    __nv_bfloat16* kh, __nv_bfloat16* kl, float* vout)
{
    __shared__ uint32_t sAH[128*SROW], sAL[128*SROW];
    __shared__ uint32_t sWH[128*SROW], sWL[128*SROW];
    const int z = blockIdx.z;
    __nv_bfloat16* oh = (z == 0) ? qh : kh;
    __nv_bfloat16* ol = (z == 0) ? ql : kl;
    const int mode = (z == 2) ? 2 : 0;
    gemm_body(p.ah[z], p.al[z], p.wh[z], p.wl[z], nullptr, vout, oh, ol,
              mode, sAH, sAL, sWH, sWL);
}

__global__ void __launch_bounds__(256) outproj_gemm_kernel(
    const __nv_bfloat16* __restrict__ ah, const __nv_bfloat16* __restrict__ al,
    const __nv_bfloat16* __restrict__ wh, const __nv_bfloat16* __restrict__ wl,
    const float* __restrict__ resid, float* __restrict__ outF)
{
    __shared__ uint32_t sAH[128*SROW], sAL[128*SROW];
    __shared__ uint32_t sWH[128*SROW], sWL[128*SROW];
    gemm_body(ah, al, wh, wl, resid, outF, nullptr, nullptr, 1,
              sAH, sAL, sWH, sWL);
}

// ---------------------------------------------------------------------------
// V transpose + split: [b,h,s,d] fp32 -> [b,h,d,s] hi/lo bf16 (64x64 tiles)
// ---------------------------------------------------------------------------
__global__ void __launch_bounds__(256) vsplitT_kernel(
    const float* __restrict__ V, __nv_bfloat16* __restrict__ vth,
    __nv_bfloat16* __restrict__ vtl)
{
    __shared__ float tile[64][67];
    const int s0 = blockIdx.x * 64;
    const int bh = blockIdx.y;
    const float* vb = V + (size_t)bh * SEQ * DK;
    for (int idx = threadIdx.x; idx < 64 * 16; idx += 256) {
        const int r = idx >> 4, c4 = (idx & 15) << 2;
        float4 v = *(const float4*)&vb[(size_t)(s0 + r) * DK + c4];
        tile[r][c4] = v.x; tile[r][c4+1] = v.y;
        tile[r][c4+2] = v.z; tile[r][c4+3] = v.w;
    }
    __syncthreads();
    for (int idx = threadIdx.x; idx < 64 * 32; idx += 256) {
        const int d = idx >> 5, sp = idx & 31;
        const float a = tile[2*sp][d], b = tile[2*sp+1][d];
        __nv_bfloat16 ha = __float2bfloat16(a), hb = __float2bfloat16(b);
        const size_t p = ((size_t)bh * DK + d) * SEQ + s0 + 2 * sp;
        *(uint32_t*)(vth + p) = pbits(ha, hb);
        *(uint32_t*)(vtl + p) = pack_bf2(a - __bfloat162float(ha),
                                         b - __bfloat162float(hb));
    }
}

// ---------------------------------------------------------------------------
// Helper kernels
// ---------------------------------------------------------------------------
__global__ void fullmask_kernel(const int* __restrict__ amask, int* __restrict__ fm)
{
    const int b = blockIdx.y;
    const int q = blockIdx.x * blockDim.x + threadIdx.x;
    if (q >= SEQ) return;
    const int* m = amask + b * SEQ;
    int any = 0;
    for (int k = q + 1; k < SEQ; k++) { if (m[k]) { any = 1; break; } }
    fm[b * SEQ + q] = !any;
}

__global__ void meanv_kernel(const float* __restrict__ V, float* __restrict__ mv)
{
    const int bh = blockIdx.x;
    const int d = threadIdx.x;
    const float* vb = V + (size_t)bh * SEQ * DK + d;
    float s = 0.f;
    for (int k = 0; k < SEQ; k++) s += vb[(size_t)k * DK];
    mv[bh * DK + d] = s * (1.0f / SEQ);
}

// ---------------------------------------------------------------------------
// Flash attention via mma.sync: 64q x 64k tile per CTA, 128 threads (4 warps,
// each m16).  All operands pre-split bf16 in gmem -> pure copy into smem.
// Mask: p = active ? exp(s - m) : 0 (bit-equivalent to reference for rows
// with an active key; fully-masked rows overridden with meanV).
// Output written as ctx hi/lo bf16 (pre-split for the out-projection).
// ---------------------------------------------------------------------------
#define WS 36                       // uint32 words per 64-elem bf16 row (+pad)
#define TW (64*WS)                  // words per tile array
#define OQH 0
#define OQL (OQH+TW)
#define OKH (OQL+TW)
#define OKL (OKH+TW)
#define OVH (OKL+TW)
#define OVL (OVH+TW)
#define OMSK (OVL+TW)
#define ATT_SMEM ((OMSK+64)*4)      // 55552 bytes

__global__ void __launch_bounds__(128) attn_mma_kernel(
    const __nv_bfloat16* __restrict__ Qh, const __nv_bfloat16* __restrict__ Ql,
    const __nv_bfloat16* __restrict__ Kh, const __nv_bfloat16* __restrict__ Kl,
    const __nv_bfloat16* __restrict__ Vth, const __nv_bfloat16* __restrict__ Vtl,
    const int* __restrict__ amask, const int* __restrict__ fm,
    const float* __restrict__ meanV,
    __nv_bfloat16* __restrict__ ctxH, __nv_bfloat16* __restrict__ ctxL)
{
    extern __shared__ uint32_t sw[];
    const int tid = threadIdx.x;
    const int wid = tid >> 5, lane = tid & 31;
    const int g = lane >> 2, kq = lane & 3;
    const int qt = blockIdx.x, h = blockIdx.y, b = blockIdx.z;
    const int q0 = qt * 64;

    const size_t bhrow = (size_t)(b * NHEADS + h) * SEQ * DK;   // Q/K base
    const size_t bhcol = (size_t)(b * NHEADS + h) * DK * SEQ;   // VT base

    // ---- load Q tile (pre-split) ----
    for (int idx = tid; idx < 512; idx += 128) {
        const int r = idx >> 3, ch = idx & 7;
        const size_t gp = bhrow + (size_t)(q0 + r) * DK + ch * 8;
        *(uint4*)&sw[OQH + r*WS + ch*4] = *(const uint4*)&Qh[gp];
        *(uint4*)&sw[OQL + r*WS + ch*4] = *(const uint4*)&Ql[gp];
    }
    __syncthreads();

    // ---- Q fragments into registers (reused across all key tiles) ----
    const int qr0 = q0 + wid * 16 + g;
    const int qr1 = qr0 + 8;
    uint32_t aQh[4][4], aQl[4][4];
    {
        const int r0 = wid * 16 + g;
#pragma unroll
        for (int kc = 0; kc < 4; kc++) {
            const int kw = kc * 8 + kq;
            aQh[kc][0] = sw[OQH + r0*WS + kw];
            aQh[kc][1] = sw[OQH + (r0+8)*WS + kw];
            aQh[kc][2] = sw[OQH + r0*WS + kw + 4];
            aQh[kc][3] = sw[OQH + (r0+8)*WS + kw + 4];
            aQl[kc][0] = sw[OQL + r0*WS + kw];
            aQl[kc][1] = sw[OQL + (r0+8)*WS + kw];
            aQl[kc][2] = sw[OQL + r0*WS + kw + 4];
            aQl[kc][3] = sw[OQL + (r0+8)*WS + kw + 4];
        }
    }

    float m0 = -3.0e38f, m1 = -3.0e38f, l0 = 0.f, l1 = 0.f;
    float o[8][4];
#pragma unroll
    for (int dt = 0; dt < 8; dt++)
#pragma unroll
        for (int i = 0; i < 4; i++) o[dt][i] = 0.f;

    for (int kt = qt; kt < SEQ / 64; kt++) {
        const int k0 = kt * 64;
        __syncthreads();   // previous iteration's mma reads done

        // ---- load K rows and VT rows (all pre-split bf16) ----
        for (int idx = tid; idx < 512; idx += 128) {
            const int r = idx >> 3, ch = idx & 7;
            const size_t gk = bhrow + (size_t)(k0 + r) * DK + ch * 8;
            *(uint4*)&sw[OKH + r*WS + ch*4] = *(const uint4*)&Kh[gk];
            *(uint4*)&sw[OKL + r*WS + ch*4] = *(const uint4*)&Kl[gk];
            const size_t gv = bhcol + (size_t)r * SEQ + k0 + ch * 8;
            *(uint4*)&sw[OVH + r*WS + ch*4] = *(const uint4*)&Vth[gv];
            *(uint4*)&sw[OVL + r*WS + ch*4] = *(const uint4*)&Vtl[gv];
        }
        if (tid < 64) ((int*)(sw + OMSK))[tid] = amask[b * SEQ + k0 + tid];
        __syncthreads();

        // ---- scores ----
        float c[8][4];
#pragma unroll
        for (int nt = 0; nt < 8; nt++)
#pragma unroll
            for (int i = 0; i < 4; i++) c[nt][i] = 0.f;
#pragma unroll
        for (int kc = 0; kc < 4; kc++) {
            const int kw = kc * 8 + kq;
#pragma unroll
            for (int nt = 0; nt < 8; nt++) {
                const int krow = nt * 8 + g;
                uint32_t bh2[2] = { sw[OKH + krow*WS + kw], sw[OKH + krow*WS + kw + 4] };
                uint32_t bl2[2] = { sw[OKL + krow*WS + kw], sw[OKL + krow*WS + kw + 4] };
                mma16816(c[nt], aQh[kc], bh2);
                mma16816(c[nt], aQh[kc], bl2);
                mma16816(c[nt], aQl[kc], bh2);
            }
        }

        // ---- activity bits ----
        const int* mk = (const int*)(sw + OMSK);
        uint32_t act0 = 0, act1 = 0;
#pragma unroll
        for (int nt = 0; nt < 8; nt++) {
#pragma unroll
            for (int e = 0; e < 2; e++) {
                const int cl = nt * 8 + 2 * kq + e;
                const int mv_ = mk[cl];
                const int colg = k0 + cl;
                if (mv_ && colg > qr0) act0 |= 1u << (nt * 2 + e);
                if (mv_ && colg > qr1) act1 |= 1u << (nt * 2 + e);
            }
        }

        // ---- scale + masked tile max ----
        float t0 = -3.0e38f, t1 = -3.0e38f;
#pragma unroll
        for (int nt = 0; nt < 8; nt++) {
#pragma unroll
            for (int e = 0; e < 2; e++) {
                float s0 = c[nt][e] * 0.125f;     c[nt][e] = s0;
                float s1 = c[nt][2 + e] * 0.125f; c[nt][2 + e] = s1;
                if ((act0 >> (nt * 2 + e)) & 1) t0 = fmaxf(t0, s0);
                if ((act1 >> (nt * 2 + e)) & 1) t1 = fmaxf(t1, s1);
            }
        }
        t0 = fmaxf(t0, __shfl_xor_sync(0xffffffffu, t0, 1));
        t0 = fmaxf(t0, __shfl_xor_sync(0xffffffffu, t0, 2));
        t1 = fmaxf(t1, __shfl_xor_sync(0xffffffffu, t1, 1));
        t1 = fmaxf(t1, __shfl_xor_sync(0xffffffffu, t1, 2));

        const float mn0 = fmaxf(m0, t0), mn1 = fmaxf(m1, t1);
        const float cr0 = __expf(m0 - mn0), cr1 = __expf(m1 - mn1);
        m0 = mn0; m1 = mn1;

        // ---- p = exp or 0; row sums ----
        float rs0 = 0.f, rs1 = 0.f;
#pragma unroll
        for (int nt = 0; nt < 8; nt++) {
#pragma unroll
            for (int e = 0; e < 2; e++) {
                float p0 = ((act0 >> (nt * 2 + e)) & 1) ? __expf(c[nt][e] - mn0) : 0.f;
                float p1 = ((act1 >> (nt * 2 + e)) & 1) ? __expf(c[nt][2 + e] - mn1) : 0.f;
                c[nt][e] = p0;     rs0 += p0;
                c[nt][2 + e] = p1; rs1 += p1;
            }
        }
        rs0 += __shfl_xor_sync(0xffffffffu, rs0, 1);
        rs0 += __shfl_xor_sync(0xffffffffu, rs0, 2);
        rs1 += __shfl_xor_sync(0xffffffffu, rs1, 1);
        rs1 += __shfl_xor_sync(0xffffffffu, rs1, 2);
        l0 = l0 * cr0 + rs0;
        l1 = l1 * cr1 + rs1;

        // ---- rescale O, then O += P @ V ----
#pragma unroll
        for (int dt = 0; dt < 8; dt++) {
            o[dt][0] *= cr0; o[dt][1] *= cr0;
            o[dt][2] *= cr1; o[dt][3] *= cr1;
        }
#pragma unroll
        for (int kc = 0; kc < 4; kc++) {
            const int tA = 2 * kc, tB = 2 * kc + 1;
            uint32_t aPh[4], aPl[4];
            {
                __nv_bfloat16 h0 = __float2bfloat16(c[tA][0]), h1 = __float2bfloat16(c[tA][1]);
                __nv_bfloat16 h2 = __float2bfloat16(c[tA][2]), h3 = __float2bfloat16(c[tA][3]);
                __nv_bfloat16 h4 = __float2bfloat16(c[tB][0]), h5 = __float2bfloat16(c[tB][1]);
                __nv_bfloat16 h6 = __float2bfloat16(c[tB][2]), h7 = __float2bfloat16(c[tB][3]);
                aPh[0] = pbits(h0, h1); aPh[1] = pbits(h2, h3);
                aPh[2] = pbits(h4, h5); aPh[3] = pbits(h6, h7);
                aPl[0] = pack_bf2(c[tA][0] - __bfloat162float(h0),
                                  c[tA][1] - __bfloat162float(h1));
                aPl[1] = pack_bf2(c[tA][2] - __bfloat162float(h2),
                                  c[tA][3] - __bfloat162float(h3));
                aPl[2] = pack_bf2(c[tB][0] - __bfloat162float(h4),
                                  c[tB][1] - __bfloat162float(h5));
                aPl[3] = pack_bf2(c[tB][2] - __bfloat162float(h6),
                                  c[tB][3] - __bfloat162float(h7));
            }
            const int kw = kc * 8 + kq;
#pragma unroll
            for (int dt = 0; dt < 8; dt++) {
                const int dr = dt * 8 + g;
                uint32_t bh2[2] = { sw[OVH + dr*WS + kw], sw[OVH + dr*WS + kw + 4] };
                uint32_t bl2[2] = { sw[OVL + dr*WS + kw], sw[OVL + dr*WS + kw + 4] };
                mma16816(o[dt], aPh, bh2);
                mma16816(o[dt], aPh, bl2);
                mma16816(o[dt], aPl, bh2);
            }
        }
    }

    // ---- epilogue: write ctx as hi/lo bf16 (pre-split for out-proj) ----
    const float inv0 = 1.0f / l0, inv1 = 1.0f / l1;
    const int fm0 = fm[b * SEQ + qr0];
    const int fm1 = fm[b * SEQ + qr1];
    const float* mvb = meanV + (size_t)(b * NHEADS + h) * DK;
#pragma unroll
    for (int dt = 0; dt < 8; dt++) {
        const int d = dt * 8 + 2 * kq;
        float2 mvv = *(const float2*)&mvb[d];
        float2 v0 = fm0 ? mvv : make_float2(o[dt][0] * inv0, o[dt][1] * inv0);
        float2 v1 = fm1 ? mvv : make_float2(o[dt][2] * inv1, o[dt][3] * inv1);
        const size_t p0 = (size_t)(b * SEQ + qr0) * DMODEL + h * DK + d;
        const size_t p1 = (size_t)(b * SEQ + qr1) * DMODEL + h * DK + d;
        __nv_bfloat16 a0 = __float2bfloat16(v0.x), a1 = __float2bfloat16(v0.y);
        __nv_bfloat16 b0 = __float2bfloat16(v1.x), b1 = __float2bfloat16(v1.y);
        *(uint32_t*)(ctxH + p0) = pbits(a0, a1);
        *(uint32_t*)(ctxL + p0) = pack_bf2(v0.x - __bfloat162float(a0),
                                           v0.y - __bfloat162float(a1));
        *(uint32_t*)(ctxH + p1) = pbits(b0, b1);
        *(uint32_t*)(ctxL + p1) = pack_bf2(v1.x - __bfloat162float(b0),
                                           v1.y - __bfloat162float(b1));
    }
}

// ---------------------------------------------------------------------------
// LayerNorm: one CTA per token row (1024 elems, 256 threads)
// ---------------------------------------------------------------------------
__global__ void __launch_bounds__(256) ln_kernel(
    const float* __restrict__ x, const float* __restrict__ gamma,
    const float* __restrict__ beta, float* __restrict__ out)
{
    const int row = blockIdx.x;
    const int tid = threadIdx.x;
    const float* xr = x + (size_t)row * DMODEL;

    float4 v = *(const float4*)&xr[tid*4];
    float s  = v.x + v.y + v.z + v.w;
    float sq = v.x*v.x + v.y*v.y + v.z*v.z + v.w*v.w;
#pragma unroll
    for (int o = 16; o > 0; o >>= 1) {
        s  += __shfl_xor_sync(0xffffffffu, s,  o);
        sq += __shfl_xor_sync(0xffffffffu, sq, o);
    }
    __shared__ float ss[8], ssq[8], smu, sinv;
    const int wid = tid >> 5, lane = tid & 31;
    if (lane == 0) { ss[wid] = s; ssq[wid] = sq; }
    __syncthreads();
    if (tid == 0) {
        float S = 0.f, SQ = 0.f;
#pragma unroll
        for (int i = 0; i < 8; i++) { S += ss[i]; SQ += ssq[i]; }
        float mu = S * (1.0f/DMODEL);
        float var = SQ * (1.0f/DMODEL) - mu*mu;
        smu = mu;
        sinv = rsqrtf(var + 1e-5f);
    }
    __syncthreads();
    float mu = smu, inv = sinv;
    float4 g = *(const float4*)&gamma[tid*4];
    float4 be = *(const float4*)&beta[tid*4];
    float4 o;
    o.x = (v.x - mu) * inv * g.x + be.x;
    o.y = (v.y - mu) * inv * g.y + be.y;
    o.z = (v.z - mu) * inv * g.z + be.z;
    o.w = (v.w - mu) * inv * g.w + be.w;
    *(float4*)&out[(size_t)row*DMODEL + tid*4] = o;
}

// ---------------------------------------------------------------------------
extern "C" void kernel_launch(void* const* d_in, const int* in_sizes, int n_in,
                              void* d_out, int out_size)
{
    const float* inQ   = (const float*)d_in[0];
    const float* inK   = (const float*)d_in[1];
    const float* inV   = (const float*)d_in[2];
    const int*   amask = (const int*)  d_in[3];
    const float* W[4]  = { (const float*)d_in[4], (const float*)d_in[5],
                           (const float*)d_in[6], (const float*)d_in[7] };
    const float* gamma = (const float*)d_in[8];
    const float* beta  = (const float*)d_in[9];
    float* out = (float*)d_out;

    __nv_bfloat16 *inH, *inL, *WHp, *WLp, *QH, *QL, *KH, *KL, *VTH, *VTL;
    __nv_bfloat16 *ctxH, *ctxL;
    float *Vf, *tmp, *mv;
    int *fmp;
    cudaGetSymbolAddress((void**)&inH,  g_inH);
    cudaGetSymbolAddress((void**)&inL,  g_inL);
    cudaGetSymbolAddress((void**)&WHp,  g_WH);
    cudaGetSymbolAddress((void**)&WLp,  g_WL);
    cudaGetSymbolAddress((void**)&QH,   g_QH);
    cudaGetSymbolAddress((void**)&QL,   g_QL);
    cudaGetSymbolAddress((void**)&KH,   g_KH);
    cudaGetSymbolAddress((void**)&KL,   g_KL);
    cudaGetSymbolAddress((void**)&Vf,   g_V);
    cudaGetSymbolAddress((void**)&VTH,  g_VTH);
    cudaGetSymbolAddress((void**)&VTL,  g_VTL);
    cudaGetSymbolAddress((void**)&ctxH, g_ctxH);
    cudaGetSymbolAddress((void**)&ctxL, g_ctxL);
    cudaGetSymbolAddress((void**)&tmp,  g_tmp);
    cudaGetSymbolAddress((void**)&mv,   g_meanV);
    cudaGetSymbolAddress((void**)&fmp,  g_fm);

    cudaFuncSetAttribute(attn_mma_kernel,
                         cudaFuncAttributeMaxDynamicSharedMemorySize, ATT_SMEM);

    // ---- one-time splits ----
    const float* ins[3] = { inQ, inK, inV };
    const int NIN = NTOK * DMODEL;         // 4M elements
    const int NW  = DMODEL * DMODEL;       // 1M elements
    for (int i = 0; i < 3; i++)
        split_kernel<<<NIN/4/256, 256>>>((const float4*)ins[i],
            (uint2*)(inH + (size_t)i * NIN), (uint2*)(inL + (size_t)i * NIN));
    for (int i = 0; i < 4; i++)
        split_kernel<<<NW/4/256, 256>>>((const float4*)W[i],
            (uint2*)(WHp + (size_t)i * NW), (uint2*)(WLp + (size_t)i * NW));

    // ---- fused QKV projection (grid z selects Q/K/V) ----
    QKVPtrs qp;
    for (int i = 0; i < 3; i++) {
        qp.ah[i] = inH + (size_t)i * NIN;
        qp.al[i] = inL + (size_t)i * NIN;
        qp.wh[i] = WHp + (size_t)i * NW;
        qp.wl[i] = WLp + (size_t)i * NW;
    }
    qkv_gemm_kernel<<<dim3(DMODEL/128, NTOK/128, 3), 256>>>(
        qp, QH, QL, KH, KL, Vf);

    vsplitT_kernel<<<dim3(SEQ/64, BH), 256>>>(Vf, VTH, VTL);
    fullmask_kernel<<<dim3(SEQ/1024, BATCH), 1024>>>(amask, fmp);
    meanv_kernel<<<BH, DK>>>(Vf, mv);

    attn_mma_kernel<<<dim3(SEQ/64, NHEADS, BATCH), 128, ATT_SMEM>>>(
        QH, QL, KH, KL, VTH, VTL, amask, fmp, mv, ctxH, ctxL);

    outproj_gemm_kernel<<<dim3(DMODEL/128, NTOK/128), 256>>>(
        ctxH, ctxL, WHp + (size_t)3 * NW, WLp + (size_t)3 * NW, inQ, tmp);

    ln_kernel<<<NTOK, 256>>>(tmp, gamma, beta, out);
}

// round 10
// speedup vs baseline: 5.2230x; 1.0545x over previous
#include <cuda_runtime.h>
#include <cuda_bf16.h>
#include <cstdint>

// Problem constants
#define BATCH 2
#define SEQ   2048
#define DMODEL 1024
#define NHEADS 16
#define DK    64
#define NTOK  (BATCH*SEQ)          // 4096
#define BH    (BATCH*NHEADS)       // 32

// ---------------------------------------------------------------------------
// Scratch (device globals; no runtime allocation allowed)
// ---------------------------------------------------------------------------
__device__ __nv_bfloat16 g_inH[3][NTOK*DMODEL];    // split inputs (Q,K,V)
__device__ __nv_bfloat16 g_inL[3][NTOK*DMODEL];
__device__ __nv_bfloat16 g_WH[4][DMODEL*DMODEL];   // split weights (WQ,WK,WV,WO)
__device__ __nv_bfloat16 g_WL[4][DMODEL*DMODEL];
__device__ __nv_bfloat16 g_QH[BH*SEQ*DK], g_QL[BH*SEQ*DK];   // [b,h,s,d]
__device__ __nv_bfloat16 g_KH[BH*SEQ*DK], g_KL[BH*SEQ*DK];
__device__ float         g_V [BH*SEQ*DK];                    // fp32 [b,h,s,d]
__device__ __nv_bfloat16 g_VTH[BH*DK*SEQ], g_VTL[BH*DK*SEQ]; // [b,h,d,s]
__device__ __nv_bfloat16 g_ctxH[NTOK*DMODEL], g_ctxL[NTOK*DMODEL];
__device__ float g_tmp[NTOK*DMODEL];         // pre-LN
__device__ float g_meanV[BH*DK];
__device__ int   g_fm[NTOK];                 // 1 if row has NO unmasked future key

// ---------------------------------------------------------------------------
// mma.sync m16n8k16 bf16 (tcgen05 rejected by this toolchain's ptxas sm_103)
// ---------------------------------------------------------------------------
__device__ __forceinline__ void mma16816(float* c, const uint32_t* a,
                                         const uint32_t* b) {
    asm volatile(
        "mma.sync.aligned.m16n8k16.row.col.f32.bf16.bf16.f32 "
        "{%0,%1,%2,%3}, {%4,%5,%6,%7}, {%8,%9}, {%0,%1,%2,%3};"
        : "+f"(c[0]), "+f"(c[1]), "+f"(c[2]), "+f"(c[3])
        : "r"(a[0]), "r"(a[1]), "r"(a[2]), "r"(a[3]), "r"(b[0]), "r"(b[1]));
}

__device__ __forceinline__ uint32_t pack_bf2(float a, float b) {
    __nv_bfloat162 t = __floats2bfloat162_rn(a, b);
    return *(uint32_t*)&t;
}
__device__ __forceinline__ uint32_t pbits(__nv_bfloat16 a, __nv_bfloat16 b) {
    uint16_t ab = *(uint16_t*)&a, bb = *(uint16_t*)&b;
    return (uint32_t)ab | ((uint32_t)bb << 16);
}
__device__ __forceinline__ void cpasync16(uint32_t dst, const void* src) {
    asm volatile("cp.async.cg.shared.global [%0], [%1], 16;"
                 :: "r"(dst), "l"(src));
}
#define CP_COMMIT() asm volatile("cp.async.commit_group;" ::: "memory")
#define CP_WAIT0()  asm volatile("cp.async.wait_group 0;" ::: "memory")

// ---------------------------------------------------------------------------
// Split kernel: fp32 -> (hi, lo) bf16, elementwise (vectorized x4)
// ---------------------------------------------------------------------------
__global__ void __launch_bounds__(256) split_kernel(
    const float4* __restrict__ x, uint2* __restrict__ hi, uint2* __restrict__ lo)
{
    const int i = blockIdx.x * 256 + threadIdx.x;
    float4 v = x[i];
    __nv_bfloat16 h0 = __float2bfloat16(v.x), h1 = __float2bfloat16(v.y);
    __nv_bfloat16 h2 = __float2bfloat16(v.z), h3 = __float2bfloat16(v.w);
    hi[i] = make_uint2(pbits(h0, h1), pbits(h2, h3));
    lo[i] = make_uint2(
        pack_bf2(v.x - __bfloat162float(h0), v.y - __bfloat162float(h1)),
        pack_bf2(v.z - __bfloat162float(h2), v.w - __bfloat162float(h3)));
}

// ---------------------------------------------------------------------------
// GEMM body: C[m,n] = sum_k A[m,k]*W[n,k], operands pre-split bf16 hi/lo.
// 3 terms: hi*hi + hi*lo + lo*hi, fp32 accumulate.
// 128x128 CTA tile, 256 threads, k-chunk 32.
// ---------------------------------------------------------------------------
#define KC 32
#define SROW 20   // uint32 words per row (16 data words + 4 pad)

__device__ __forceinline__ void gemm_body(
    const __nv_bfloat16* __restrict__ Ah, const __nv_bfloat16* __restrict__ Al,
    const __nv_bfloat16* __restrict__ Wh, const __nv_bfloat16* __restrict__ Wl,
    const float* __restrict__ resid, float* __restrict__ outF,
    __nv_bfloat16* __restrict__ outH, __nv_bfloat16* __restrict__ outL,
    int mode, uint32_t* sAH, uint32_t* sAL, uint32_t* sWH, uint32_t* sWL)
{
    const int tid  = threadIdx.x;
    const int wid  = tid >> 5;
    const int lane = tid & 31;
    const int bm = blockIdx.y * 128;
    const int bn = blockIdx.x * 128;

    const int mw = wid & 1;
    const int nw = wid >> 1;
    const int g  = lane >> 2;
    const int kq = lane & 3;

    float acc[4][4][4];
#pragma unroll
    for (int mt = 0; mt < 4; mt++)
#pragma unroll
        for (int nt = 0; nt < 4; nt++)
#pragma unroll
            for (int i = 0; i < 4; i++) acc[mt][nt][i] = 0.f;

    for (int kt = 0; kt < DMODEL / KC; kt++) {
        const int kk = kt * KC;
        __syncthreads();
#pragma unroll
        for (int it = 0; it < 2; it++) {
            const int idx = tid + it * 256;       // 0..511
            const int r  = idx >> 2;              // 0..127
            const int ch = idx & 3;               // 16B chunk
            const size_t ga = (size_t)(bm + r) * DMODEL + kk + ch * 8;
            const size_t gw = (size_t)(bn + r) * DMODEL + kk + ch * 8;
            const int so = r * SROW + ch * 4;
            *(uint4*)&sAH[so] = *(const uint4*)&Ah[ga];
            *(uint4*)&sAL[so] = *(const uint4*)&Al[ga];
            *(uint4*)&sWH[so] = *(const uint4*)&Wh[gw];
            *(uint4*)&sWL[so] = *(const uint4*)&Wl[gw];
        }
        __syncthreads();

#pragma unroll
        for (int ks = 0; ks < 2; ks++) {
            const int kw = ks * 8 + kq;
            uint32_t bHf[4][2], bLf[4][2];
#pragma unroll
            for (int nt = 0; nt < 4; nt++) {
                const int nrow = nw * 32 + nt * 8 + g;
                bHf[nt][0] = sWH[nrow * SROW + kw];
                bHf[nt][1] = sWH[nrow * SROW + kw + 4];
                bLf[nt][0] = sWL[nrow * SROW + kw];
                bLf[nt][1] = sWL[nrow * SROW + kw + 4];
            }
#pragma unroll
            for (int mt = 0; mt < 4; mt++) {
                const int r0 = mw * 64 + mt * 16 + g;
                uint32_t aH[4], aL[4];
                aH[0] = sAH[r0 * SROW + kw];
                aH[1] = sAH[(r0 + 8) * SROW + kw];
                aH[2] = sAH[r0 * SROW + kw + 4];
                aH[3] = sAH[(r0 + 8) * SROW + kw + 4];
                aL[0] = sAL[r0 * SROW + kw];
                aL[1] = sAL[(r0 + 8) * SROW + kw];
                aL[2] = sAL[r0 * SROW + kw + 4];
                aL[3] = sAL[(r0 + 8) * SROW + kw + 4];
#pragma unroll
                for (int nt = 0; nt < 4; nt++) {
                    mma16816(acc[mt][nt], aH, bHf[nt]);
                    mma16816(acc[mt][nt], aH, bLf[nt]);
                    mma16816(acc[mt][nt], aL, bHf[nt]);
                }
            }
        }
    }

#pragma unroll
    for (int mt = 0; mt < 4; mt++) {
#pragma unroll
        for (int nt = 0; nt < 4; nt++) {
            const int m0 = bm + mw * 64 + mt * 16 + g;
            const int n  = bn + nw * 32 + nt * 8 + ((lane & 3) << 1);
#pragma unroll
            for (int half = 0; half < 2; half++) {
                const int m = m0 + half * 8;
                const float c0 = acc[mt][nt][half * 2 + 0];
                const float c1 = acc[mt][nt][half * 2 + 1];
                if (mode == 1) {
                    const size_t off = (size_t)m * DMODEL + n;
                    float2 rs = *(const float2*)&resid[off];
                    *(float2*)&outF[off] = make_float2(c0 + rs.x, c1 + rs.y);
                } else {
                    const int b = m >> 11, s = m & 2047;
                    const int h = n >> 6, d0 = n & 63;
                    const size_t p =
                        ((size_t)(b * NHEADS + h) * SEQ + s) * DK + d0;
                    if (mode == 2) {
                        *(float2*)&outF[p] = make_float2(c0, c1);
                    } else {
                        __nv_bfloat16 h0 = __float2bfloat16(c0);
                        __nv_bfloat16 h1 = __float2bfloat16(c1);
                        *(uint32_t*)(outH + p) = pbits(h0, h1);
                        *(uint32_t*)(outL + p) =
                            pack_bf2(c0 - __bfloat162float(h0),
                                     c1 - __bfloat162float(h1));
                    }
                }
            }
        }
    }
}

struct QKVPtrs {
    const __nv_bfloat16 *ah[3], *al[3], *wh[3], *wl[3];
};

__global__ void __launch_bounds__(256) qkv_gemm_kernel(
    QKVPtrs p, __nv_bfloat16* qh, __nv_bfloat16* ql,
    __nv_bfloat16* kh, __nv_bfloat16* kl, float* vout)
{
    __shared__ uint32_t sAH[128*SROW], sAL[128*SROW];
    __shared__ uint32_t sWH[128*SROW], sWL[128*SROW];
    const int z = blockIdx.z;
    __nv_bfloat16* oh = (z == 0) ? qh : kh;
    __nv_bfloat16* ol = (z == 0) ? ql : kl;
    const int mode = (z == 2) ? 2 : 0;
    gemm_body(p.ah[z], p.al[z], p.wh[z], p.wl[z], nullptr, vout, oh, ol,
              mode, sAH, sAL, sWH, sWL);
}

__global__ void __launch_bounds__(256) outproj_gemm_kernel(
    const __nv_bfloat16* __restrict__ ah, const __nv_bfloat16* __restrict__ al,
    const __nv_bfloat16* __restrict__ wh, const __nv_bfloat16* __restrict__ wl,
    const float* __restrict__ resid, float* __restrict__ outF)
{
    __shared__ uint32_t sAH[128*SROW], sAL[128*SROW];
    __shared__ uint32_t sWH[128*SROW], sWL[128*SROW];
    gemm_body(ah, al, wh, wl, resid, outF, nullptr, nullptr, 1,
              sAH, sAL, sWH, sWL);
}

// ---------------------------------------------------------------------------
// V transpose + split: [b,h,s,d] fp32 -> [b,h,d,s] hi/lo bf16 (64x64 tiles)
// ---------------------------------------------------------------------------
__global__ void __launch_bounds__(256) vsplitT_kernel(
    const float* __restrict__ V, __nv_bfloat16* __restrict__ vth,
    __nv_bfloat16* __restrict__ vtl)
{
    __shared__ float tile[64][67];
    const int s0 = blockIdx.x * 64;
    const int bh = blockIdx.y;
    const float* vb = V + (size_t)bh * SEQ * DK;
    for (int idx = threadIdx.x; idx < 64 * 16; idx += 256) {
        const int r = idx >> 4, c4 = (idx & 15) << 2;
        float4 v = *(const float4*)&vb[(size_t)(s0 + r) * DK + c4];
        tile[r][c4] = v.x; tile[r][c4+1] = v.y;
        tile[r][c4+2] = v.z; tile[r][c4+3] = v.w;
    }
    __syncthreads();
    for (int idx = threadIdx.x; idx < 64 * 32; idx += 256) {
        const int d = idx >> 5, sp = idx & 31;
        const float a = tile[2*sp][d], b = tile[2*sp+1][d];
        __nv_bfloat16 ha = __float2bfloat16(a), hb = __float2bfloat16(b);
        const size_t p = ((size_t)bh * DK + d) * SEQ + s0 + 2 * sp;
        *(uint32_t*)(vth + p) = pbits(ha, hb);
        *(uint32_t*)(vtl + p) = pack_bf2(a - __bfloat162float(ha),
                                         b - __bfloat162float(hb));
    }
}

// ---------------------------------------------------------------------------
// Helper kernels
// ---------------------------------------------------------------------------
__global__ void fullmask_kernel(const int* __restrict__ amask, int* __restrict__ fm)
{
    const int b = blockIdx.y;
    const int q = blockIdx.x * blockDim.x + threadIdx.x;
    if (q >= SEQ) return;
    const int* m = amask + b * SEQ;
    int any = 0;
    for (int k = q + 1; k < SEQ; k++) { if (m[k]) { any = 1; break; } }
    fm[b * SEQ + q] = !any;
}

__global__ void meanv_kernel(const float* __restrict__ V, float* __restrict__ mv)
{
    const int bh = blockIdx.x;
    const int d = threadIdx.x;
    const float* vb = V + (size_t)bh * SEQ * DK + d;
    float s = 0.f;
    for (int k = 0; k < SEQ; k++) s += vb[(size_t)k * DK];
    mv[bh * DK + d] = s * (1.0f / SEQ);
}

// ---------------------------------------------------------------------------
// Flash attention via mma.sync, triangular-paired + cp.async double-buffered.
// CTA qp handles q-tiles qp and 31-qp (each 64 rows) -> every CTA does
// exactly 33 key-tiles: one balanced wave of 512 CTAs.
// Per tile, K (hi/lo, [key][d]) and VT (hi/lo, [d][key]) are prefetched with
// cp.async into the alternate buffer while the current tile computes.
// Q fragments are loaded directly from gmem (no smem staging).
// Mask: p = active ? exp(s-m) : 0; fully-masked rows overridden with meanV.
// ---------------------------------------------------------------------------
#define WS 36                        // uint32 words per 64-elem bf16 row (+pad)
#define TW (64*WS)                   // 2304 words per tile array
#define BUFW (4*TW)                  // 9216 words per buffer (KH,KL,VH,VL)
#define OMSKW (2*BUFW)               // mask area (2 x 64 ints)
#define ATT_SMEM ((OMSKW + 128)*4)   // 74240 bytes

__global__ void __launch_bounds__(128) attn_mma_kernel(
    const __nv_bfloat16* __restrict__ Qh, const __nv_bfloat16* __restrict__ Ql,
    const __nv_bfloat16* __restrict__ Kh, const __nv_bfloat16* __restrict__ Kl,
    const __nv_bfloat16* __restrict__ Vth, const __nv_bfloat16* __restrict__ Vtl,
    const int* __restrict__ amask, const int* __restrict__ fm,
    const float* __restrict__ meanV,
    __nv_bfloat16* __restrict__ ctxH, __nv_bfloat16* __restrict__ ctxL)
{
    extern __shared__ uint32_t sw[];
    const int tid = threadIdx.x;
    const int wid = tid >> 5, lane = tid & 31;
    const int g = lane >> 2, kq = lane & 3;
    const int qp = blockIdx.x, h = blockIdx.y, b = blockIdx.z;

    const size_t bhrow = (size_t)(b * NHEADS + h) * SEQ * DK;   // Q/K base
    const size_t bhcol = (size_t)(b * NHEADS + h) * DK * SEQ;   // VT base
    const int* amask_b = amask + b * SEQ;

    uint32_t sbase;
    {
        size_t a = __cvta_generic_to_shared(sw);
        sbase = (uint32_t)a;
    }

#pragma unroll 1
    for (int halfq = 0; halfq < 2; halfq++) {
        const int qt = (halfq == 0) ? qp : (31 - qp);
        const int q0 = qt * 64;

        // ---- Q fragments straight from gmem ----
        const int qr0 = q0 + wid * 16 + g;
        const int qr1 = qr0 + 8;
        uint32_t aQh[4][4], aQl[4][4];
        {
            const __nv_bfloat16* r0h = Qh + bhrow + (size_t)qr0 * DK;
            const __nv_bfloat16* r1h = Qh + bhrow + (size_t)qr1 * DK;
            const __nv_bfloat16* r0l = Ql + bhrow + (size_t)qr0 * DK;
            const __nv_bfloat16* r1l = Ql + bhrow + (size_t)qr1 * DK;
#pragma unroll
            for (int kc = 0; kc < 4; kc++) {
                const int kw = kc * 8 + kq;
                aQh[kc][0] = *(const uint32_t*)(r0h + kw * 2);
                aQh[kc][1] = *(const uint32_t*)(r1h + kw * 2);
                aQh[kc][2] = *(const uint32_t*)(r0h + (kw + 4) * 2);
                aQh[kc][3] = *(const uint32_t*)(r1h + (kw + 4) * 2);
                aQl[kc][0] = *(const uint32_t*)(r0l + kw * 2);
                aQl[kc][1] = *(const uint32_t*)(r1l + kw * 2);
                aQl[kc][2] = *(const uint32_t*)(r0l + (kw + 4) * 2);
                aQl[kc][3] = *(const uint32_t*)(r1l + (kw + 4) * 2);
            }
        }

        float m0 = -3.0e38f, m1 = -3.0e38f, l0 = 0.f, l1 = 0.f;
        float o[8][4];
#pragma unroll
        for (int dt = 0; dt < 8; dt++)
#pragma unroll
            for (int i = 0; i < 4; i++) o[dt][i] = 0.f;

        const int ktStart = qt;            // first key tile at the diagonal
        const int nkt = SEQ / 64 - ktStart;
        int buf = 0;

        // ---- prefetch first tile ----
        {
            const int k0 = ktStart * 64;
            const uint32_t bb = sbase + buf * (BUFW * 4);
            for (int idx = tid; idx < 512; idx += 128) {
                const int r = idx >> 3, ch = idx & 7;
                const uint32_t so = (r * WS + ch * 4) * 4;
                const size_t gk = bhrow + (size_t)(k0 + r) * DK + ch * 8;
                const size_t gv = bhcol + (size_t)r * SEQ + k0 + ch * 8;
                cpasync16(bb + so, Kh + gk);
                cpasync16(bb + TW * 4 + so, Kl + gk);
                cpasync16(bb + 2 * TW * 4 + so, Vth + gv);
                cpasync16(bb + 3 * TW * 4 + so, Vtl + gv);
            }
            if (tid < 16)
                cpasync16(sbase + (OMSKW + buf * 64 + tid * 4) * 4,
                          amask_b + k0 + tid * 4);
        }
        CP_COMMIT();

#pragma unroll 1
        for (int i = 0; i < nkt; i++) {
            const int kt = ktStart + i;
            const int k0 = kt * 64;
            CP_WAIT0();
            __syncthreads();

            // ---- prefetch next tile into the other buffer ----
            if (i + 1 < nkt) {
                const int kn0 = k0 + 64;
                const uint32_t bb = sbase + (buf ^ 1) * (BUFW * 4);
                for (int idx = tid; idx < 512; idx += 128) {
                    const int r = idx >> 3, ch = idx & 7;
                    const uint32_t so = (r * WS + ch * 4) * 4;
                    const size_t gk = bhrow + (size_t)(kn0 + r) * DK + ch * 8;
                    const size_t gv = bhcol + (size_t)r * SEQ + kn0 + ch * 8;
                    cpasync16(bb + so, Kh + gk);
                    cpasync16(bb + TW * 4 + so, Kl + gk);
                    cpasync16(bb + 2 * TW * 4 + so, Vth + gv);
                    cpasync16(bb + 3 * TW * 4 + so, Vtl + gv);
                }
                if (tid < 16)
                    cpasync16(sbase + (OMSKW + (buf ^ 1) * 64 + tid * 4) * 4,
                              amask_b + kn0 + tid * 4);
            }
            CP_COMMIT();

            const uint32_t kb = buf * BUFW;

            // ---- scores ----
            float c[8][4];
#pragma unroll
            for (int nt = 0; nt < 8; nt++)
#pragma unroll
                for (int j = 0; j < 4; j++) c[nt][j] = 0.f;
#pragma unroll
            for (int kc = 0; kc < 4; kc++) {
                const int kw = kc * 8 + kq;
#pragma unroll
                for (int nt = 0; nt < 8; nt++) {
                    const int krow = nt * 8 + g;
                    uint32_t bh2[2] = { sw[kb + krow*WS + kw],
                                        sw[kb + krow*WS + kw + 4] };
                    uint32_t bl2[2] = { sw[kb + TW + krow*WS + kw],
                                        sw[kb + TW + krow*WS + kw + 4] };
                    mma16816(c[nt], aQh[kc], bh2);
                    mma16816(c[nt], aQh[kc], bl2);
                    mma16816(c[nt], aQl[kc], bh2);
                }
            }

            // ---- activity bits ----
            const int* mk = (const int*)(sw + OMSKW + buf * 64);
            uint32_t act0 = 0, act1 = 0;
#pragma unroll
            for (int nt = 0; nt < 8; nt++) {
#pragma unroll
                for (int e = 0; e < 2; e++) {
                    const int cl = nt * 8 + 2 * kq + e;
                    const int mv_ = mk[cl];
                    const int colg = k0 + cl;
                    if (mv_ && colg > qr0) act0 |= 1u << (nt * 2 + e);
                    if (mv_ && colg > qr1) act1 |= 1u << (nt * 2 + e);
                }
            }

            // ---- scale + masked tile max ----
            float t0 = -3.0e38f, t1 = -3.0e38f;
#pragma unroll
            for (int nt = 0; nt < 8; nt++) {
#pragma unroll
                for (int e = 0; e < 2; e++) {
                    float s0 = c[nt][e] * 0.125f;     c[nt][e] = s0;
                    float s1 = c[nt][2 + e] * 0.125f; c[nt][2 + e] = s1;
                    if ((act0 >> (nt * 2 + e)) & 1) t0 = fmaxf(t0, s0);
                    if ((act1 >> (nt * 2 + e)) & 1) t1 = fmaxf(t1, s1);
                }
            }
            t0 = fmaxf(t0, __shfl_xor_sync(0xffffffffu, t0, 1));
            t0 = fmaxf(t0, __shfl_xor_sync(0xffffffffu, t0, 2));
            t1 = fmaxf(t1, __shfl_xor_sync(0xffffffffu, t1, 1));
            t1 = fmaxf(t1, __shfl_xor_sync(0xffffffffu, t1, 2));

            const float mn0 = fmaxf(m0, t0), mn1 = fmaxf(m1, t1);
            const float cr0 = __expf(m0 - mn0), cr1 = __expf(m1 - mn1);
            m0 = mn0; m1 = mn1;

            // ---- p = exp or 0; row sums ----
            float rs0 = 0.f, rs1 = 0.f;
#pragma unroll
            for (int nt = 0; nt < 8; nt++) {
#pragma unroll
                for (int e = 0; e < 2; e++) {
                    float p0 = ((act0 >> (nt * 2 + e)) & 1)
                               ? __expf(c[nt][e] - mn0) : 0.f;
                    float p1 = ((act1 >> (nt * 2 + e)) & 1)
                               ? __expf(c[nt][2 + e] - mn1) : 0.f;
                    c[nt][e] = p0;     rs0 += p0;
                    c[nt][2 + e] = p1; rs1 += p1;
                }
            }
            rs0 += __shfl_xor_sync(0xffffffffu, rs0, 1);
            rs0 += __shfl_xor_sync(0xffffffffu, rs0, 2);
            rs1 += __shfl_xor_sync(0xffffffffu, rs1, 1);
            rs1 += __shfl_xor_sync(0xffffffffu, rs1, 2);
            l0 = l0 * cr0 + rs0;
            l1 = l1 * cr1 + rs1;

            // ---- rescale O, then O += P @ V ----
#pragma unroll
            for (int dt = 0; dt < 8; dt++) {
                o[dt][0] *= cr0; o[dt][1] *= cr0;
                o[dt][2] *= cr1; o[dt][3] *= cr1;
            }
#pragma unroll
            for (int kc = 0; kc < 4; kc++) {
                const int tA = 2 * kc, tB = 2 * kc + 1;
                uint32_t aPh[4], aPl[4];
                {
                    __nv_bfloat16 h0 = __float2bfloat16(c[tA][0]),
                                  h1 = __float2bfloat16(c[tA][1]);
                    __nv_bfloat16 h2 = __float2bfloat16(c[tA][2]),
                                  h3 = __float2bfloat16(c[tA][3]);
                    __nv_bfloat16 h4 = __float2bfloat16(c[tB][0]),
                                  h5 = __float2bfloat16(c[tB][1]);
                    __nv_bfloat16 h6 = __float2bfloat16(c[tB][2]),
                                  h7 = __float2bfloat16(c[tB][3]);
                    aPh[0] = pbits(h0, h1); aPh[1] = pbits(h2, h3);
                    aPh[2] = pbits(h4, h5); aPh[3] = pbits(h6, h7);
                    aPl[0] = pack_bf2(c[tA][0] - __bfloat162float(h0),
                                      c[tA][1] - __bfloat162float(h1));
                    aPl[1] = pack_bf2(c[tA][2] - __bfloat162float(h2),
                                      c[tA][3] - __bfloat162float(h3));
                    aPl[2] = pack_bf2(c[tB][0] - __bfloat162float(h4),
                                      c[tB][1] - __bfloat162float(h5));
                    aPl[3] = pack_bf2(c[tB][2] - __bfloat162float(h6),
                                      c[tB][3] - __bfloat162float(h7));
                }
                const int kw = kc * 8 + kq;
#pragma unroll
                for (int dt = 0; dt < 8; dt++) {
                    const int dr = dt * 8 + g;
                    uint32_t bh2[2] = { sw[kb + 2*TW + dr*WS + kw],
                                        sw[kb + 2*TW + dr*WS + kw + 4] };
                    uint32_t bl2[2] = { sw[kb + 3*TW + dr*WS + kw],
                                        sw[kb + 3*TW + dr*WS + kw + 4] };
                    mma16816(o[dt], aPh, bh2);
                    mma16816(o[dt], aPh, bl2);
                    mma16816(o[dt], aPl, bh2);
                }
            }
            __syncthreads();
            buf ^= 1;
        }

        // ---- epilogue: write ctx as hi/lo bf16 ----
        const float inv0 = 1.0f / l0, inv1 = 1.0f / l1;
        const int fm0 = fm[b * SEQ + qr0];
        const int fm1 = fm[b * SEQ + qr1];
        const float* mvb = meanV + (size_t)(b * NHEADS + h) * DK;
#pragma unroll
        for (int dt = 0; dt < 8; dt++) {
            const int d = dt * 8 + 2 * kq;
            float2 mvv = *(const float2*)&mvb[d];
            float2 v0 = fm0 ? mvv : make_float2(o[dt][0] * inv0, o[dt][1] * inv0);
            float2 v1 = fm1 ? mvv : make_float2(o[dt][2] * inv1, o[dt][3] * inv1);
            const size_t p0 = (size_t)(b * SEQ + qr0) * DMODEL + h * DK + d;
            const size_t p1 = (size_t)(b * SEQ + qr1) * DMODEL + h * DK + d;
            __nv_bfloat16 a0 = __float2bfloat16(v0.x), a1 = __float2bfloat16(v0.y);
            __nv_bfloat16 b0 = __float2bfloat16(v1.x), b1 = __float2bfloat16(v1.y);
            *(uint32_t*)(ctxH + p0) = pbits(a0, a1);
            *(uint32_t*)(ctxL + p0) = pack_bf2(v0.x - __bfloat162float(a0),
                                               v0.y - __bfloat162float(a1));
            *(uint32_t*)(ctxH + p1) = pbits(b0, b1);
            *(uint32_t*)(ctxL + p1) = pack_bf2(v1.x - __bfloat162float(b0),
                                               v1.y - __bfloat162float(b1));
        }
    }
}

// ---------------------------------------------------------------------------
// LayerNorm: one CTA per token row (1024 elems, 256 threads)
// ---------------------------------------------------------------------------
__global__ void __launch_bounds__(256) ln_kernel(
    const float* __restrict__ x, const float* __restrict__ gamma,
    const float* __restrict__ beta, float* __restrict__ out)
{
    const int row = blockIdx.x;
    const int tid = threadIdx.x;
    const float* xr = x + (size_t)row * DMODEL;

    float4 v = *(const float4*)&xr[tid*4];
    float s  = v.x + v.y + v.z + v.w;
    float sq = v.x*v.x + v.y*v.y + v.z*v.z + v.w*v.w;
#pragma unroll
    for (int o = 16; o > 0; o >>= 1) {
        s  += __shfl_xor_sync(0xffffffffu, s,  o);
        sq += __shfl_xor_sync(0xffffffffu, sq, o);
    }
    __shared__ float ss[8], ssq[8], smu, sinv;
    const int wid = tid >> 5, lane = tid & 31;
    if (lane == 0) { ss[wid] = s; ssq[wid] = sq; }
    __syncthreads();
    if (tid == 0) {
        float S = 0.f, SQ = 0.f;
#pragma unroll
        for (int i = 0; i < 8; i++) { S += ss[i]; SQ += ssq[i]; }
        float mu = S * (1.0f/DMODEL);
        float var = SQ * (1.0f/DMODEL) - mu*mu;
        smu = mu;
        sinv = rsqrtf(var + 1e-5f);
    }
    __syncthreads();
    float mu = smu, inv = sinv;
    float4 g = *(const float4*)&gamma[tid*4];
    float4 be = *(const float4*)&beta[tid*4];
    float4 o;
    o.x = (v.x - mu) * inv * g.x + be.x;
    o.y = (v.y - mu) * inv * g.y + be.y;
    o.z = (v.z - mu) * inv * g.z + be.z;
    o.w = (v.w - mu) * inv * g.w + be.w;
    *(float4*)&out[(size_t)row*DMODEL + tid*4] = o;
}

// ---------------------------------------------------------------------------
extern "C" void kernel_launch(void* const* d_in, const int* in_sizes, int n_in,
                              void* d_out, int out_size)
{
    const float* inQ   = (const float*)d_in[0];
    const float* inK   = (const float*)d_in[1];
    const float* inV   = (const float*)d_in[2];
    const int*   amask = (const int*)  d_in[3];
    const float* W[4]  = { (const float*)d_in[4], (const float*)d_in[5],
                           (const float*)d_in[6], (const float*)d_in[7] };
    const float* gamma = (const float*)d_in[8];
    const float* beta  = (const float*)d_in[9];
    float* out = (float*)d_out;

    __nv_bfloat16 *inH, *inL, *WHp, *WLp, *QH, *QL, *KH, *KL, *VTH, *VTL;
    __nv_bfloat16 *ctxH, *ctxL;
    float *Vf, *tmp, *mv;
    int *fmp;
    cudaGetSymbolAddress((void**)&inH,  g_inH);
    cudaGetSymbolAddress((void**)&inL,  g_inL);
    cudaGetSymbolAddress((void**)&WHp,  g_WH);
    cudaGetSymbolAddress((void**)&WLp,  g_WL);
    cudaGetSymbolAddress((void**)&QH,   g_QH);
    cudaGetSymbolAddress((void**)&QL,   g_QL);
    cudaGetSymbolAddress((void**)&KH,   g_KH);
    cudaGetSymbolAddress((void**)&KL,   g_KL);
    cudaGetSymbolAddress((void**)&Vf,   g_V);
    cudaGetSymbolAddress((void**)&VTH,  g_VTH);
    cudaGetSymbolAddress((void**)&VTL,  g_VTL);
    cudaGetSymbolAddress((void**)&ctxH, g_ctxH);
    cudaGetSymbolAddress((void**)&ctxL, g_ctxL);
    cudaGetSymbolAddress((void**)&tmp,  g_tmp);
    cudaGetSymbolAddress((void**)&mv,   g_meanV);
    cudaGetSymbolAddress((void**)&fmp,  g_fm);

    cudaFuncSetAttribute(attn_mma_kernel,
                         cudaFuncAttributeMaxDynamicSharedMemorySize, ATT_SMEM);

    // ---- one-time splits ----
    const float* ins[3] = { inQ, inK, inV };
    const int NIN = NTOK * DMODEL;         // 4M elements
    const int NW  = DMODEL * DMODEL;       // 1M elements
    for (int i = 0; i < 3; i++)
        split_kernel<<<NIN/4/256, 256>>>((const float4*)ins[i],
            (uint2*)(inH + (size_t)i * NIN), (uint2*)(inL + (size_t)i * NIN));
    for (int i = 0; i < 4; i++)
        split_kernel<<<NW/4/256, 256>>>((const float4*)W[i],
            (uint2*)(WHp + (size_t)i * NW), (uint2*)(WLp + (size_t)i * NW));

    // ---- fused QKV projection (grid z selects Q/K/V) ----
    QKVPtrs qp;
    for (int i = 0; i < 3; i++) {
        qp.ah[i] = inH + (size_t)i * NIN;
        qp.al[i] = inL + (size_t)i * NIN;
        qp.wh[i] = WHp + (size_t)i * NW;
        qp.wl[i] = WLp + (size_t)i * NW;
    }
    qkv_gemm_kernel<<<dim3(DMODEL/128, NTOK/128, 3), 256>>>(
        qp, QH, QL, KH, KL, Vf);

    vsplitT_kernel<<<dim3(SEQ/64, BH), 256>>>(Vf, VTH, VTL);
    fullmask_kernel<<<dim3(SEQ/1024, BATCH), 1024>>>(amask, fmp);
    meanv_kernel<<<BH, DK>>>(Vf, mv);

    attn_mma_kernel<<<dim3(16, NHEADS, BATCH), 128, ATT_SMEM>>>(
        QH, QL, KH, KL, VTH, VTL, amask, fmp, mv, ctxH, ctxL);

    outproj_gemm_kernel<<<dim3(DMODEL/128, NTOK/128), 256>>>(
        ctxH, ctxL, WHp + (size_t)3 * NW, WLp + (size_t)3 * NW, inQ, tmp);

    ln_kernel<<<NTOK, 256>>>(tmp, gamma, beta, out);
}

// round 11
// speedup vs baseline: 5.7405x; 1.0991x over previous
#include <cuda_runtime.h>
#include <cuda_bf16.h>
#include <cstdint>

// Problem constants
#define BATCH 2
#define SEQ   2048
#define DMODEL 1024
#define NHEADS 16
#define DK    64
#define NTOK  (BATCH*SEQ)          // 4096
#define BH    (BATCH*NHEADS)       // 32

// ---------------------------------------------------------------------------
// Scratch (device globals; no runtime allocation allowed)
// ---------------------------------------------------------------------------
__device__ __nv_bfloat16 g_inH[3][NTOK*DMODEL];    // split inputs (Q,K,V)
__device__ __nv_bfloat16 g_inL[3][NTOK*DMODEL];
__device__ __nv_bfloat16 g_WH[4][DMODEL*DMODEL];   // split weights (WQ,WK,WV,WO)
__device__ __nv_bfloat16 g_WL[4][DMODEL*DMODEL];
__device__ __nv_bfloat16 g_QH[BH*SEQ*DK], g_QL[BH*SEQ*DK];   // [b,h,s,d]
__device__ __nv_bfloat16 g_KH[BH*SEQ*DK], g_KL[BH*SEQ*DK];
__device__ float         g_V [BH*SEQ*DK];                    // fp32 [b,h,s,d]
__device__ __nv_bfloat16 g_VTH[BH*DK*SEQ], g_VTL[BH*DK*SEQ]; // [b,h,d,s]
__device__ __nv_bfloat16 g_ctxH[NTOK*DMODEL], g_ctxL[NTOK*DMODEL];
__device__ float g_tmp[NTOK*DMODEL];         // pre-LN
__device__ float g_meanV[BH*DK];
__device__ int   g_fm[NTOK];                 // 1 if row has NO unmasked future key

// ---------------------------------------------------------------------------
// mma.sync m16n8k16 bf16 + ldmatrix (tcgen05 rejected by this ptxas target)
// ---------------------------------------------------------------------------
__device__ __forceinline__ void mma16816(float* c, const uint32_t* a,
                                         const uint32_t* b) {
    asm volatile(
        "mma.sync.aligned.m16n8k16.row.col.f32.bf16.bf16.f32 "
        "{%0,%1,%2,%3}, {%4,%5,%6,%7}, {%8,%9}, {%0,%1,%2,%3};"
        : "+f"(c[0]), "+f"(c[1]), "+f"(c[2]), "+f"(c[3])
        : "r"(a[0]), "r"(a[1]), "r"(a[2]), "r"(a[3]), "r"(b[0]), "r"(b[1]));
}
__device__ __forceinline__ void ldsm_x4(uint32_t* r, uint32_t addr) {
    asm volatile("ldmatrix.sync.aligned.m8n8.x4.shared.b16 {%0,%1,%2,%3}, [%4];"
                 : "=r"(r[0]), "=r"(r[1]), "=r"(r[2]), "=r"(r[3]) : "r"(addr));
}
__device__ __forceinline__ void ldsm_x2(uint32_t* r, uint32_t addr) {
    asm volatile("ldmatrix.sync.aligned.m8n8.x2.shared.b16 {%0,%1}, [%2];"
                 : "=r"(r[0]), "=r"(r[1]) : "r"(addr));
}

__device__ __forceinline__ uint32_t pack_bf2(float a, float b) {
    __nv_bfloat162 t = __floats2bfloat162_rn(a, b);
    return *(uint32_t*)&t;
}
__device__ __forceinline__ uint32_t pbits(__nv_bfloat16 a, __nv_bfloat16 b) {
    uint16_t ab = *(uint16_t*)&a, bb = *(uint16_t*)&b;
    return (uint32_t)ab | ((uint32_t)bb << 16);
}
__device__ __forceinline__ void cpasync16(uint32_t dst, const void* src) {
    asm volatile("cp.async.cg.shared.global [%0], [%1], 16;"
                 :: "r"(dst), "l"(src));
}
#define CP_COMMIT() asm volatile("cp.async.commit_group;" ::: "memory")
#define CP_WAIT0()  asm volatile("cp.async.wait_group 0;" ::: "memory")

// ---------------------------------------------------------------------------
// Split kernels: fp32 -> (hi, lo) bf16, multi-tensor via grid.y
// ---------------------------------------------------------------------------
struct SplitJobs {
    const float4* x[4];
    uint2* hi[4];
    uint2* lo[4];
};

__global__ void __launch_bounds__(256) split_multi_kernel(SplitJobs jb)
{
    const int t = blockIdx.y;
    const int i = blockIdx.x * 256 + threadIdx.x;
    float4 v = jb.x[t][i];
    __nv_bfloat16 h0 = __float2bfloat16(v.x), h1 = __float2bfloat16(v.y);
    __nv_bfloat16 h2 = __float2bfloat16(v.z), h3 = __float2bfloat16(v.w);
    jb.hi[t][i] = make_uint2(pbits(h0, h1), pbits(h2, h3));
    jb.lo[t][i] = make_uint2(
        pack_bf2(v.x - __bfloat162float(h0), v.y - __bfloat162float(h1)),
        pack_bf2(v.z - __bfloat162float(h2), v.w - __bfloat162float(h3)));
}

// ---------------------------------------------------------------------------
// GEMM body: C[m,n] = sum_k A[m,k]*W[n,k], operands pre-split bf16 hi/lo.
// 3 terms: hi*hi + hi*lo + lo*hi, fp32 accumulate.
// 128x128 CTA tile, 256 threads, k-chunk 32, cp.async double-buffered,
// ldmatrix fragment loads.
// ---------------------------------------------------------------------------
#define KC 32
#define SROW 20                // uint32 words per row (16 data words + 4 pad)
#define ARRW (128*SROW)        // 2560 words per array
#define GBUFW (4*ARRW)         // words per buffer (AH,AL,WH,WL)
#define G_SMEM (2*GBUFW*4)     // 81920 bytes

__device__ __forceinline__ void gemm_body(
    const __nv_bfloat16* __restrict__ Ah, const __nv_bfloat16* __restrict__ Al,
    const __nv_bfloat16* __restrict__ Wh, const __nv_bfloat16* __restrict__ Wl,
    const float* __restrict__ resid, float* __restrict__ outF,
    __nv_bfloat16* __restrict__ outH, __nv_bfloat16* __restrict__ outL,
    int mode, uint32_t sb)
{
    const int tid  = threadIdx.x;
    const int wid  = tid >> 5;
    const int lane = tid & 31;
    const int bm = blockIdx.y * 128;
    const int bn = blockIdx.x * 128;

    const int mw = wid & 1;
    const int nw = wid >> 1;
    const int g  = lane >> 2;          (void)g;
    const int lr8 = lane & 7;
    const int lh  = (lane >> 3) & 1;
    const int lq  = lane >> 4;

    float acc[4][4][4];
#pragma unroll
    for (int mt = 0; mt < 4; mt++)
#pragma unroll
        for (int nt = 0; nt < 4; nt++)
#pragma unroll
            for (int i = 0; i < 4; i++) acc[mt][nt][i] = 0.f;

    auto prefetch = [&](int kt, int bsel) {
        const int kk = kt * KC;
        const uint32_t pb = sb + bsel * (GBUFW * 4);
#pragma unroll
        for (int it = 0; it < 2; it++) {
            const int idx = tid + it * 256;       // 0..511
            const int r  = idx >> 2;              // 0..127
            const int ch = idx & 3;               // 16B chunk
            const size_t ga = (size_t)(bm + r) * DMODEL + kk + ch * 8;
            const size_t gw = (size_t)(bn + r) * DMODEL + kk + ch * 8;
            const uint32_t so = (r * SROW + ch * 4) * 4;
            cpasync16(pb + so, Ah + ga);
            cpasync16(pb + ARRW * 4 + so, Al + ga);
            cpasync16(pb + 2 * ARRW * 4 + so, Wh + gw);
            cpasync16(pb + 3 * ARRW * 4 + so, Wl + gw);
        }
    };

    int buf = 0;
    prefetch(0, 0);
    CP_COMMIT();

    for (int kt = 0; kt < DMODEL / KC; kt++) {
        CP_WAIT0();
        __syncthreads();
        if (kt + 1 < DMODEL / KC) prefetch(kt + 1, buf ^ 1);
        CP_COMMIT();

        const uint32_t bb = sb + buf * (GBUFW * 4);
#pragma unroll
        for (int ks = 0; ks < 2; ks++) {
            uint32_t bHf[4][2], bLf[4][2];
#pragma unroll
            for (int nt = 0; nt < 4; nt++) {
                const uint32_t aw = bb +
                    (2 * ARRW + (nw * 32 + nt * 8 + lr8) * SROW
                              + ks * 8 + lh * 4) * 4;
                ldsm_x2(bHf[nt], aw);
                ldsm_x2(bLf[nt], aw + ARRW * 4);
            }
#pragma unroll
            for (int mt = 0; mt < 4; mt++) {
                const uint32_t aw = bb +
                    ((mw * 64 + mt * 16 + lr8 + lh * 8) * SROW
                     + ks * 8 + lq * 4) * 4;
                uint32_t aH[4], aL[4];
                ldsm_x4(aH, aw);
                ldsm_x4(aL, aw + ARRW * 4);
#pragma unroll
                for (int nt = 0; nt < 4; nt++) {
                    mma16816(acc[mt][nt], aH, bHf[nt]);
                    mma16816(acc[mt][nt], aH, bLf[nt]);
                    mma16816(acc[mt][nt], aL, bHf[nt]);
                }
            }
        }
        __syncthreads();
        buf ^= 1;
    }

#pragma unroll
    for (int mt = 0; mt < 4; mt++) {
#pragma unroll
        for (int nt = 0; nt < 4; nt++) {
            const int m0 = bm + mw * 64 + mt * 16 + (lane >> 2);
            const int n  = bn + nw * 32 + nt * 8 + ((lane & 3) << 1);
#pragma unroll
            for (int half = 0; half < 2; half++) {
                const int m = m0 + half * 8;
                const float c0 = acc[mt][nt][half * 2 + 0];
                const float c1 = acc[mt][nt][half * 2 + 1];
                if (mode == 1) {
                    const size_t off = (size_t)m * DMODEL + n;
                    float2 rs = *(const float2*)&resid[off];
                    *(float2*)&outF[off] = make_float2(c0 + rs.x, c1 + rs.y);
                } else {
                    const int b = m >> 11, s = m & 2047;
                    const int h = n >> 6, d0 = n & 63;
                    const size_t p =
                        ((size_t)(b * NHEADS + h) * SEQ + s) * DK + d0;
                    if (mode == 2) {
                        *(float2*)&outF[p] = make_float2(c0, c1);
                    } else {
                        __nv_bfloat16 h0 = __float2bfloat16(c0);
                        __nv_bfloat16 h1 = __float2bfloat16(c1);
                        *(uint32_t*)(outH + p) = pbits(h0, h1);
                        *(uint32_t*)(outL + p) =
                            pack_bf2(c0 - __bfloat162float(h0),
                                     c1 - __bfloat162float(h1));
                    }
                }
            }
        }
    }
}

struct QKVPtrs {
    const __nv_bfloat16 *ah[3], *al[3], *wh[3], *wl[3];
};

__global__ void __launch_bounds__(256) qkv_gemm_kernel(
    QKVPtrs p, __nv_bfloat16* qh, __nv_bfloat16* ql,
    __nv_bfloat16* kh, __nv_bfloat16* kl, float* vout)
{
    extern __shared__ uint32_t gsm[];
    const uint32_t sb = (uint32_t)__cvta_generic_to_shared(gsm);
    const int z = blockIdx.z;
    __nv_bfloat16* oh = (z == 0) ? qh : kh;
    __nv_bfloat16* ol = (z == 0) ? ql : kl;
    const int mode = (z == 2) ? 2 : 0;
    gemm_body(p.ah[z], p.al[z], p.wh[z], p.wl[z], nullptr, vout, oh, ol,
              mode, sb);
}

__global__ void __launch_bounds__(256) outproj_gemm_kernel(
    const __nv_bfloat16* __restrict__ ah, const __nv_bfloat16* __restrict__ al,
    const __nv_bfloat16* __restrict__ wh, const __nv_bfloat16* __restrict__ wl,
    const float* __restrict__ resid, float* __restrict__ outF)
{
    extern __shared__ uint32_t gsm[];
    const uint32_t sb = (uint32_t)__cvta_generic_to_shared(gsm);
    gemm_body(ah, al, wh, wl, resid, outF, nullptr, nullptr, 1, sb);
}

// ---------------------------------------------------------------------------
// V transpose + split: [b,h,s,d] fp32 -> [b,h,d,s] hi/lo bf16 (64x64 tiles)
// ---------------------------------------------------------------------------
__global__ void __launch_bounds__(256) vsplitT_kernel(
    const float* __restrict__ V, __nv_bfloat16* __restrict__ vth,
    __nv_bfloat16* __restrict__ vtl)
{
    __shared__ float tile[64][67];
    const int s0 = blockIdx.x * 64;
    const int bh = blockIdx.y;
    const float* vb = V + (size_t)bh * SEQ * DK;
    for (int idx = threadIdx.x; idx < 64 * 16; idx += 256) {
        const int r = idx >> 4, c4 = (idx & 15) << 2;
        float4 v = *(const float4*)&vb[(size_t)(s0 + r) * DK + c4];
        tile[r][c4] = v.x; tile[r][c4+1] = v.y;
        tile[r][c4+2] = v.z; tile[r][c4+3] = v.w;
    }
    __syncthreads();
    for (int idx = threadIdx.x; idx < 64 * 32; idx += 256) {
        const int d = idx >> 5, sp = idx & 31;
        const float a = tile[2*sp][d], b = tile[2*sp+1][d];
        __nv_bfloat16 ha = __float2bfloat16(a), hb = __float2bfloat16(b);
        const size_t p = ((size_t)bh * DK + d) * SEQ + s0 + 2 * sp;
        *(uint32_t*)(vth + p) = pbits(ha, hb);
        *(uint32_t*)(vtl + p) = pack_bf2(a - __bfloat162float(ha),
                                         b - __bfloat162float(hb));
    }
}

// ---------------------------------------------------------------------------
// Helper kernels
// ---------------------------------------------------------------------------
__global__ void fullmask_kernel(const int* __restrict__ amask, int* __restrict__ fm)
{
    const int b = blockIdx.y;
    const int q = blockIdx.x * blockDim.x + threadIdx.x;
    if (q >= SEQ) return;
    const int* m = amask + b * SEQ;
    int any = 0;
    for (int k = q + 1; k < SEQ; k++) { if (m[k]) { any = 1; break; } }
    fm[b * SEQ + q] = !any;
}

__global__ void __launch_bounds__(256) meanv_kernel(
    const float* __restrict__ V, float* __restrict__ mv)
{
    __shared__ float red[256];
    const int bh = blockIdx.x;
    const int tid = threadIdx.x;
    const int d = tid & 63, seg = tid >> 6;      // 4 segments of 512 rows
    const float* vb = V + (size_t)bh * SEQ * DK + d;
    float s = 0.f;
    for (int k = seg * 512; k < (seg + 1) * 512; k++) s += vb[(size_t)k * DK];
    red[tid] = s;
    __syncthreads();
    if (seg == 0)
        mv[bh * DK + d] = (red[d] + red[64 + d] + red[128 + d] + red[192 + d])
                          * (1.0f / SEQ);
}

// ---------------------------------------------------------------------------
// Flash attention via mma.sync, triangular-paired + cp.async double-buffered,
// ldmatrix fragment loads.  CTA qp handles q-tiles qp and 31-qp.
// Mask: p = active ? exp(s-m) : 0; fully-masked rows overridden with meanV.
// ---------------------------------------------------------------------------
#define WS 36                        // uint32 words per 64-elem bf16 row (+pad)
#define TW (64*WS)                   // 2304 words per tile array
#define BUFW (4*TW)                  // 9216 words per buffer (KH,KL,VH,VL)
#define OMSKW (2*BUFW)               // mask area (2 x 64 ints)
#define ATT_SMEM ((OMSKW + 128)*4)   // 74240 bytes

__global__ void __launch_bounds__(128) attn_mma_kernel(
    const __nv_bfloat16* __restrict__ Qh, const __nv_bfloat16* __restrict__ Ql,
    const __nv_bfloat16* __restrict__ Kh, const __nv_bfloat16* __restrict__ Kl,
    const __nv_bfloat16* __restrict__ Vth, const __nv_bfloat16* __restrict__ Vtl,
    const int* __restrict__ amask, const int* __restrict__ fm,
    const float* __restrict__ meanV,
    __nv_bfloat16* __restrict__ ctxH, __nv_bfloat16* __restrict__ ctxL)
{
    extern __shared__ uint32_t sw[];
    const int tid = threadIdx.x;
    const int wid = tid >> 5, lane = tid & 31;
    const int g = lane >> 2, kq = lane & 3;
    const int alr = lane & 7, alh = (lane >> 3) & 1;
    const int qp = blockIdx.x, h = blockIdx.y, b = blockIdx.z;

    const size_t bhrow = (size_t)(b * NHEADS + h) * SEQ * DK;   // Q/K base
    const size_t bhcol = (size_t)(b * NHEADS + h) * DK * SEQ;   // VT base
    const int* amask_b = amask + b * SEQ;

    const uint32_t sbase = (uint32_t)__cvta_generic_to_shared(sw);

#pragma unroll 1
    for (int halfq = 0; halfq < 2; halfq++) {
        const int qt = (halfq == 0) ? qp : (31 - qp);
        const int q0 = qt * 64;

        // ---- Q fragments straight from gmem ----
        const int qr0 = q0 + wid * 16 + g;
        const int qr1 = qr0 + 8;
        uint32_t aQh[4][4], aQl[4][4];
        {
            const __nv_bfloat16* r0h = Qh + bhrow + (size_t)qr0 * DK;
            const __nv_bfloat16* r1h = Qh + bhrow + (size_t)qr1 * DK;
            const __nv_bfloat16* r0l = Ql + bhrow + (size_t)qr0 * DK;
            const __nv_bfloat16* r1l = Ql + bhrow + (size_t)qr1 * DK;
#pragma unroll
            for (int kc = 0; kc < 4; kc++) {
                const int kw = kc * 8 + kq;
                aQh[kc][0] = *(const uint32_t*)(r0h + kw * 2);
                aQh[kc][1] = *(const uint32_t*)(r1h + kw * 2);
                aQh[kc][2] = *(const uint32_t*)(r0h + (kw + 4) * 2);
                aQh[kc][3] = *(const uint32_t*)(r1h + (kw + 4) * 2);
                aQl[kc][0] = *(const uint32_t*)(r0l + kw * 2);
                aQl[kc][1] = *(const uint32_t*)(r1l + kw * 2);
                aQl[kc][2] = *(const uint32_t*)(r0l + (kw + 4) * 2);
                aQl[kc][3] = *(const uint32_t*)(r1l + (kw + 4) * 2);
            }
        }

        float m0 = -3.0e38f, m1 = -3.0e38f, l0 = 0.f, l1 = 0.f;
        float o[8][4];
#pragma unroll
        for (int dt = 0; dt < 8; dt++)
#pragma unroll
            for (int i = 0; i < 4; i++) o[dt][i] = 0.f;

        const int ktStart = qt;            // first key tile at the diagonal
        const int nkt = SEQ / 64 - ktStart;
        int buf = 0;

        // ---- prefetch first tile ----
        {
            const int k0 = ktStart * 64;
            const uint32_t bb = sbase + buf * (BUFW * 4);
            for (int idx = tid; idx < 512; idx += 128) {
                const int r = idx >> 3, ch = idx & 7;
                const uint32_t so = (r * WS + ch * 4) * 4;
                const size_t gk = bhrow + (size_t)(k0 + r) * DK + ch * 8;
                const size_t gv = bhcol + (size_t)r * SEQ + k0 + ch * 8;
                cpasync16(bb + so, Kh + gk);
                cpasync16(bb + TW * 4 + so, Kl + gk);
                cpasync16(bb + 2 * TW * 4 + so, Vth + gv);
                cpasync16(bb + 3 * TW * 4 + so, Vtl + gv);
            }
            if (tid < 16)
                cpasync16(sbase + (OMSKW + buf * 64 + tid * 4) * 4,
                          amask_b + k0 + tid * 4);
        }
        CP_COMMIT();

#pragma unroll 1
        for (int i = 0; i < nkt; i++) {
            const int kt = ktStart + i;
            const int k0 = kt * 64;
            CP_WAIT0();
            __syncthreads();

            // ---- prefetch next tile into the other buffer ----
            if (i + 1 < nkt) {
                const int kn0 = k0 + 64;
                const uint32_t bb = sbase + (buf ^ 1) * (BUFW * 4);
                for (int idx = tid; idx < 512; idx += 128) {
                    const int r = idx >> 3, ch = idx & 7;
                    const uint32_t so = (r * WS + ch * 4) * 4;
                    const size_t gk = bhrow + (size_t)(kn0 + r) * DK + ch * 8;
                    const size_t gv = bhcol + (size_t)r * SEQ + kn0 + ch * 8;
                    cpasync16(bb + so, Kh + gk);
                    cpasync16(bb + TW * 4 + so, Kl + gk);
                    cpasync16(bb + 2 * TW * 4 + so, Vth + gv);
                    cpasync16(bb + 3 * TW * 4 + so, Vtl + gv);
                }
                if (tid < 16)
                    cpasync16(sbase + (OMSKW + (buf ^ 1) * 64 + tid * 4) * 4,
                              amask_b + kn0 + tid * 4);
            }
            CP_COMMIT();

            const uint32_t kb = buf * BUFW;
            const uint32_t kbb = sbase + kb * 4;

            // ---- scores (ldmatrix K fragments) ----
            float c[8][4];
#pragma unroll
            for (int nt = 0; nt < 8; nt++)
#pragma unroll
                for (int j = 0; j < 4; j++) c[nt][j] = 0.f;
#pragma unroll
            for (int kc = 0; kc < 4; kc++) {
#pragma unroll
                for (int nt = 0; nt < 8; nt++) {
                    const uint32_t aw = kbb +
                        ((nt * 8 + alr) * WS + kc * 8 + alh * 4) * 4;
                    uint32_t bh2[2], bl2[2];
                    ldsm_x2(bh2, aw);
                    ldsm_x2(bl2, aw + TW * 4);
                    mma16816(c[nt], aQh[kc], bh2);
                    mma16816(c[nt], aQh[kc], bl2);
                    mma16816(c[nt], aQl[kc], bh2);
                }
            }

            // ---- activity bits ----
            const int* mk = (const int*)(sw + OMSKW + buf * 64);
            uint32_t act0 = 0, act1 = 0;
#pragma unroll
            for (int nt = 0; nt < 8; nt++) {
#pragma unroll
                for (int e = 0; e < 2; e++) {
                    const int cl = nt * 8 + 2 * kq + e;
                    const int mv_ = mk[cl];
                    const int colg = k0 + cl;
                    if (mv_ && colg > qr0) act0 |= 1u << (nt * 2 + e);
                    if (mv_ && colg > qr1) act1 |= 1u << (nt * 2 + e);
                }
            }

            // ---- scale + masked tile max ----
            float t0 = -3.0e38f, t1 = -3.0e38f;
#pragma unroll
            for (int nt = 0; nt < 8; nt++) {
#pragma unroll
                for (int e = 0; e < 2; e++) {
                    float s0 = c[nt][e] * 0.125f;     c[nt][e] = s0;
                    float s1 = c[nt][2 + e] * 0.125f; c[nt][2 + e] = s1;
                    if ((act0 >> (nt * 2 + e)) & 1) t0 = fmaxf(t0, s0);
                    if ((act1 >> (nt * 2 + e)) & 1) t1 = fmaxf(t1, s1);
                }
            }
            t0 = fmaxf(t0, __shfl_xor_sync(0xffffffffu, t0, 1));
            t0 = fmaxf(t0, __shfl_xor_sync(0xffffffffu, t0, 2));
            t1 = fmaxf(t1, __shfl_xor_sync(0xffffffffu, t1, 1));
            t1 = fmaxf(t1, __shfl_xor_sync(0xffffffffu, t1, 2));

            const float mn0 = fmaxf(m0, t0), mn1 = fmaxf(m1, t1);
            const float cr0 = __expf(m0 - mn0), cr1 = __expf(m1 - mn1);
            m0 = mn0; m1 = mn1;

            // ---- p = exp or 0; row sums ----
            float rs0 = 0.f, rs1 = 0.f;
#pragma unroll
            for (int nt = 0; nt < 8; nt++) {
#pragma unroll
                for (int e = 0; e < 2; e++) {
                    float p0 = ((act0 >> (nt * 2 + e)) & 1)
                               ? __expf(c[nt][e] - mn0) : 0.f;
                    float p1 = ((act1 >> (nt * 2 + e)) & 1)
                               ? __expf(c[nt][2 + e] - mn1) : 0.f;
                    c[nt][e] = p0;     rs0 += p0;
                    c[nt][2 + e] = p1; rs1 += p1;
                }
            }
            rs0 += __shfl_xor_sync(0xffffffffu, rs0, 1);
            rs0 += __shfl_xor_sync(0xffffffffu, rs0, 2);
            rs1 += __shfl_xor_sync(0xffffffffu, rs1, 1);
            rs1 += __shfl_xor_sync(0xffffffffu, rs1, 2);
            l0 = l0 * cr0 + rs0;
            l1 = l1 * cr1 + rs1;

            // ---- rescale O, then O += P @ V (ldmatrix V fragments) ----
#pragma unroll
            for (int dt = 0; dt < 8; dt++) {
                o[dt][0] *= cr0; o[dt][1] *= cr0;
                o[dt][2] *= cr1; o[dt][3] *= cr1;
            }
#pragma unroll
            for (int kc = 0; kc < 4; kc++) {
                const int tA = 2 * kc, tB = 2 * kc + 1;
                uint32_t aPh[4], aPl[4];
                {
                    __nv_bfloat16 h0 = __float2bfloat16(c[tA][0]),
                                  h1 = __float2bfloat16(c[tA][1]);
                    __nv_bfloat16 h2 = __float2bfloat16(c[tA][2]),
                                  h3 = __float2bfloat16(c[tA][3]);
                    __nv_bfloat16 h4 = __float2bfloat16(c[tB][0]),
                                  h5 = __float2bfloat16(c[tB][1]);
                    __nv_bfloat16 h6 = __float2bfloat16(c[tB][2]),
                                  h7 = __float2bfloat16(c[tB][3]);
                    aPh[0] = pbits(h0, h1); aPh[1] = pbits(h2, h3);
                    aPh[2] = pbits(h4, h5); aPh[3] = pbits(h6, h7);
                    aPl[0] = pack_bf2(c[tA][0] - __bfloat162float(h0),
                                      c[tA][1] - __bfloat162float(h1));
                    aPl[1] = pack_bf2(c[tA][2] - __bfloat162float(h2),
                                      c[tA][3] - __bfloat162float(h3));
                    aPl[2] = pack_bf2(c[tB][0] - __bfloat162float(h4),
                                      c[tB][1] - __bfloat162float(h5));
                    aPl[3] = pack_bf2(c[tB][2] - __bfloat162float(h6),
                                      c[tB][3] - __bfloat162float(h7));
                }
#pragma unroll
                for (int dt = 0; dt < 8; dt++) {
                    const uint32_t aw = kbb +
                        (2 * TW + (dt * 8 + alr) * WS + kc * 8 + alh * 4) * 4;
                    uint32_t bh2[2], bl2[2];
                    ldsm_x2(bh2, aw);
                    ldsm_x2(bl2, aw + TW * 4);
                    mma16816(o[dt], aPh, bh2);
                    mma16816(o[dt], aPh, bl2);
                    mma16816(o[dt], aPl, bh2);
                }
            }
            __syncthreads();
            buf ^= 1;
        }

        // ---- epilogue: write ctx as hi/lo bf16 ----
        const float inv0 = 1.0f / l0, inv1 = 1.0f / l1;
        const int fm0 = fm[b * SEQ + qr0];
        const int fm1 = fm[b * SEQ + qr1];
        const float* mvb = meanV + (size_t)(b * NHEADS + h) * DK;
#pragma unroll
        for (int dt = 0; dt < 8; dt++) {
            const int d = dt * 8 + 2 * kq;
            float2 mvv = *(const float2*)&mvb[d];
            float2 v0 = fm0 ? mvv : make_float2(o[dt][0] * inv0, o[dt][1] * inv0);
            float2 v1 = fm1 ? mvv : make_float2(o[dt][2] * inv1, o[dt][3] * inv1);
            const size_t p0 = (size_t)(b * SEQ + qr0) * DMODEL + h * DK + d;
            const size_t p1 = (size_t)(b * SEQ + qr1) * DMODEL + h * DK + d;
            __nv_bfloat16 a0 = __float2bfloat16(v0.x), a1 = __float2bfloat16(v0.y);
            __nv_bfloat16 b0 = __float2bfloat16(v1.x), b1 = __float2bfloat16(v1.y);
            *(uint32_t*)(ctxH + p0) = pbits(a0, a1);
            *(uint32_t*)(ctxL + p0) = pack_bf2(v0.x - __bfloat162float(a0),
                                               v0.y - __bfloat162float(a1));
            *(uint32_t*)(ctxH + p1) = pbits(b0, b1);
            *(uint32_t*)(ctxL + p1) = pack_bf2(v1.x - __bfloat162float(b0),
                                               v1.y - __bfloat162float(b1));
        }
    }
}

// ---------------------------------------------------------------------------
// LayerNorm: one CTA per token row (1024 elems, 256 threads)
// ---------------------------------------------------------------------------
__global__ void __launch_bounds__(256) ln_kernel(
    const float* __restrict__ x, const float* __restrict__ gamma,
    const float* __restrict__ beta, float* __restrict__ out)
{
    const int row = blockIdx.x;
    const int tid = threadIdx.x;
    const float* xr = x + (size_t)row * DMODEL;

    float4 v = *(const float4*)&xr[tid*4];
    float s  = v.x + v.y + v.z + v.w;
    float sq = v.x*v.x + v.y*v.y + v.z*v.z + v.w*v.w;
#pragma unroll
    for (int o = 16; o > 0; o >>= 1) {
        s  += __shfl_xor_sync(0xffffffffu, s,  o);
        sq += __shfl_xor_sync(0xffffffffu, sq, o);
    }
    __shared__ float ss[8], ssq[8], smu, sinv;
    const int wid = tid >> 5, lane = tid & 31;
    if (lane == 0) { ss[wid] = s; ssq[wid] = sq; }
    __syncthreads();
    if (tid == 0) {
        float S = 0.f, SQ = 0.f;
#pragma unroll
        for (int i = 0; i < 8; i++) { S += ss[i]; SQ += ssq[i]; }
        float mu = S * (1.0f/DMODEL);
        float var = SQ * (1.0f/DMODEL) - mu*mu;
        smu = mu;
        sinv = rsqrtf(var + 1e-5f);
    }
    __syncthreads();
    float mu = smu, inv = sinv;
    float4 g = *(const float4*)&gamma[tid*4];
    float4 be = *(const float4*)&beta[tid*4];
    float4 o;
    o.x = (v.x - mu) * inv * g.x + be.x;
    o.y = (v.y - mu) * inv * g.y + be.y;
    o.z = (v.z - mu) * inv * g.z + be.z;
    o.w = (v.w - mu) * inv * g.w + be.w;
    *(float4*)&out[(size_t)row*DMODEL + tid*4] = o;
}

// ---------------------------------------------------------------------------
extern "C" void kernel_launch(void* const* d_in, const int* in_sizes, int n_in,
                              void* d_out, int out_size)
{
    const float* inQ   = (const float*)d_in[0];
    const float* inK   = (const float*)d_in[1];
    const float* inV   = (const float*)d_in[2];
    const int*   amask = (const int*)  d_in[3];
    const float* W[4]  = { (const float*)d_in[4], (const float*)d_in[5],
                           (const float*)d_in[6], (const float*)d_in[7] };
    const float* gamma = (const float*)d_in[8];
    const float* beta  = (const float*)d_in[9];
    float* out = (float*)d_out;

    __nv_bfloat16 *inH, *inL, *WHp, *WLp, *QH, *QL, *KH, *KL, *VTH, *VTL;
    __nv_bfloat16 *ctxH, *ctxL;
    float *Vf, *tmp, *mv;
    int *fmp;
    cudaGetSymbolAddress((void**)&inH,  g_inH);
    cudaGetSymbolAddress((void**)&inL,  g_inL);
    cudaGetSymbolAddress((void**)&WHp,  g_WH);
    cudaGetSymbolAddress((void**)&WLp,  g_WL);
    cudaGetSymbolAddress((void**)&QH,   g_QH);
    cudaGetSymbolAddress((void**)&QL,   g_QL);
    cudaGetSymbolAddress((void**)&KH,   g_KH);
    cudaGetSymbolAddress((void**)&KL,   g_KL);
    cudaGetSymbolAddress((void**)&Vf,   g_V);
    cudaGetSymbolAddress((void**)&VTH,  g_VTH);
    cudaGetSymbolAddress((void**)&VTL,  g_VTL);
    cudaGetSymbolAddress((void**)&ctxH, g_ctxH);
    cudaGetSymbolAddress((void**)&ctxL, g_ctxL);
    cudaGetSymbolAddress((void**)&tmp,  g_tmp);
    cudaGetSymbolAddress((void**)&mv,   g_meanV);
    cudaGetSymbolAddress((void**)&fmp,  g_fm);

    cudaFuncSetAttribute(attn_mma_kernel,
                         cudaFuncAttributeMaxDynamicSharedMemorySize, ATT_SMEM);
    cudaFuncSetAttribute(qkv_gemm_kernel,
                         cudaFuncAttributeMaxDynamicSharedMemorySize, G_SMEM);
    cudaFuncSetAttribute(outproj_gemm_kernel,
                         cudaFuncAttributeMaxDynamicSharedMemorySize, G_SMEM);

    // ---- one-time splits (2 launches) ----
    const float* ins[3] = { inQ, inK, inV };
    const int NIN = NTOK * DMODEL;         // 4M elements
    const int NW  = DMODEL * DMODEL;       // 1M elements
    SplitJobs sji{}, sjw{};
    for (int i = 0; i < 3; i++) {
        sji.x[i]  = (const float4*)ins[i];
        sji.hi[i] = (uint2*)(inH + (size_t)i * NIN);
        sji.lo[i] = (uint2*)(inL + (size_t)i * NIN);
    }
    sji.x[3] = sji.x[0]; sji.hi[3] = sji.hi[0]; sji.lo[3] = sji.lo[0];
    for (int i = 0; i < 4; i++) {
        sjw.x[i]  = (const float4*)W[i];
        sjw.hi[i] = (uint2*)(WHp + (size_t)i * NW);
        sjw.lo[i] = (uint2*)(WLp + (size_t)i * NW);
    }
    split_multi_kernel<<<dim3(NIN/4/256, 3), 256>>>(sji);
    split_multi_kernel<<<dim3(NW/4/256, 4), 256>>>(sjw);

    // ---- fused QKV projection (grid z selects Q/K/V) ----
    QKVPtrs qp;
    for (int i = 0; i < 3; i++) {
        qp.ah[i] = inH + (size_t)i * NIN;
        qp.al[i] = inL + (size_t)i * NIN;
        qp.wh[i] = WHp + (size_t)i * NW;
        qp.wl[i] = WLp + (size_t)i * NW;
    }
    qkv_gemm_kernel<<<dim3(DMODEL/128, NTOK/128, 3), 256, G_SMEM>>>(
        qp, QH, QL, KH, KL, Vf);

    vsplitT_kernel<<<dim3(SEQ/64, BH), 256>>>(Vf, VTH, VTL);
    fullmask_kernel<<<dim3(SEQ/1024, BATCH), 1024>>>(amask, fmp);
    meanv_kernel<<<BH, 256>>>(Vf, mv);

    attn_mma_kernel<<<dim3(16, NHEADS, BATCH), 128, ATT_SMEM>>>(
        QH, QL, KH, KL, VTH, VTL, amask, fmp, mv, ctxH, ctxL);

    outproj_gemm_kernel<<<dim3(DMODEL/128, NTOK/128), 256, G_SMEM>>>(
        ctxH, ctxL, WHp + (size_t)3 * NW, WLp + (size_t)3 * NW, inQ, tmp);

    ln_kernel<<<NTOK, 256>>>(tmp, gamma, beta, out);
}

// round 12
// speedup vs baseline: 5.9014x; 1.0280x over previous
#include <cuda_runtime.h>
#include <cuda_bf16.h>
#include <cstdint>

// Problem constants
#define BATCH 2
#define SEQ   2048
#define DMODEL 1024
#define NHEADS 16
#define DK    64
#define NTOK  (BATCH*SEQ)          // 4096
#define BH    (BATCH*NHEADS)       // 32

// ---------------------------------------------------------------------------
// Scratch (device globals; no runtime allocation allowed)
// ---------------------------------------------------------------------------
__device__ __nv_bfloat16 g_inH[3][NTOK*DMODEL];    // split inputs (Q,K,V)
__device__ __nv_bfloat16 g_inL[3][NTOK*DMODEL];
__device__ __nv_bfloat16 g_WH[4][DMODEL*DMODEL];   // split weights (WQ,WK,WV,WO)
__device__ __nv_bfloat16 g_WL[4][DMODEL*DMODEL];
__device__ __nv_bfloat16 g_QH[BH*SEQ*DK], g_QL[BH*SEQ*DK];   // [b,h,s,d]
__device__ __nv_bfloat16 g_KH[BH*SEQ*DK], g_KL[BH*SEQ*DK];
__device__ float         g_V [BH*SEQ*DK];                    // fp32 [b,h,s,d]
__device__ __nv_bfloat16 g_VTH[BH*DK*SEQ], g_VTL[BH*DK*SEQ]; // [b,h,d,s]
__device__ __nv_bfloat16 g_ctxH[NTOK*DMODEL], g_ctxL[NTOK*DMODEL];
__device__ float g_tmp[NTOK*DMODEL];         // pre-LN
__device__ float g_meanV[BH*DK];
__device__ int   g_fm[NTOK];                 // 1 if row has NO unmasked future key

// ---------------------------------------------------------------------------
// mma.sync m16n8k16 bf16 + ldmatrix (tcgen05 rejected by this ptxas target)
// ---------------------------------------------------------------------------
__device__ __forceinline__ void mma16816(float* c, const uint32_t* a,
                                         const uint32_t* b) {
    asm volatile(
        "mma.sync.aligned.m16n8k16.row.col.f32.bf16.bf16.f32 "
        "{%0,%1,%2,%3}, {%4,%5,%6,%7}, {%8,%9}, {%0,%1,%2,%3};"
        : "+f"(c[0]), "+f"(c[1]), "+f"(c[2]), "+f"(c[3])
        : "r"(a[0]), "r"(a[1]), "r"(a[2]), "r"(a[3]), "r"(b[0]), "r"(b[1]));
}
__device__ __forceinline__ void ldsm_x4(uint32_t* r, uint32_t addr) {
    asm volatile("ldmatrix.sync.aligned.m8n8.x4.shared.b16 {%0,%1,%2,%3}, [%4];"
                 : "=r"(r[0]), "=r"(r[1]), "=r"(r[2]), "=r"(r[3]) : "r"(addr));
}
__device__ __forceinline__ void ldsm_x2(uint32_t* r, uint32_t addr) {
    asm volatile("ldmatrix.sync.aligned.m8n8.x2.shared.b16 {%0,%1}, [%2];"
                 : "=r"(r[0]), "=r"(r[1]) : "r"(addr));
}

__device__ __forceinline__ uint32_t pack_bf2(float a, float b) {
    __nv_bfloat162 t = __floats2bfloat162_rn(a, b);
    return *(uint32_t*)&t;
}
__device__ __forceinline__ uint32_t pbits(__nv_bfloat16 a, __nv_bfloat16 b) {
    uint16_t ab = *(uint16_t*)&a, bb = *(uint16_t*)&b;
    return (uint32_t)ab | ((uint32_t)bb << 16);
}
__device__ __forceinline__ void cpasync16(uint32_t dst, const void* src) {
    asm volatile("cp.async.cg.shared.global [%0], [%1], 16;"
                 :: "r"(dst), "l"(src));
}
#define CP_COMMIT() asm volatile("cp.async.commit_group;" ::: "memory")
#define CP_WAIT0()  asm volatile("cp.async.wait_group 0;" ::: "memory")

// ---------------------------------------------------------------------------
// Split kernels: fp32 -> (hi, lo) bf16, multi-tensor via grid.y
// ---------------------------------------------------------------------------
struct SplitJobs {
    const float4* x[4];
    uint2* hi[4];
    uint2* lo[4];
};

__global__ void __launch_bounds__(256) split_multi_kernel(SplitJobs jb)
{
    const int t = blockIdx.y;
    const int i = blockIdx.x * 256 + threadIdx.x;
    float4 v = jb.x[t][i];
    __nv_bfloat16 h0 = __float2bfloat16(v.x), h1 = __float2bfloat16(v.y);
    __nv_bfloat16 h2 = __float2bfloat16(v.z), h3 = __float2bfloat16(v.w);
    jb.hi[t][i] = make_uint2(pbits(h0, h1), pbits(h2, h3));
    jb.lo[t][i] = make_uint2(
        pack_bf2(v.x - __bfloat162float(h0), v.y - __bfloat162float(h1)),
        pack_bf2(v.z - __bfloat162float(h2), v.w - __bfloat162float(h3)));
}

// ---------------------------------------------------------------------------
// GEMM body: C[m,n] = sum_k A[m,k]*W[n,k], operands pre-split bf16 hi/lo.
// 3 terms: hi*hi + hi*lo + lo*hi, fp32 accumulate.
// 128x128 CTA tile, 256 threads, k-chunk 32, cp.async double-buffered,
// ldmatrix fragment loads.
// ---------------------------------------------------------------------------
#define KC 32
#define SROW 20                // uint32 words per row (16 data words + 4 pad)
#define ARRW (128*SROW)        // 2560 words per array
#define GBUFW (4*ARRW)         // words per buffer (AH,AL,WH,WL)
#define G_SMEM (2*GBUFW*4)     // 81920 bytes

__device__ __forceinline__ void gemm_body(
    const __nv_bfloat16* __restrict__ Ah, const __nv_bfloat16* __restrict__ Al,
    const __nv_bfloat16* __restrict__ Wh, const __nv_bfloat16* __restrict__ Wl,
    const float* __restrict__ resid, float* __restrict__ outF,
    __nv_bfloat16* __restrict__ outH, __nv_bfloat16* __restrict__ outL,
    int mode, uint32_t sb)
{
    const int tid  = threadIdx.x;
    const int wid  = tid >> 5;
    const int lane = tid & 31;
    const int bm = blockIdx.y * 128;
    const int bn = blockIdx.x * 128;

    const int mw = wid & 1;
    const int nw = wid >> 1;
    const int lr8 = lane & 7;
    const int lh  = (lane >> 3) & 1;
    const int lq  = lane >> 4;

    float acc[4][4][4];
#pragma unroll
    for (int mt = 0; mt < 4; mt++)
#pragma unroll
        for (int nt = 0; nt < 4; nt++)
#pragma unroll
            for (int i = 0; i < 4; i++) acc[mt][nt][i] = 0.f;

    auto prefetch = [&](int kt, int bsel) {
        const int kk = kt * KC;
        const uint32_t pb = sb + bsel * (GBUFW * 4);
#pragma unroll
        for (int it = 0; it < 2; it++) {
            const int idx = tid + it * 256;       // 0..511
            const int r  = idx >> 2;              // 0..127
            const int ch = idx & 3;               // 16B chunk
            const size_t ga = (size_t)(bm + r) * DMODEL + kk + ch * 8;
            const size_t gw = (size_t)(bn + r) * DMODEL + kk + ch * 8;
            const uint32_t so = (r * SROW + ch * 4) * 4;
            cpasync16(pb + so, Ah + ga);
            cpasync16(pb + ARRW * 4 + so, Al + ga);
            cpasync16(pb + 2 * ARRW * 4 + so, Wh + gw);
            cpasync16(pb + 3 * ARRW * 4 + so, Wl + gw);
        }
    };

    int buf = 0;
    prefetch(0, 0);
    CP_COMMIT();

    for (int kt = 0; kt < DMODEL / KC; kt++) {
        CP_WAIT0();
        __syncthreads();
        if (kt + 1 < DMODEL / KC) prefetch(kt + 1, buf ^ 1);
        CP_COMMIT();

        const uint32_t bb = sb + buf * (GBUFW * 4);
#pragma unroll
        for (int ks = 0; ks < 2; ks++) {
            uint32_t bHf[4][2], bLf[4][2];
#pragma unroll
            for (int nt = 0; nt < 4; nt++) {
                const uint32_t aw = bb +
                    (2 * ARRW + (nw * 32 + nt * 8 + lr8) * SROW
                              + ks * 8 + lh * 4) * 4;
                ldsm_x2(bHf[nt], aw);
                ldsm_x2(bLf[nt], aw + ARRW * 4);
            }
#pragma unroll
            for (int mt = 0; mt < 4; mt++) {
                const uint32_t aw = bb +
                    ((mw * 64 + mt * 16 + lr8 + lh * 8) * SROW
                     + ks * 8 + lq * 4) * 4;
                uint32_t aH[4], aL[4];
                ldsm_x4(aH, aw);
                ldsm_x4(aL, aw + ARRW * 4);
#pragma unroll
                for (int nt = 0; nt < 4; nt++) {
                    mma16816(acc[mt][nt], aH, bHf[nt]);
                    mma16816(acc[mt][nt], aH, bLf[nt]);
                    mma16816(acc[mt][nt], aL, bHf[nt]);
                }
            }
        }
        __syncthreads();
        buf ^= 1;
    }

#pragma unroll
    for (int mt = 0; mt < 4; mt++) {
#pragma unroll
        for (int nt = 0; nt < 4; nt++) {
            const int m0 = bm + mw * 64 + mt * 16 + (lane >> 2);
            const int n  = bn + nw * 32 + nt * 8 + ((lane & 3) << 1);
#pragma unroll
            for (int half = 0; half < 2; half++) {
                const int m = m0 + half * 8;
                const float c0 = acc[mt][nt][half * 2 + 0];
                const float c1 = acc[mt][nt][half * 2 + 1];
                if (mode == 1) {
                    const size_t off = (size_t)m * DMODEL + n;
                    float2 rs = *(const float2*)&resid[off];
                    *(float2*)&outF[off] = make_float2(c0 + rs.x, c1 + rs.y);
                } else {
                    const int b = m >> 11, s = m & 2047;
                    const int h = n >> 6, d0 = n & 63;
                    const size_t p =
                        ((size_t)(b * NHEADS + h) * SEQ + s) * DK + d0;
                    if (mode == 2) {
                        *(float2*)&outF[p] = make_float2(c0, c1);
                    } else {
                        __nv_bfloat16 h0 = __float2bfloat16(c0);
                        __nv_bfloat16 h1 = __float2bfloat16(c1);
                        *(uint32_t*)(outH + p) = pbits(h0, h1);
                        *(uint32_t*)(outL + p) =
                            pack_bf2(c0 - __bfloat162float(h0),
                                     c1 - __bfloat162float(h1));
                    }
                }
            }
        }
    }
}

struct QKVPtrs {
    const __nv_bfloat16 *ah[3], *al[3], *wh[3], *wl[3];
};

__global__ void __launch_bounds__(256) qkv_gemm_kernel(
    QKVPtrs p, __nv_bfloat16* qh, __nv_bfloat16* ql,
    __nv_bfloat16* kh, __nv_bfloat16* kl, float* vout)
{
    extern __shared__ uint32_t gsm[];
    const uint32_t sb = (uint32_t)__cvta_generic_to_shared(gsm);
    const int z = blockIdx.z;
    __nv_bfloat16* oh = (z == 0) ? qh : kh;
    __nv_bfloat16* ol = (z == 0) ? ql : kl;
    const int mode = (z == 2) ? 2 : 0;
    gemm_body(p.ah[z], p.al[z], p.wh[z], p.wl[z], nullptr, vout, oh, ol,
              mode, sb);
}

__global__ void __launch_bounds__(256) outproj_gemm_kernel(
    const __nv_bfloat16* __restrict__ ah, const __nv_bfloat16* __restrict__ al,
    const __nv_bfloat16* __restrict__ wh, const __nv_bfloat16* __restrict__ wl,
    const float* __restrict__ resid, float* __restrict__ outF)
{
    extern __shared__ uint32_t gsm[];
    const uint32_t sb = (uint32_t)__cvta_generic_to_shared(gsm);
    gemm_body(ah, al, wh, wl, resid, outF, nullptr, nullptr, 1, sb);
}

// ---------------------------------------------------------------------------
// V transpose + split: [b,h,s,d] fp32 -> [b,h,d,s] hi/lo bf16 (64x64 tiles)
// ---------------------------------------------------------------------------
__global__ void __launch_bounds__(256) vsplitT_kernel(
    const float* __restrict__ V, __nv_bfloat16* __restrict__ vth,
    __nv_bfloat16* __restrict__ vtl)
{
    __shared__ float tile[64][67];
    const int s0 = blockIdx.x * 64;
    const int bh = blockIdx.y;
    const float* vb = V + (size_t)bh * SEQ * DK;
    for (int idx = threadIdx.x; idx < 64 * 16; idx += 256) {
        const int r = idx >> 4, c4 = (idx & 15) << 2;
        float4 v = *(const float4*)&vb[(size_t)(s0 + r) * DK + c4];
        tile[r][c4] = v.x; tile[r][c4+1] = v.y;
        tile[r][c4+2] = v.z; tile[r][c4+3] = v.w;
    }
    __syncthreads();
    for (int idx = threadIdx.x; idx < 64 * 32; idx += 256) {
        const int d = idx >> 5, sp = idx & 31;
        const float a = tile[2*sp][d], b = tile[2*sp+1][d];
        __nv_bfloat16 ha = __float2bfloat16(a), hb = __float2bfloat16(b);
        const size_t p = ((size_t)bh * DK + d) * SEQ + s0 + 2 * sp;
        *(uint32_t*)(vth + p) = pbits(ha, hb);
        *(uint32_t*)(vtl + p) = pack_bf2(a - __bfloat162float(ha),
                                         b - __bfloat162float(hb));
    }
}

// ---------------------------------------------------------------------------
// Helper kernels
// ---------------------------------------------------------------------------
__global__ void fullmask_kernel(const int* __restrict__ amask, int* __restrict__ fm)
{
    const int b = blockIdx.y;
    const int q = blockIdx.x * blockDim.x + threadIdx.x;
    if (q >= SEQ) return;
    const int* m = amask + b * SEQ;
    int any = 0;
    for (int k = q + 1; k < SEQ; k++) { if (m[k]) { any = 1; break; } }
    fm[b * SEQ + q] = !any;
}

__global__ void __launch_bounds__(256) meanv_kernel(
    const float* __restrict__ V, float* __restrict__ mv)
{
    __shared__ float red[256];
    const int bh = blockIdx.x;
    const int tid = threadIdx.x;
    const int d = tid & 63, seg = tid >> 6;      // 4 segments of 512 rows
    const float* vb = V + (size_t)bh * SEQ * DK + d;
    float s = 0.f;
    for (int k = seg * 512; k < (seg + 1) * 512; k++) s += vb[(size_t)k * DK];
    red[tid] = s;
    __syncthreads();
    if (seg == 0)
        mv[bh * DK + d] = (red[d] + red[64 + d] + red[128 + d] + red[192 + d])
                          * (1.0f / SEQ);
}

// ---------------------------------------------------------------------------
// Flash attention via mma.sync: 128-row q-tiles (8 warps, 256 threads),
// triangular-paired (CTA qp handles q-tiles qp and 15-qp -> 34 key-tiles
// each), cp.async double-buffered K/V, ldmatrix fragment loads.
// 256 CTAs at 2 CTAs/SM -> one balanced wave.
// Mask: p = active ? exp(s-m) : 0; fully-masked rows overridden with meanV.
// ---------------------------------------------------------------------------
#define WS 36                        // uint32 words per 64-elem bf16 row (+pad)
#define TW (64*WS)                   // 2304 words per tile array
#define BUFW (4*TW)                  // 9216 words per buffer (KH,KL,VH,VL)
#define OMSKW (2*BUFW)               // mask area (2 x 64 ints)
#define ATT_SMEM ((OMSKW + 128)*4)   // 74240 bytes

__global__ void __launch_bounds__(256, 2) attn_mma_kernel(
    const __nv_bfloat16* __restrict__ Qh, const __nv_bfloat16* __restrict__ Ql,
    const __nv_bfloat16* __restrict__ Kh, const __nv_bfloat16* __restrict__ Kl,
    const __nv_bfloat16* __restrict__ Vth, const __nv_bfloat16* __restrict__ Vtl,
    const int* __restrict__ amask, const int* __restrict__ fm,
    const float* __restrict__ meanV,
    __nv_bfloat16* __restrict__ ctxH, __nv_bfloat16* __restrict__ ctxL)
{
    extern __shared__ uint32_t sw[];
    const int tid = threadIdx.x;
    const int wid = tid >> 5, lane = tid & 31;
    const int g = lane >> 2, kq = lane & 3;
    const int alr = lane & 7, alh = (lane >> 3) & 1;
    const int qp = blockIdx.x, h = blockIdx.y, b = blockIdx.z;

    const size_t bhrow = (size_t)(b * NHEADS + h) * SEQ * DK;   // Q/K base
    const size_t bhcol = (size_t)(b * NHEADS + h) * DK * SEQ;   // VT base
    const int* amask_b = amask + b * SEQ;

    const uint32_t sbase = (uint32_t)__cvta_generic_to_shared(sw);

#pragma unroll 1
    for (int halfq = 0; halfq < 2; halfq++) {
        const int qt = (halfq == 0) ? qp : (15 - qp);   // 128-row q-tile id
        const int q0 = qt * 128;

        // ---- Q fragments straight from gmem (8 warps x 16 rows = 128) ----
        const int qr0 = q0 + wid * 16 + g;
        const int qr1 = qr0 + 8;
        uint32_t aQh[4][4], aQl[4][4];
        {
            const __nv_bfloat16* r0h = Qh + bhrow + (size_t)qr0 * DK;
            const __nv_bfloat16* r1h = Qh + bhrow + (size_t)qr1 * DK;
            const __nv_bfloat16* r0l = Ql + bhrow + (size_t)qr0 * DK;
            const __nv_bfloat16* r1l = Ql + bhrow + (size_t)qr1 * DK;
#pragma unroll
            for (int kc = 0; kc < 4; kc++) {
                const int kw = kc * 8 + kq;
                aQh[kc][0] = *(const uint32_t*)(r0h + kw * 2);
                aQh[kc][1] = *(const uint32_t*)(r1h + kw * 2);
                aQh[kc][2] = *(const uint32_t*)(r0h + (kw + 4) * 2);
                aQh[kc][3] = *(const uint32_t*)(r1h + (kw + 4) * 2);
                aQl[kc][0] = *(const uint32_t*)(r0l + kw * 2);
                aQl[kc][1] = *(const uint32_t*)(r1l + kw * 2);
                aQl[kc][2] = *(const uint32_t*)(r0l + (kw + 4) * 2);
                aQl[kc][3] = *(const uint32_t*)(r1l + (kw + 4) * 2);
            }
        }

        float m0 = -3.0e38f, m1 = -3.0e38f, l0 = 0.f, l1 = 0.f;
        float o[8][4];
#pragma unroll
        for (int dt = 0; dt < 8; dt++)
#pragma unroll
            for (int i = 0; i < 4; i++) o[dt][i] = 0.f;

        const int ktStart = qt * 2;        // first 64-key tile at the diagonal
        const int nkt = SEQ / 64 - ktStart;
        int buf = 0;

        // ---- prefetch first tile ----
        {
            const int k0 = ktStart * 64;
            const uint32_t bb = sbase + buf * (BUFW * 4);
            for (int idx = tid; idx < 512; idx += 256) {
                const int r = idx >> 3, ch = idx & 7;
                const uint32_t so = (r * WS + ch * 4) * 4;
                const size_t gk = bhrow + (size_t)(k0 + r) * DK + ch * 8;
                const size_t gv = bhcol + (size_t)r * SEQ + k0 + ch * 8;
                cpasync16(bb + so, Kh + gk);
                cpasync16(bb + TW * 4 + so, Kl + gk);
                cpasync16(bb + 2 * TW * 4 + so, Vth + gv);
                cpasync16(bb + 3 * TW * 4 + so, Vtl + gv);
            }
            if (tid < 16)
                cpasync16(sbase + (OMSKW + buf * 64 + tid * 4) * 4,
                          amask_b + k0 + tid * 4);
        }
        CP_COMMIT();

#pragma unroll 1
        for (int i = 0; i < nkt; i++) {
            const int kt = ktStart + i;
            const int k0 = kt * 64;
            CP_WAIT0();
            __syncthreads();

            // ---- prefetch next tile into the other buffer ----
            if (i + 1 < nkt) {
                const int kn0 = k0 + 64;
                const uint32_t bb = sbase + (buf ^ 1) * (BUFW * 4);
                for (int idx = tid; idx < 512; idx += 256) {
                    const int r = idx >> 3, ch = idx & 7;
                    const uint32_t so = (r * WS + ch * 4) * 4;
                    const size_t gk = bhrow + (size_t)(kn0 + r) * DK + ch * 8;
                    const size_t gv = bhcol + (size_t)r * SEQ + kn0 + ch * 8;
                    cpasync16(bb + so, Kh + gk);
                    cpasync16(bb + TW * 4 + so, Kl + gk);
                    cpasync16(bb + 2 * TW * 4 + so, Vth + gv);
                    cpasync16(bb + 3 * TW * 4 + so, Vtl + gv);
                }
                if (tid < 16)
                    cpasync16(sbase + (OMSKW + (buf ^ 1) * 64 + tid * 4) * 4,
                              amask_b + kn0 + tid * 4);
            }
            CP_COMMIT();

            const uint32_t kb = buf * BUFW;
            const uint32_t kbb = sbase + kb * 4;

            // ---- scores (ldmatrix K fragments) ----
            float c[8][4];
#pragma unroll
            for (int nt = 0; nt < 8; nt++)
#pragma unroll
                for (int j = 0; j < 4; j++) c[nt][j] = 0.f;
#pragma unroll
            for (int kc = 0; kc < 4; kc++) {
#pragma unroll
                for (int nt = 0; nt < 8; nt++) {
                    const uint32_t aw = kbb +
                        ((nt * 8 + alr) * WS + kc * 8 + alh * 4) * 4;
                    uint32_t bh2[2], bl2[2];
                    ldsm_x2(bh2, aw);
                    ldsm_x2(bl2, aw + TW * 4);
                    mma16816(c[nt], aQh[kc], bh2);
                    mma16816(c[nt], aQh[kc], bl2);
                    mma16816(c[nt], aQl[kc], bh2);
                }
            }

            // ---- activity bits ----
            const int* mk = (const int*)(sw + OMSKW + buf * 64);
            uint32_t act0 = 0, act1 = 0;
#pragma unroll
            for (int nt = 0; nt < 8; nt++) {
#pragma unroll
                for (int e = 0; e < 2; e++) {
                    const int cl = nt * 8 + 2 * kq + e;
                    const int mv_ = mk[cl];
                    const int colg = k0 + cl;
                    if (mv_ && colg > qr0) act0 |= 1u << (nt * 2 + e);
                    if (mv_ && colg > qr1) act1 |= 1u << (nt * 2 + e);
                }
            }

            // ---- scale + masked tile max ----
            float t0 = -3.0e38f, t1 = -3.0e38f;
#pragma unroll
            for (int nt = 0; nt < 8; nt++) {
#pragma unroll
                for (int e = 0; e < 2; e++) {
                    float s0 = c[nt][e] * 0.125f;     c[nt][e] = s0;
                    float s1 = c[nt][2 + e] * 0.125f; c[nt][2 + e] = s1;
                    if ((act0 >> (nt * 2 + e)) & 1) t0 = fmaxf(t0, s0);
                    if ((act1 >> (nt * 2 + e)) & 1) t1 = fmaxf(t1, s1);
                }
            }
            t0 = fmaxf(t0, __shfl_xor_sync(0xffffffffu, t0, 1));
            t0 = fmaxf(t0, __shfl_xor_sync(0xffffffffu, t0, 2));
            t1 = fmaxf(t1, __shfl_xor_sync(0xffffffffu, t1, 1));
            t1 = fmaxf(t1, __shfl_xor_sync(0xffffffffu, t1, 2));

            const float mn0 = fmaxf(m0, t0), mn1 = fmaxf(m1, t1);
            const float cr0 = __expf(m0 - mn0), cr1 = __expf(m1 - mn1);
            m0 = mn0; m1 = mn1;

            // ---- p = exp or 0; row sums ----
            float rs0 = 0.f, rs1 = 0.f;
#pragma unroll
            for (int nt = 0; nt < 8; nt++) {
#pragma unroll
                for (int e = 0; e < 2; e++) {
                    float p0 = ((act0 >> (nt * 2 + e)) & 1)
                               ? __expf(c[nt][e] - mn0) : 0.f;
                    float p1 = ((act1 >> (nt * 2 + e)) & 1)
                               ? __expf(c[nt][2 + e] - mn1) : 0.f;
                    c[nt][e] = p0;     rs0 += p0;
                    c[nt][2 + e] = p1; rs1 += p1;
                }
            }
            rs0 += __shfl_xor_sync(0xffffffffu, rs0, 1);
            rs0 += __shfl_xor_sync(0xffffffffu, rs0, 2);
            rs1 += __shfl_xor_sync(0xffffffffu, rs1, 1);
            rs1 += __shfl_xor_sync(0xffffffffu, rs1, 2);
            l0 = l0 * cr0 + rs0;
            l1 = l1 * cr1 + rs1;

            // ---- rescale O, then O += P @ V (ldmatrix V fragments) ----
#pragma unroll
            for (int dt = 0; dt < 8; dt++) {
                o[dt][0] *= cr0; o[dt][1] *= cr0;
                o[dt][2] *= cr1; o[dt][3] *= cr1;
            }
#pragma unroll
            for (int kc = 0; kc < 4; kc++) {
                const int tA = 2 * kc, tB = 2 * kc + 1;
                uint32_t aPh[4], aPl[4];
                {
                    __nv_bfloat16 h0 = __float2bfloat16(c[tA][0]),
                                  h1 = __float2bfloat16(c[tA][1]);
                    __nv_bfloat16 h2 = __float2bfloat16(c[tA][2]),
                                  h3 = __float2bfloat16(c[tA][3]);
                    __nv_bfloat16 h4 = __float2bfloat16(c[tB][0]),
                                  h5 = __float2bfloat16(c[tB][1]);
                    __nv_bfloat16 h6 = __float2bfloat16(c[tB][2]),
                                  h7 = __float2bfloat16(c[tB][3]);
                    aPh[0] = pbits(h0, h1); aPh[1] = pbits(h2, h3);
                    aPh[2] = pbits(h4, h5); aPh[3] = pbits(h6, h7);
                    aPl[0] = pack_bf2(c[tA][0] - __bfloat162float(h0),
                                      c[tA][1] - __bfloat162float(h1));
                    aPl[1] = pack_bf2(c[tA][2] - __bfloat162float(h2),
                                      c[tA][3] - __bfloat162float(h3));
                    aPl[2] = pack_bf2(c[tB][0] - __bfloat162float(h4),
                                      c[tB][1] - __bfloat162float(h5));
                    aPl[3] = pack_bf2(c[tB][2] - __bfloat162float(h6),
                                      c[tB][3] - __bfloat162float(h7));
                }
#pragma unroll
                for (int dt = 0; dt < 8; dt++) {
                    const uint32_t aw = kbb +
                        (2 * TW + (dt * 8 + alr) * WS + kc * 8 + alh * 4) * 4;
                    uint32_t bh2[2], bl2[2];
                    ldsm_x2(bh2, aw);
                    ldsm_x2(bl2, aw + TW * 4);
                    mma16816(o[dt], aPh, bh2);
                    mma16816(o[dt], aPh, bl2);
                    mma16816(o[dt], aPl, bh2);
                }
            }
            __syncthreads();
            buf ^= 1;
        }

        // ---- epilogue: write ctx as hi/lo bf16 ----
        const float inv0 = 1.0f / l0, inv1 = 1.0f / l1;
        const int fm0 = fm[b * SEQ + qr0];
        const int fm1 = fm[b * SEQ + qr1];
        const float* mvb = meanV + (size_t)(b * NHEADS + h) * DK;
#pragma unroll
        for (int dt = 0; dt < 8; dt++) {
            const int d = dt * 8 + 2 * kq;
            float2 mvv = *(const float2*)&mvb[d];
            float2 v0 = fm0 ? mvv : make_float2(o[dt][0] * inv0, o[dt][1] * inv0);
            float2 v1 = fm1 ? mvv : make_float2(o[dt][2] * inv1, o[dt][3] * inv1);
            const size_t p0 = (size_t)(b * SEQ + qr0) * DMODEL + h * DK + d;
            const size_t p1 = (size_t)(b * SEQ + qr1) * DMODEL + h * DK + d;
            __nv_bfloat16 a0 = __float2bfloat16(v0.x), a1 = __float2bfloat16(v0.y);
            __nv_bfloat16 b0 = __float2bfloat16(v1.x), b1 = __float2bfloat16(v1.y);
            *(uint32_t*)(ctxH + p0) = pbits(a0, a1);
            *(uint32_t*)(ctxL + p0) = pack_bf2(v0.x - __bfloat162float(a0),
                                               v0.y - __bfloat162float(a1));
            *(uint32_t*)(ctxH + p1) = pbits(b0, b1);
            *(uint32_t*)(ctxL + p1) = pack_bf2(v1.x - __bfloat162float(b0),
                                               v1.y - __bfloat162float(b1));
        }
    }
}

// ---------------------------------------------------------------------------
// LayerNorm: one CTA per token row (1024 elems, 256 threads)
// ---------------------------------------------------------------------------
__global__ void __launch_bounds__(256) ln_kernel(
    const float* __restrict__ x, const float* __restrict__ gamma,
    const float* __restrict__ beta, float* __restrict__ out)
{
    const int row = blockIdx.x;
    const int tid = threadIdx.x;
    const float* xr = x + (size_t)row * DMODEL;

    float4 v = *(const float4*)&xr[tid*4];
    float s  = v.x + v.y + v.z + v.w;
    float sq = v.x*v.x + v.y*v.y + v.z*v.z + v.w*v.w;
#pragma unroll
    for (int o = 16; o > 0; o >>= 1) {
        s  += __shfl_xor_sync(0xffffffffu, s,  o);
        sq += __shfl_xor_sync(0xffffffffu, sq, o);
    }
    __shared__ float ss[8], ssq[8], smu, sinv;
    const int wid = tid >> 5, lane = tid & 31;
    if (lane == 0) { ss[wid] = s; ssq[wid] = sq; }
    __syncthreads();
    if (tid == 0) {
        float S = 0.f, SQ = 0.f;
#pragma unroll
        for (int i = 0; i < 8; i++) { S += ss[i]; SQ += ssq[i]; }
        float mu = S * (1.0f/DMODEL);
        float var = SQ * (1.0f/DMODEL) - mu*mu;
        smu = mu;
        sinv = rsqrtf(var + 1e-5f);
    }
    __syncthreads();
    float mu = smu, inv = sinv;
    float4 g = *(const float4*)&gamma[tid*4];
    float4 be = *(const float4*)&beta[tid*4];
    float4 o;
    o.x = (v.x - mu) * inv * g.x + be.x;
    o.y = (v.y - mu) * inv * g.y + be.y;
    o.z = (v.z - mu) * inv * g.z + be.z;
    o.w = (v.w - mu) * inv * g.w + be.w;
    *(float4*)&out[(size_t)row*DMODEL + tid*4] = o;
}

// ---------------------------------------------------------------------------
extern "C" void kernel_launch(void* const* d_in, const int* in_sizes, int n_in,
                              void* d_out, int out_size)
{
    const float* inQ   = (const float*)d_in[0];
    const float* inK   = (const float*)d_in[1];
    const float* inV   = (const float*)d_in[2];
    const int*   amask = (const int*)  d_in[3];
    const float* W[4]  = { (const float*)d_in[4], (const float*)d_in[5],
                           (const float*)d_in[6], (const float*)d_in[7] };
    const float* gamma = (const float*)d_in[8];
    const float* beta  = (const float*)d_in[9];
    float* out = (float*)d_out;

    __nv_bfloat16 *inH, *inL, *WHp, *WLp, *QH, *QL, *KH, *KL, *VTH, *VTL;
    __nv_bfloat16 *ctxH, *ctxL;
    float *Vf, *tmp, *mv;
    int *fmp;
    cudaGetSymbolAddress((void**)&inH,  g_inH);
    cudaGetSymbolAddress((void**)&inL,  g_inL);
    cudaGetSymbolAddress((void**)&WHp,  g_WH);
    cudaGetSymbolAddress((void**)&WLp,  g_WL);
    cudaGetSymbolAddress((void**)&QH,   g_QH);
    cudaGetSymbolAddress((void**)&QL,   g_QL);
    cudaGetSymbolAddress((void**)&KH,   g_KH);
    cudaGetSymbolAddress((void**)&KL,   g_KL);
    cudaGetSymbolAddress((void**)&Vf,   g_V);
    cudaGetSymbolAddress((void**)&VTH,  g_VTH);
    cudaGetSymbolAddress((void**)&VTL,  g_VTL);
    cudaGetSymbolAddress((void**)&ctxH, g_ctxH);
    cudaGetSymbolAddress((void**)&ctxL, g_ctxL);
    cudaGetSymbolAddress((void**)&tmp,  g_tmp);
    cudaGetSymbolAddress((void**)&mv,   g_meanV);
    cudaGetSymbolAddress((void**)&fmp,  g_fm);

    cudaFuncSetAttribute(attn_mma_kernel,
                         cudaFuncAttributeMaxDynamicSharedMemorySize, ATT_SMEM);
    cudaFuncSetAttribute(qkv_gemm_kernel,
                         cudaFuncAttributeMaxDynamicSharedMemorySize, G_SMEM);
    cudaFuncSetAttribute(outproj_gemm_kernel,
                         cudaFuncAttributeMaxDynamicSharedMemorySize, G_SMEM);

    // ---- one-time splits (2 launches) ----
    const float* ins[3] = { inQ, inK, inV };
    const int NIN = NTOK * DMODEL;         // 4M elements
    const int NW  = DMODEL * DMODEL;       // 1M elements
    SplitJobs sji{}, sjw{};
    for (int i = 0; i < 3; i++) {
        sji.x[i]  = (const float4*)ins[i];
        sji.hi[i] = (uint2*)(inH + (size_t)i * NIN);
        sji.lo[i] = (uint2*)(inL + (size_t)i * NIN);
    }
    sji.x[3] = sji.x[0]; sji.hi[3] = sji.hi[0]; sji.lo[3] = sji.lo[0];
    for (int i = 0; i < 4; i++) {
        sjw.x[i]  = (const float4*)W[i];
        sjw.hi[i] = (uint2*)(WHp + (size_t)i * NW);
        sjw.lo[i] = (uint2*)(WLp + (size_t)i * NW);
    }
    split_multi_kernel<<<dim3(NIN/4/256, 3), 256>>>(sji);
    split_multi_kernel<<<dim3(NW/4/256, 4), 256>>>(sjw);

    // ---- fused QKV projection (grid z selects Q/K/V) ----
    QKVPtrs qp;
    for (int i = 0; i < 3; i++) {
        qp.ah[i] = inH + (size_t)i * NIN;
        qp.al[i] = inL + (size_t)i * NIN;
        qp.wh[i] = WHp + (size_t)i * NW;
        qp.wl[i] = WLp + (size_t)i * NW;
    }
    qkv_gemm_kernel<<<dim3(DMODEL/128, NTOK/128, 3), 256, G_SMEM>>>(
        qp, QH, QL, KH, KL, Vf);

    vsplitT_kernel<<<dim3(SEQ/64, BH), 256>>>(Vf, VTH, VTL);
    fullmask_kernel<<<dim3(SEQ/1024, BATCH), 1024>>>(amask, fmp);
    meanv_kernel<<<BH, 256>>>(Vf, mv);

    attn_mma_kernel<<<dim3(8, NHEADS, BATCH), 256, ATT_SMEM>>>(
        QH, QL, KH, KL, VTH, VTL, amask, fmp, mv, ctxH, ctxL);

    outproj_gemm_kernel<<<dim3(DMODEL/128, NTOK/128), 256, G_SMEM>>>(
        ctxH, ctxL, WHp + (size_t)3 * NW, WLp + (size_t)3 * NW, inQ, tmp);

    ln_kernel<<<NTOK, 256>>>(tmp, gamma, beta, out);
}